// round 11
// baseline (speedup 1.0000x reference)
#include <cuda_runtime.h>
#include <cuda_bf16.h>
#include <cstdint>
#include <math.h>

#define BB 4
#define CC 64
#define FF 256
#define TT 400
#define DC 16
#define SP (FF*TT)

#define QS 0.36067376022224085f   /* 0.25 * log2(e) */

__device__ __forceinline__ float ex2f(float x) {
    float r; asm("ex2.approx.ftz.f32 %0, %1;" : "=f"(r) : "f"(x)); return r;
}
__device__ __forceinline__ uint32_t smem_u32(const void* p) {
    uint32_t a;
    asm("{ .reg .u64 t; cvta.to.shared.u64 t, %1; cvt.u32.u64 %0, t; }" : "=r"(a) : "l"(p));
    return a;
}
__device__ __forceinline__ void ldmx2(uint32_t& r0, uint32_t& r1, uint32_t a) {
    asm volatile("ldmatrix.sync.aligned.m8n8.x2.shared.b16 {%0,%1}, [%2];"
                 : "=r"(r0), "=r"(r1) : "r"(a));
}
__device__ __forceinline__ void ldmx4(uint4& r, uint32_t a) {
    asm volatile("ldmatrix.sync.aligned.m8n8.x4.shared.b16 {%0,%1,%2,%3}, [%4];"
                 : "=r"(r.x), "=r"(r.y), "=r"(r.z), "=r"(r.w) : "r"(a));
}
__device__ __forceinline__ void mma16816(float* d, uint4 a, uint32_t b0, uint32_t b1) {
    asm volatile("mma.sync.aligned.m16n8k16.row.col.f32.bf16.bf16.f32 "
        "{%0,%1,%2,%3}, {%4,%5,%6,%7}, {%8,%9}, {%0,%1,%2,%3};"
        : "+f"(d[0]), "+f"(d[1]), "+f"(d[2]), "+f"(d[3])
        : "r"(a.x), "r"(a.y), "r"(a.z), "r"(a.w), "r"(b0), "r"(b1));
}
#define PACKBF(r, a, b) asm("cvt.rn.bf16x2.f32 %0, %1, %2;" : "=r"(r) : "f"(b), "f"(a))

// ---------------- scratch ----------------
static __device__ float g_qkvf_t[(size_t)BB*48*FF*TT];
static __device__ float g_qkvf_f[(size_t)BB*TT*48*FF];
static __device__ float g_tqk2 [(size_t)BB*32*FF*TT];
static __device__ float g_fout_f[(size_t)BB*FF*DC*TT];
static __device__ __align__(16) uint4 g_wafH[640];
static __device__ __align__(16) uint4 g_wafL[640];
static __device__ float g_shift[80];
static __device__ float g_alpha[80];

// greedy-balanced causal tile assignment over 8 warps (chunk loads 38-44)
static __device__ const int TILE_LUT8[8][8] = {
    {24, 14, 0, -1, -1, -1, -1, -1},
    {23, 15, -1, -1, -1, -1, -1, -1},
    {22, 16, -1, -1, -1, -1, -1, -1},
    {21, 17, -1, -1, -1, -1, -1, -1},
    {20, 18, -1, -1, -1, -1, -1, -1},
    {19, 13, 6, -1, -1, -1, -1, -1},
    {12, 11, 10, 4, -1, -1, -1, -1},
    {9, 8, 7, 5, 3, 2, 1, -1}
};

// ================= kernel 0: prep =================
__global__ __launch_bounds__(256)
void asa_prep_kernel(const float* __restrict__ w_fqkv, const float* __restrict__ w_tqk,
    const float* __restrict__ g1, const float* __restrict__ b1,
    const float* __restrict__ m1, const float* __restrict__ v1, const float* __restrict__ a1,
    const float* __restrict__ g2, const float* __restrict__ b2,
    const float* __restrict__ m2, const float* __restrict__ v2, const float* __restrict__ a2)
{
    int i = blockIdx.x * 256 + threadIdx.x;
    if (i < 640) {
        int lane = i & 31, ks = (i >> 5) & 3, o = i >> 7;
        int r = lane >> 2, cp = (lane & 3) * 2;
        int oc0 = o * 16 + r, k0 = ks * 16 + cp;
        uint32_t hiR[4], loR[4];
        #pragma unroll
        for (int aa = 0; aa < 4; aa++) {
            int oc = oc0 + ((aa & 1) << 3);
            int kk = k0 + ((aa >> 1) << 3);
            float s, w0, w1;
            if (oc < 48) {
                s = g1[oc] * rsqrtf(v1[oc] + 1e-5f);
                w0 = w_fqkv[oc * 64 + kk] * s; w1 = w_fqkv[oc * 64 + kk + 1] * s;
            } else {
                int j = oc - 48;
                s = g2[j] * rsqrtf(v2[j] + 1e-5f);
                w0 = w_tqk[j * 64 + kk] * s; w1 = w_tqk[j * 64 + kk + 1] * s;
            }
            uint32_t h; PACKBF(h, w0, w1);
            float r0 = __uint_as_float(h << 16);
            float r1 = __uint_as_float(h & 0xffff0000u);
            uint32_t l; PACKBF(l, w0 - r0, w1 - r1);
            hiR[aa] = h; loR[aa] = l;
        }
        g_wafH[i] = make_uint4(hiR[0], hiR[1], hiR[2], hiR[3]);
        g_wafL[i] = make_uint4(loR[0], loR[1], loR[2], loR[3]);
    }
    if (i < 80) {
        float ss, sh, al;
        if (i < 48) { ss = g1[i] * rsqrtf(v1[i] + 1e-5f); sh = b1[i] - m1[i] * ss; al = a1[i]; }
        else { int j = i - 48; ss = g2[j] * rsqrtf(v2[j] + 1e-5f); sh = b2[j] - m2[j] * ss; al = a2[j]; }
        g_shift[i] = sh; g_alpha[i] = al;
    }
}

// ====== kernel 1: conv1x1 via mma.sync bf16 — float4 loads + smem staging ======
__global__ __launch_bounds__(320)
void asa_conv_mma_kernel(const float* __restrict__ inp)
{
    __shared__ __align__(16) float xstage[64 * 68];
    __shared__ __align__(16) char xhi[8192];
    __shared__ __align__(16) char xlo[8192];
    int tid = threadIdx.x, wid = tid >> 5, lane = tid & 31;
    int b = blockIdx.y;
    int n0 = blockIdx.x * 64;
    const float* xb = inp + (size_t)b * CC * SP + n0;

    for (int i = tid; i < 1024; i += 320) {
        int k = i >> 4, s4 = (i & 15) * 4;
        float4 v = *(const float4*)(xb + (size_t)k * SP + s4);
        *(float4*)(xstage + k * 68 + s4) = v;
    }
    __syncthreads();

    for (int ch = tid; ch < 512; ch += 320) {
        int sp = ch & 63, kb = ch >> 6;
        float v[8];
        #pragma unroll
        for (int j = 0; j < 8; j++) v[j] = xstage[(kb * 8 + j) * 68 + sp];
        uint32_t hp[4], lp[4];
        #pragma unroll
        for (int j = 0; j < 4; j++) {
            uint32_t h; PACKBF(h, v[2*j], v[2*j+1]);
            float r0 = __uint_as_float(h << 16);
            float r1 = __uint_as_float(h & 0xffff0000u);
            uint32_t l; PACKBF(l, v[2*j] - r0, v[2*j+1] - r1);
            hp[j] = h; lp[j] = l;
        }
        uint32_t off = sp * 128 + ((kb * 16) ^ ((sp & 7) << 4));
        *(uint4*)(xhi + off) = make_uint4(hp[0], hp[1], hp[2], hp[3]);
        *(uint4*)(xlo + off) = make_uint4(lp[0], lp[1], lp[2], lp[3]);
    }
    __syncthreads();

    int octile = wid >> 1, sptile = wid & 1;
    uint32_t shi = smem_u32(xhi), slo = smem_u32(xlo);
    float d[4][4];
    #pragma unroll
    for (int nt = 0; nt < 4; nt++)
        #pragma unroll
        for (int j = 0; j < 4; j++) d[nt][j] = 0.f;

    int ln = lane & 15;
    int sprow_base = sptile * 32 + (ln & 7);
    int khalf = ((ln >> 3) & 1) << 3;

    #pragma unroll
    for (int ks = 0; ks < 4; ks++) {
        uint4 ah = g_wafH[(octile * 4 + ks) * 32 + lane];
        uint4 al = g_wafL[(octile * 4 + ks) * 32 + lane];
        #pragma unroll
        for (int nt = 0; nt < 4; nt++) {
            int spr = sprow_base + nt * 8;
            int ke = ks * 16 + khalf;
            uint32_t aoff = spr * 128 + ((ke * 2) ^ ((spr & 7) << 4));
            uint32_t bh0, bh1, bl0, bl1;
            ldmx2(bh0, bh1, shi + aoff);
            ldmx2(bl0, bl1, slo + aoff);
            mma16816(d[nt], ah, bh0, bh1);
            mma16816(d[nt], al, bh0, bh1);
            mma16816(d[nt], ah, bl0, bl1);
        }
    }

    int r = lane >> 2, cp = (lane & 3) * 2;
    #pragma unroll
    for (int half = 0; half < 2; half++) {
        int oc = octile * 16 + r + half * 8;
        float sh = g_shift[oc], al = g_alpha[oc];
        float* dst;
        if (oc < 48) dst = g_qkvf_t + ((size_t)b * 48 + oc) * SP + n0;
        else         dst = g_tqk2  + ((size_t)b * 32 + (oc - 48)) * SP + n0;
        #pragma unroll
        for (int nt = 0; nt < 4; nt++) {
            float v0 = d[nt][half * 2 + 0] + sh; v0 = v0 > 0.f ? v0 : al * v0;
            float v1 = d[nt][half * 2 + 1] + sh; v1 = v1 > 0.f ? v1 : al * v1;
            int sp = sptile * 32 + nt * 8 + cp;
            *(float2*)(dst + sp) = make_float2(v0, v1);
        }
    }
}

// ================= transpose 1 =================
__global__ __launch_bounds__(256)
void asa_transpose_qkv_kernel()
{
    __shared__ float tile[32][33];
    int z = blockIdx.z;
    int t0 = blockIdx.x * 32, f0 = blockIdx.y * 32;
    int tx = threadIdx.x, ty = threadIdx.y;
    size_t ibase = (size_t)z * FF * TT;
    #pragma unroll
    for (int k = 0; k < 32; k += 8) {
        int t = t0 + tx, f = f0 + ty + k;
        if (t < TT) tile[ty + k][tx] = g_qkvf_t[ibase + (size_t)f * TT + t];
    }
    __syncthreads();
    int b = z / 48, oc = z % 48;
    #pragma unroll
    for (int k = 0; k < 32; k += 8) {
        int t = t0 + ty + k, f = f0 + tx;
        if (t < TT) g_qkvf_f[((size_t)(b * TT + t) * 48 + oc) * FF + f] = tile[tx][ty + k];
    }
}

// ========== kernel 2: frequency attention via mma.sync (flash-style, fused output) ==========
#define FQ_QHI 0
#define FQ_QLO 8192
#define FQ_KHI 16384
#define FQ_KLO 24576
#define FQ_VHI 32768
#define FQ_VLO 40960

__global__ __launch_bounds__(128)
void asa_freq_attn_kernel()
{
    __shared__ __align__(16) char smf[49152];
    int tid = threadIdx.x, wid = tid >> 5, lane = tid & 31;
    int t = blockIdx.x, b = blockIdx.y;
    const float* base = g_qkvf_f + (size_t)(b * TT + t) * 48 * FF;
    uint32_t sb = smem_u32(smf);

    for (int it = 0; it < 16; it++) {
        int idx = it * 128 + tid;
        int row = idx & 255;
        int cp = idx >> 8;
        uint32_t qkoff = (uint32_t)(row * 32 + cp * 4) ^ (uint32_t)(((row >> 2) & 1) << 4);
        {
            float x0 = base[(2*cp) * 256 + row] * QS;
            float x1 = base[(2*cp+1) * 256 + row] * QS;
            uint32_t h; PACKBF(h, x0, x1);
            float r0 = __uint_as_float(h << 16);
            float r1 = __uint_as_float(h & 0xffff0000u);
            uint32_t l; PACKBF(l, x0 - r0, x1 - r1);
            *(uint32_t*)(smf + FQ_QHI + qkoff) = h;
            *(uint32_t*)(smf + FQ_QLO + qkoff) = l;
        }
        {
            float x0 = base[4096 + (2*cp) * 256 + row];
            float x1 = base[4096 + (2*cp+1) * 256 + row];
            uint32_t h; PACKBF(h, x0, x1);
            float r0 = __uint_as_float(h << 16);
            float r1 = __uint_as_float(h & 0xffff0000u);
            uint32_t l; PACKBF(l, x0 - r0, x1 - r1);
            *(uint32_t*)(smf + FQ_KHI + qkoff) = h;
            *(uint32_t*)(smf + FQ_KLO + qkoff) = l;
        }
        {
            float x0 = base[8192 + (2*cp) * 256 + row];
            float x1 = base[8192 + (2*cp+1) * 256 + row];
            uint32_t h; PACKBF(h, x0, x1);
            float r0 = __uint_as_float(h << 16);
            float r1 = __uint_as_float(h & 0xffff0000u);
            uint32_t l; PACKBF(l, x0 - r0, x1 - r1);
            int c0 = 2*cp, c1 = 2*cp + 1, y = row;
            uint32_t o0 = (uint32_t)(c0 * 512 + y * 2) ^ (uint32_t)((c0 & 7) << 4);
            uint32_t o1 = (uint32_t)(c1 * 512 + y * 2) ^ (uint32_t)((c1 & 7) << 4);
            *(uint16_t*)(smf + FQ_VHI + o0) = (uint16_t)(h & 0xffff);
            *(uint16_t*)(smf + FQ_VHI + o1) = (uint16_t)(h >> 16);
            *(uint16_t*)(smf + FQ_VLO + o0) = (uint16_t)(l & 0xffff);
            *(uint16_t*)(smf + FQ_VLO + o1) = (uint16_t)(l >> 16);
        }
    }
    __syncthreads();

    int fw = wid * 64;
    int l16 = lane & 15;
    int kh16 = ((lane >> 4) & 1) << 4;
    uint4 qh[4], ql[4];
    #pragma unroll
    for (int mt = 0; mt < 4; mt++) {
        int fr = fw + mt * 16 + l16;
        uint32_t off = (uint32_t)(fr * 32 + kh16) ^ (uint32_t)(((fr >> 2) & 1) << 4);
        ldmx4(qh[mt], sb + FQ_QHI + off);
        ldmx4(ql[mt], sb + FQ_QLO + off);
    }

    float O[4][2][4];
    #pragma unroll
    for (int mt = 0; mt < 4; mt++)
        #pragma unroll
        for (int nt = 0; nt < 2; nt++)
            #pragma unroll
            for (int j = 0; j < 4; j++) O[mt][nt][j] = 0.f;
    float lsum[8];
    #pragma unroll
    for (int i = 0; i < 8; i++) lsum[i] = 0.f;

    int rlow = l16 & 7;
    int khb = ((l16 >> 3) & 1) << 4;

    for (int y0 = 0; y0 < 256; y0 += 16) {
        uint32_t kb0[2], kb1[2], klb0[2], klb1[2];
        #pragma unroll
        for (int nt = 0; nt < 2; nt++) {
            int kr = y0 + nt * 8 + rlow;
            uint32_t off = (uint32_t)(kr * 32 + khb) ^ (uint32_t)(((kr >> 2) & 1) << 4);
            ldmx2(kb0[nt], kb1[nt], sb + FQ_KHI + off);
            ldmx2(klb0[nt], klb1[nt], sb + FQ_KLO + off);
        }
        float S[4][2][4];
        #pragma unroll
        for (int mt = 0; mt < 4; mt++)
            #pragma unroll
            for (int nt = 0; nt < 2; nt++) {
                #pragma unroll
                for (int j = 0; j < 4; j++) S[mt][nt][j] = 0.f;
                mma16816(S[mt][nt], qh[mt], kb0[nt], kb1[nt]);
                mma16816(S[mt][nt], ql[mt], kb0[nt], kb1[nt]);
                mma16816(S[mt][nt], qh[mt], klb0[nt], klb1[nt]);
            }
        uint4 ph[4], pl[4];
        #pragma unroll
        for (int mt = 0; mt < 4; mt++) {
            float p[2][4];
            #pragma unroll
            for (int nt = 0; nt < 2; nt++)
                #pragma unroll
                for (int j = 0; j < 4; j++) p[nt][j] = ex2f(S[mt][nt][j]);
            lsum[2*mt]   += (p[0][0] + p[0][1]) + (p[1][0] + p[1][1]);
            lsum[2*mt+1] += (p[0][2] + p[0][3]) + (p[1][2] + p[1][3]);
            uint32_t hreg[4], lreg[4];
            #pragma unroll
            for (int q = 0; q < 4; q++) {
                int nt = q >> 1, jo = (q & 1) * 2;
                uint32_t h; PACKBF(h, p[nt][jo], p[nt][jo+1]);
                float r0 = __uint_as_float(h << 16);
                float r1 = __uint_as_float(h & 0xffff0000u);
                uint32_t l; PACKBF(l, p[nt][jo] - r0, p[nt][jo+1] - r1);
                hreg[q] = h; lreg[q] = l;
            }
            ph[mt] = make_uint4(hreg[0], hreg[1], hreg[2], hreg[3]);
            pl[mt] = make_uint4(lreg[0], lreg[1], lreg[2], lreg[3]);
        }
        uint32_t vb0[2], vb1[2], vlb0[2], vlb1[2];
        #pragma unroll
        for (int nt = 0; nt < 2; nt++) {
            int vc = nt * 8 + rlow;
            uint32_t off = (uint32_t)(vc * 512 + y0 * 2 + khb) ^ (uint32_t)((vc & 7) << 4);
            ldmx2(vb0[nt], vb1[nt], sb + FQ_VHI + off);
            ldmx2(vlb0[nt], vlb1[nt], sb + FQ_VLO + off);
        }
        #pragma unroll
        for (int mt = 0; mt < 4; mt++)
            #pragma unroll
            for (int nt = 0; nt < 2; nt++) {
                mma16816(O[mt][nt], ph[mt], vb0[nt], vb1[nt]);
                mma16816(O[mt][nt], pl[mt], vb0[nt], vb1[nt]);
                mma16816(O[mt][nt], ph[mt], vlb0[nt], vlb1[nt]);
            }
    }

    #pragma unroll
    for (int i = 0; i < 8; i++) {
        lsum[i] += __shfl_xor_sync(0xffffffffu, lsum[i], 1);
        lsum[i] += __shfl_xor_sync(0xffffffffu, lsum[i], 2);
    }

    // fused output: scatter directly to [b][f][c][t] (kills transpose2)
    int rq = lane >> 2, cq = (lane & 3) * 2;
    #pragma unroll
    for (int mt = 0; mt < 4; mt++) {
        float i0 = 1.f / lsum[2*mt], i1 = 1.f / lsum[2*mt+1];
        int fg = fw + mt * 16 + rq;
        #pragma unroll
        for (int nt = 0; nt < 2; nt++) {
            int c = nt * 8 + cq;
            size_t o = ((size_t)(b * FF + fg) * DC + c) * TT + t;
            g_fout_f[o]                    = O[mt][nt][0] * i0;
            g_fout_f[o + TT]               = O[mt][nt][1] * i0;
            g_fout_f[o + 8 * DC * TT]      = O[mt][nt][2] * i1;
            g_fout_f[o + 8 * DC * TT + TT] = O[mt][nt][3] * i1;
        }
    }
}

// ======= kernel 3: causal time attention via mma.sync, 8 warps =======
#define TQ_QHI 0        /* 400*32 = 12800 */
#define TQ_QLO 12800
#define TQ_KHI 25600
#define TQ_KLO 38400
#define TQ_VHI 51200    /* 16 rows * 816 = 13056 */
#define TQ_VLO 64256
#define TQ_ST  77312    /* 400 rows * 80B = 32000 */
#define TQ_WP  109312
#define TQ_SC  113408
#define TQ_SH  113664
#define TQ_AL  113920
#define TQ_SMEM 114176

__global__ __launch_bounds__(256, 2)
void asa_time_attn_kernel(const float* __restrict__ inp, const float* __restrict__ w_proj,
    const float* __restrict__ g3, const float* __restrict__ b3, const float* __restrict__ m3,
    const float* __restrict__ v3, const float* __restrict__ a3, float* __restrict__ out)
{
    extern __shared__ char smt[];
    uint32_t sb = smem_u32(smt);
    int tid = threadIdx.x, wid = tid >> 5, lane = tid & 31;
    int f = blockIdx.x, b = blockIdx.y;
    size_t cbase = (size_t)b * 32 * SP + (size_t)f * TT;
    const float* vg = g_fout_f + (size_t)(b * FF + f) * DC * TT;

    #pragma unroll 1
    for (int idx = tid; idx < 3200; idx += 256) {
        int t = idx % 400;
        int cp = idx / 400;
        uint32_t qkoff = (uint32_t)(t * 32 + cp * 4) ^ (uint32_t)(((t >> 2) & 1) << 4);
        {
            float x0 = g_tqk2[cbase + (size_t)(2*cp) * SP + t] * QS;
            float x1 = g_tqk2[cbase + (size_t)(2*cp+1) * SP + t] * QS;
            uint32_t h; PACKBF(h, x0, x1);
            float r0 = __uint_as_float(h << 16);
            float r1 = __uint_as_float(h & 0xffff0000u);
            uint32_t l; PACKBF(l, x0 - r0, x1 - r1);
            *(uint32_t*)(smt + TQ_QHI + qkoff) = h;
            *(uint32_t*)(smt + TQ_QLO + qkoff) = l;
        }
        {
            float x0 = g_tqk2[cbase + (size_t)(16 + 2*cp) * SP + t];
            float x1 = g_tqk2[cbase + (size_t)(17 + 2*cp) * SP + t];
            uint32_t h; PACKBF(h, x0, x1);
            float r0 = __uint_as_float(h << 16);
            float r1 = __uint_as_float(h & 0xffff0000u);
            uint32_t l; PACKBF(l, x0 - r0, x1 - r1);
            *(uint32_t*)(smt + TQ_KHI + qkoff) = h;
            *(uint32_t*)(smt + TQ_KLO + qkoff) = l;
        }
        {
            float x0 = vg[(size_t)(2*cp) * TT + t];
            float x1 = vg[(size_t)(2*cp+1) * TT + t];
            uint32_t h; PACKBF(h, x0, x1);
            float r0 = __uint_as_float(h << 16);
            float r1 = __uint_as_float(h & 0xffff0000u);
            uint32_t l; PACKBF(l, x0 - r0, x1 - r1);
            uint32_t o0 = (uint32_t)((2*cp) * 816 + t * 2);
            uint32_t o1 = (uint32_t)((2*cp+1) * 816 + t * 2);
            *(uint16_t*)(smt + TQ_VHI + o0) = (uint16_t)(h & 0xffff);
            *(uint16_t*)(smt + TQ_VHI + o1) = (uint16_t)(h >> 16);
            *(uint16_t*)(smt + TQ_VLO + o0) = (uint16_t)(l & 0xffff);
            *(uint16_t*)(smt + TQ_VLO + o1) = (uint16_t)(l >> 16);
        }
    }
    for (int i = tid; i < 1024; i += 256) ((float*)(smt + TQ_WP))[i] = w_proj[i];
    if (tid < 64) {
        float s = g3[tid] * rsqrtf(v3[tid] + 1e-5f);
        ((float*)(smt + TQ_SC))[tid] = s;
        ((float*)(smt + TQ_SH))[tid] = b3[tid] - m3[tid] * s;
        ((float*)(smt + TQ_AL))[tid] = a3[tid];
    }
    __syncthreads();

    int l16 = lane & 15;
    int kh16 = ((lane >> 4) & 1) << 4;
    int rlow = l16 & 7;
    int khb = ((l16 >> 3) & 1) << 4;
    int rq = lane >> 2, cq = (lane & 3) * 2;
    float* st = (float*)(smt + TQ_ST);

    #pragma unroll 1
    for (int k8 = 0; k8 < 8; k8++) {
        int tile = TILE_LUT8[wid][k8];
        if (tile < 0) break;

        uint4 qh, ql;
        {
            int fr = tile * 16 + l16;
            uint32_t off = (uint32_t)(fr * 32 + kh16) ^ (uint32_t)(((fr >> 2) & 1) << 4);
            ldmx4(qh, sb + TQ_QHI + off);
            ldmx4(ql, sb + TQ_QLO + off);
        }
        float O[2][4];
        #pragma unroll
        for (int nt = 0; nt < 2; nt++)
            #pragma unroll
            for (int j = 0; j < 4; j++) O[nt][j] = 0.f;
        float ls0 = 0.f, ls1 = 0.f;

        #pragma unroll 1
        for (int ch = 0; ch <= tile; ch++) {
            int y0 = ch * 16;
            uint32_t kb0[2], kb1[2], klb0[2], klb1[2];
            #pragma unroll
            for (int nt = 0; nt < 2; nt++) {
                int kr = y0 + nt * 8 + rlow;
                uint32_t off = (uint32_t)(kr * 32 + khb) ^ (uint32_t)(((kr >> 2) & 1) << 4);
                ldmx2(kb0[nt], kb1[nt], sb + TQ_KHI + off);
                ldmx2(klb0[nt], klb1[nt], sb + TQ_KLO + off);
            }
            float S[2][4];
            #pragma unroll
            for (int nt = 0; nt < 2; nt++) {
                #pragma unroll
                for (int j = 0; j < 4; j++) S[nt][j] = 0.f;
                mma16816(S[nt], qh, kb0[nt], kb1[nt]);
                mma16816(S[nt], ql, kb0[nt], kb1[nt]);
                mma16816(S[nt], qh, klb0[nt], klb1[nt]);
            }
            if (ch == tile) {
                #pragma unroll
                for (int nt = 0; nt < 2; nt++) {
                    int c0 = nt * 8 + cq;
                    if (c0     > rq)     S[nt][0] = -3e38f;
                    if (c0 + 1 > rq)     S[nt][1] = -3e38f;
                    if (c0     > rq + 8) S[nt][2] = -3e38f;
                    if (c0 + 1 > rq + 8) S[nt][3] = -3e38f;
                }
            }
            float p[2][4];
            #pragma unroll
            for (int nt = 0; nt < 2; nt++)
                #pragma unroll
                for (int j = 0; j < 4; j++) p[nt][j] = ex2f(S[nt][j]);
            ls0 += (p[0][0] + p[0][1]) + (p[1][0] + p[1][1]);
            ls1 += (p[0][2] + p[0][3]) + (p[1][2] + p[1][3]);
            uint32_t hreg[4], lreg[4];
            #pragma unroll
            for (int q = 0; q < 4; q++) {
                int nt = q >> 1, jo = (q & 1) * 2;
                uint32_t h; PACKBF(h, p[nt][jo], p[nt][jo+1]);
                float r0 = __uint_as_float(h << 16);
                float r1 = __uint_as_float(h & 0xffff0000u);
                uint32_t l; PACKBF(l, p[nt][jo] - r0, p[nt][jo+1] - r1);
                hreg[q] = h; lreg[q] = l;
            }
            uint4 ph = make_uint4(hreg[0], hreg[1], hreg[2], hreg[3]);
            uint4 pl = make_uint4(lreg[0], lreg[1], lreg[2], lreg[3]);

            uint32_t vb0[2], vb1[2], vlb0[2], vlb1[2];
            #pragma unroll
            for (int nt = 0; nt < 2; nt++) {
                int vc = nt * 8 + rlow;
                uint32_t off = (uint32_t)(vc * 816 + y0 * 2 + khb);
                ldmx2(vb0[nt], vb1[nt], sb + TQ_VHI + off);
                ldmx2(vlb0[nt], vlb1[nt], sb + TQ_VLO + off);
            }
            #pragma unroll
            for (int nt = 0; nt < 2; nt++) {
                mma16816(O[nt], ph, vb0[nt], vb1[nt]);
                mma16816(O[nt], pl, vb0[nt], vb1[nt]);
                mma16816(O[nt], ph, vlb0[nt], vlb1[nt]);
            }
        }

        ls0 += __shfl_xor_sync(0xffffffffu, ls0, 1);
        ls0 += __shfl_xor_sync(0xffffffffu, ls0, 2);
        ls1 += __shfl_xor_sync(0xffffffffu, ls1, 1);
        ls1 += __shfl_xor_sync(0xffffffffu, ls1, 2);
        float i0 = 1.f / ls0, i1 = 1.f / ls1;

        int row0 = tile * 16 + rq, row1 = row0 + 8;
        #pragma unroll
        for (int nt = 0; nt < 2; nt++) {
            int c = nt * 8 + cq;
            st[row0 * 20 + c]     = O[nt][0] * i0;
            st[row0 * 20 + c + 1] = O[nt][1] * i0;
            st[row1 * 20 + c]     = O[nt][2] * i1;
            st[row1 * 20 + c + 1] = O[nt][3] * i1;
        }
    }
    __syncthreads();

    const float* wp  = (const float*)(smt + TQ_WP);
    const float* sc3 = (const float*)(smt + TQ_SC);
    const float* sh3 = (const float*)(smt + TQ_SH);
    const float* al3 = (const float*)(smt + TQ_AL);
    #pragma unroll 1
    for (int t = tid; t < 400; t += 256) {
        float a[16];
        const float* sr = st + t * 20;
        #pragma unroll
        for (int c = 0; c < 16; c++) a[c] = sr[c];
        size_t obase = (((size_t)b * CC) * FF + f) * TT + t;
        #pragma unroll 8
        for (int oc = 0; oc < CC; oc++) {
            const float4* wr = (const float4*)(wp + oc * 16);
            float4 w0 = wr[0], w1 = wr[1], w2 = wr[2], w3 = wr[3];
            float r = 0.f;
            r = fmaf(w0.x, a[0],  r); r = fmaf(w0.y, a[1],  r);
            r = fmaf(w0.z, a[2],  r); r = fmaf(w0.w, a[3],  r);
            r = fmaf(w1.x, a[4],  r); r = fmaf(w1.y, a[5],  r);
            r = fmaf(w1.z, a[6],  r); r = fmaf(w1.w, a[7],  r);
            r = fmaf(w2.x, a[8],  r); r = fmaf(w2.y, a[9],  r);
            r = fmaf(w2.z, a[10], r); r = fmaf(w2.w, a[11], r);
            r = fmaf(w3.x, a[12], r); r = fmaf(w3.y, a[13], r);
            r = fmaf(w3.z, a[14], r); r = fmaf(w3.w, a[15], r);
            r = fmaf(r, sc3[oc], sh3[oc]);
            r = r > 0.f ? r : al3[oc] * r;
            out[obase + (size_t)oc * SP] = r + inp[obase + (size_t)oc * SP];
        }
    }
}

// ================= launcher =================
extern "C" void kernel_launch(void* const* d_in, const int* in_sizes, int n_in,
                              void* d_out, int out_size)
{
    (void)in_sizes; (void)n_in; (void)out_size;
    const float* inp    = (const float*)d_in[0];
    const float* w_fqkv = (const float*)d_in[2];
    const float* g1 = (const float*)d_in[3];
    const float* b1 = (const float*)d_in[4];
    const float* m1 = (const float*)d_in[5];
    const float* v1 = (const float*)d_in[6];
    const float* a1 = (const float*)d_in[7];
    const float* w_tqk  = (const float*)d_in[8];
    const float* g2 = (const float*)d_in[9];
    const float* b2 = (const float*)d_in[10];
    const float* m2 = (const float*)d_in[11];
    const float* v2 = (const float*)d_in[12];
    const float* a2 = (const float*)d_in[13];
    const float* w_proj = (const float*)d_in[14];
    const float* g3 = (const float*)d_in[15];
    const float* b3 = (const float*)d_in[16];
    const float* m3 = (const float*)d_in[17];
    const float* v3 = (const float*)d_in[18];
    const float* a3 = (const float*)d_in[19];
    float* out = (float*)d_out;

    cudaFuncSetAttribute(asa_time_attn_kernel,
                         cudaFuncAttributeMaxDynamicSharedMemorySize, TQ_SMEM);

    asa_prep_kernel<<<3, 256>>>(w_fqkv, w_tqk, g1, b1, m1, v1, a1,
                                g2, b2, m2, v2, a2);
    asa_conv_mma_kernel<<<dim3(1600, BB), 320>>>(inp);
    asa_transpose_qkv_kernel<<<dim3(13, 8, BB * 48), dim3(32, 8)>>>();
    asa_freq_attn_kernel<<<dim3(TT, BB), 128>>>();
    asa_time_attn_kernel<<<dim3(FF, BB), 256, TQ_SMEM>>>(inp, w_proj,
        g3, b3, m3, v3, a3, out);
}

// round 12
// speedup vs baseline: 1.0770x; 1.0770x over previous
#include <cuda_runtime.h>
#include <cuda_bf16.h>
#include <cstdint>
#include <math.h>

#define BB 4
#define CC 64
#define FF 256
#define TT 400
#define DC 16
#define SP (FF*TT)

#define QS 0.36067376022224085f   /* 0.25 * log2(e) */

__device__ __forceinline__ float ex2f(float x) {
    float r; asm("ex2.approx.ftz.f32 %0, %1;" : "=f"(r) : "f"(x)); return r;
}
__device__ __forceinline__ uint32_t smem_u32(const void* p) {
    uint32_t a;
    asm("{ .reg .u64 t; cvta.to.shared.u64 t, %1; cvt.u32.u64 %0, t; }" : "=r"(a) : "l"(p));
    return a;
}
__device__ __forceinline__ void ldmx2(uint32_t& r0, uint32_t& r1, uint32_t a) {
    asm volatile("ldmatrix.sync.aligned.m8n8.x2.shared.b16 {%0,%1}, [%2];"
                 : "=r"(r0), "=r"(r1) : "r"(a));
}
__device__ __forceinline__ void ldmx4(uint4& r, uint32_t a) {
    asm volatile("ldmatrix.sync.aligned.m8n8.x4.shared.b16 {%0,%1,%2,%3}, [%4];"
                 : "=r"(r.x), "=r"(r.y), "=r"(r.z), "=r"(r.w) : "r"(a));
}
__device__ __forceinline__ void mma16816(float* d, uint4 a, uint32_t b0, uint32_t b1) {
    asm volatile("mma.sync.aligned.m16n8k16.row.col.f32.bf16.bf16.f32 "
        "{%0,%1,%2,%3}, {%4,%5,%6,%7}, {%8,%9}, {%0,%1,%2,%3};"
        : "+f"(d[0]), "+f"(d[1]), "+f"(d[2]), "+f"(d[3])
        : "r"(a.x), "r"(a.y), "r"(a.z), "r"(a.w), "r"(b0), "r"(b1));
}
#define PACKBF(r, a, b) asm("cvt.rn.bf16x2.f32 %0, %1, %2;" : "=r"(r) : "f"(b), "f"(a))

// ---------------- scratch ----------------
static __device__ float g_qkvf_t[(size_t)BB*48*FF*TT];
static __device__ float g_qkvf_f[(size_t)BB*TT*48*FF];
static __device__ float g_tqk2 [(size_t)BB*32*FF*TT];
static __device__ float g_fout_t[(size_t)BB*TT*DC*FF];
static __device__ float g_fout_f[(size_t)BB*FF*DC*TT];
static __device__ __align__(16) uint4 g_wafH[640];
static __device__ __align__(16) uint4 g_wafL[640];
static __device__ float g_shift[80];
static __device__ float g_alpha[80];

// greedy-balanced causal tile assignment over 8 warps (chunk loads 38-44)
static __device__ const int TILE_LUT8[8][8] = {
    {24, 14, 0, -1, -1, -1, -1, -1},
    {23, 15, -1, -1, -1, -1, -1, -1},
    {22, 16, -1, -1, -1, -1, -1, -1},
    {21, 17, -1, -1, -1, -1, -1, -1},
    {20, 18, -1, -1, -1, -1, -1, -1},
    {19, 13, 6, -1, -1, -1, -1, -1},
    {12, 11, 10, 4, -1, -1, -1, -1},
    {9, 8, 7, 5, 3, 2, 1, -1}
};

// ================= kernel 0: prep =================
__global__ __launch_bounds__(256)
void asa_prep_kernel(const float* __restrict__ w_fqkv, const float* __restrict__ w_tqk,
    const float* __restrict__ g1, const float* __restrict__ b1,
    const float* __restrict__ m1, const float* __restrict__ v1, const float* __restrict__ a1,
    const float* __restrict__ g2, const float* __restrict__ b2,
    const float* __restrict__ m2, const float* __restrict__ v2, const float* __restrict__ a2)
{
    int i = blockIdx.x * 256 + threadIdx.x;
    if (i < 640) {
        int lane = i & 31, ks = (i >> 5) & 3, o = i >> 7;
        int r = lane >> 2, cp = (lane & 3) * 2;
        int oc0 = o * 16 + r, k0 = ks * 16 + cp;
        uint32_t hiR[4], loR[4];
        #pragma unroll
        for (int aa = 0; aa < 4; aa++) {
            int oc = oc0 + ((aa & 1) << 3);
            int kk = k0 + ((aa >> 1) << 3);
            float s, w0, w1;
            if (oc < 48) {
                s = g1[oc] * rsqrtf(v1[oc] + 1e-5f);
                w0 = w_fqkv[oc * 64 + kk] * s; w1 = w_fqkv[oc * 64 + kk + 1] * s;
            } else {
                int j = oc - 48;
                s = g2[j] * rsqrtf(v2[j] + 1e-5f);
                w0 = w_tqk[j * 64 + kk] * s; w1 = w_tqk[j * 64 + kk + 1] * s;
            }
            uint32_t h; PACKBF(h, w0, w1);
            float r0 = __uint_as_float(h << 16);
            float r1 = __uint_as_float(h & 0xffff0000u);
            uint32_t l; PACKBF(l, w0 - r0, w1 - r1);
            hiR[aa] = h; loR[aa] = l;
        }
        g_wafH[i] = make_uint4(hiR[0], hiR[1], hiR[2], hiR[3]);
        g_wafL[i] = make_uint4(loR[0], loR[1], loR[2], loR[3]);
    }
    if (i < 80) {
        float ss, sh, al;
        if (i < 48) { ss = g1[i] * rsqrtf(v1[i] + 1e-5f); sh = b1[i] - m1[i] * ss; al = a1[i]; }
        else { int j = i - 48; ss = g2[j] * rsqrtf(v2[j] + 1e-5f); sh = b2[j] - m2[j] * ss; al = a2[j]; }
        g_shift[i] = sh; g_alpha[i] = al;
    }
}

// ====== kernel 1: conv1x1 via mma.sync bf16 — float4 loads + smem staging ======
__global__ __launch_bounds__(320)
void asa_conv_mma_kernel(const float* __restrict__ inp)
{
    __shared__ __align__(16) float xstage[64 * 68];
    __shared__ __align__(16) char xhi[8192];
    __shared__ __align__(16) char xlo[8192];
    int tid = threadIdx.x, wid = tid >> 5, lane = tid & 31;
    int b = blockIdx.y;
    int n0 = blockIdx.x * 64;
    const float* xb = inp + (size_t)b * CC * SP + n0;

    for (int i = tid; i < 1024; i += 320) {
        int k = i >> 4, s4 = (i & 15) * 4;
        float4 v = *(const float4*)(xb + (size_t)k * SP + s4);
        *(float4*)(xstage + k * 68 + s4) = v;
    }
    __syncthreads();

    for (int ch = tid; ch < 512; ch += 320) {
        int sp = ch & 63, kb = ch >> 6;
        float v[8];
        #pragma unroll
        for (int j = 0; j < 8; j++) v[j] = xstage[(kb * 8 + j) * 68 + sp];
        uint32_t hp[4], lp[4];
        #pragma unroll
        for (int j = 0; j < 4; j++) {
            uint32_t h; PACKBF(h, v[2*j], v[2*j+1]);
            float r0 = __uint_as_float(h << 16);
            float r1 = __uint_as_float(h & 0xffff0000u);
            uint32_t l; PACKBF(l, v[2*j] - r0, v[2*j+1] - r1);
            hp[j] = h; lp[j] = l;
        }
        uint32_t off = sp * 128 + ((kb * 16) ^ ((sp & 7) << 4));
        *(uint4*)(xhi + off) = make_uint4(hp[0], hp[1], hp[2], hp[3]);
        *(uint4*)(xlo + off) = make_uint4(lp[0], lp[1], lp[2], lp[3]);
    }
    __syncthreads();

    int octile = wid >> 1, sptile = wid & 1;
    uint32_t shi = smem_u32(xhi), slo = smem_u32(xlo);
    float d[4][4];
    #pragma unroll
    for (int nt = 0; nt < 4; nt++)
        #pragma unroll
        for (int j = 0; j < 4; j++) d[nt][j] = 0.f;

    int ln = lane & 15;
    int sprow_base = sptile * 32 + (ln & 7);
    int khalf = ((ln >> 3) & 1) << 3;

    #pragma unroll
    for (int ks = 0; ks < 4; ks++) {
        uint4 ah = g_wafH[(octile * 4 + ks) * 32 + lane];
        uint4 al = g_wafL[(octile * 4 + ks) * 32 + lane];
        #pragma unroll
        for (int nt = 0; nt < 4; nt++) {
            int spr = sprow_base + nt * 8;
            int ke = ks * 16 + khalf;
            uint32_t aoff = spr * 128 + ((ke * 2) ^ ((spr & 7) << 4));
            uint32_t bh0, bh1, bl0, bl1;
            ldmx2(bh0, bh1, shi + aoff);
            ldmx2(bl0, bl1, slo + aoff);
            mma16816(d[nt], ah, bh0, bh1);
            mma16816(d[nt], al, bh0, bh1);
            mma16816(d[nt], ah, bl0, bl1);
        }
    }

    int r = lane >> 2, cp = (lane & 3) * 2;
    #pragma unroll
    for (int half = 0; half < 2; half++) {
        int oc = octile * 16 + r + half * 8;
        float sh = g_shift[oc], al = g_alpha[oc];
        float* dst;
        if (oc < 48) dst = g_qkvf_t + ((size_t)b * 48 + oc) * SP + n0;
        else         dst = g_tqk2  + ((size_t)b * 32 + (oc - 48)) * SP + n0;
        #pragma unroll
        for (int nt = 0; nt < 4; nt++) {
            float v0 = d[nt][half * 2 + 0] + sh; v0 = v0 > 0.f ? v0 : al * v0;
            float v1 = d[nt][half * 2 + 1] + sh; v1 = v1 > 0.f ? v1 : al * v1;
            int sp = sptile * 32 + nt * 8 + cp;
            *(float2*)(dst + sp) = make_float2(v0, v1);
        }
    }
}

// ================= transpose 1 =================
__global__ __launch_bounds__(256)
void asa_transpose_qkv_kernel()
{
    __shared__ float tile[32][33];
    int z = blockIdx.z;
    int t0 = blockIdx.x * 32, f0 = blockIdx.y * 32;
    int tx = threadIdx.x, ty = threadIdx.y;
    size_t ibase = (size_t)z * FF * TT;
    #pragma unroll
    for (int k = 0; k < 32; k += 8) {
        int t = t0 + tx, f = f0 + ty + k;
        if (t < TT) tile[ty + k][tx] = g_qkvf_t[ibase + (size_t)f * TT + t];
    }
    __syncthreads();
    int b = z / 48, oc = z % 48;
    #pragma unroll
    for (int k = 0; k < 32; k += 8) {
        int t = t0 + ty + k, f = f0 + tx;
        if (t < TT) g_qkvf_f[((size_t)(b * TT + t) * 48 + oc) * FF + f] = tile[tx][ty + k];
    }
}

// ========== kernel 2: frequency attention via mma.sync, 8 warps, shared fill ==========
#define FQ_QHI 0
#define FQ_QLO 8192
#define FQ_KHI 16384
#define FQ_KLO 24576
#define FQ_VHI 32768
#define FQ_VLO 40960

__global__ __launch_bounds__(256)
void asa_freq_attn_kernel()
{
    __shared__ __align__(16) char smf[49152];
    int tid = threadIdx.x, wid = tid >> 5, lane = tid & 31;
    int t = blockIdx.x, b = blockIdx.y;
    const float* base = g_qkvf_f + (size_t)(b * TT + t) * 48 * FF;
    uint32_t sb = smem_u32(smf);

    for (int it = 0; it < 8; it++) {
        int idx = it * 256 + tid;
        int row = idx & 255;
        int cp = idx >> 8;
        uint32_t qkoff = (uint32_t)(row * 32 + cp * 4) ^ (uint32_t)(((row >> 2) & 1) << 4);
        {
            float x0 = base[(2*cp) * 256 + row] * QS;
            float x1 = base[(2*cp+1) * 256 + row] * QS;
            uint32_t h; PACKBF(h, x0, x1);
            float r0 = __uint_as_float(h << 16);
            float r1 = __uint_as_float(h & 0xffff0000u);
            uint32_t l; PACKBF(l, x0 - r0, x1 - r1);
            *(uint32_t*)(smf + FQ_QHI + qkoff) = h;
            *(uint32_t*)(smf + FQ_QLO + qkoff) = l;
        }
        {
            float x0 = base[4096 + (2*cp) * 256 + row];
            float x1 = base[4096 + (2*cp+1) * 256 + row];
            uint32_t h; PACKBF(h, x0, x1);
            float r0 = __uint_as_float(h << 16);
            float r1 = __uint_as_float(h & 0xffff0000u);
            uint32_t l; PACKBF(l, x0 - r0, x1 - r1);
            *(uint32_t*)(smf + FQ_KHI + qkoff) = h;
            *(uint32_t*)(smf + FQ_KLO + qkoff) = l;
        }
        {
            float x0 = base[8192 + (2*cp) * 256 + row];
            float x1 = base[8192 + (2*cp+1) * 256 + row];
            uint32_t h; PACKBF(h, x0, x1);
            float r0 = __uint_as_float(h << 16);
            float r1 = __uint_as_float(h & 0xffff0000u);
            uint32_t l; PACKBF(l, x0 - r0, x1 - r1);
            int c0 = 2*cp, c1 = 2*cp + 1, y = row;
            uint32_t o0 = (uint32_t)(c0 * 512 + y * 2) ^ (uint32_t)((c0 & 7) << 4);
            uint32_t o1 = (uint32_t)(c1 * 512 + y * 2) ^ (uint32_t)((c1 & 7) << 4);
            *(uint16_t*)(smf + FQ_VHI + o0) = (uint16_t)(h & 0xffff);
            *(uint16_t*)(smf + FQ_VHI + o1) = (uint16_t)(h >> 16);
            *(uint16_t*)(smf + FQ_VLO + o0) = (uint16_t)(l & 0xffff);
            *(uint16_t*)(smf + FQ_VLO + o1) = (uint16_t)(l >> 16);
        }
    }
    __syncthreads();

    int fw = wid * 32;                 // each warp owns 32 f
    int l16 = lane & 15;
    int kh16 = ((lane >> 4) & 1) << 4;
    uint4 qh[2], ql[2];
    #pragma unroll
    for (int mt = 0; mt < 2; mt++) {
        int fr = fw + mt * 16 + l16;
        uint32_t off = (uint32_t)(fr * 32 + kh16) ^ (uint32_t)(((fr >> 2) & 1) << 4);
        ldmx4(qh[mt], sb + FQ_QHI + off);
        ldmx4(ql[mt], sb + FQ_QLO + off);
    }

    float O[2][2][4];
    #pragma unroll
    for (int mt = 0; mt < 2; mt++)
        #pragma unroll
        for (int nt = 0; nt < 2; nt++)
            #pragma unroll
            for (int j = 0; j < 4; j++) O[mt][nt][j] = 0.f;
    float lsum[4];
    #pragma unroll
    for (int i = 0; i < 4; i++) lsum[i] = 0.f;

    int rlow = l16 & 7;
    int khb = ((l16 >> 3) & 1) << 4;

    for (int y0 = 0; y0 < 256; y0 += 16) {
        uint32_t kb0[2], kb1[2], klb0[2], klb1[2];
        #pragma unroll
        for (int nt = 0; nt < 2; nt++) {
            int kr = y0 + nt * 8 + rlow;
            uint32_t off = (uint32_t)(kr * 32 + khb) ^ (uint32_t)(((kr >> 2) & 1) << 4);
            ldmx2(kb0[nt], kb1[nt], sb + FQ_KHI + off);
            ldmx2(klb0[nt], klb1[nt], sb + FQ_KLO + off);
        }
        float S[2][2][4];
        #pragma unroll
        for (int mt = 0; mt < 2; mt++)
            #pragma unroll
            for (int nt = 0; nt < 2; nt++) {
                #pragma unroll
                for (int j = 0; j < 4; j++) S[mt][nt][j] = 0.f;
                mma16816(S[mt][nt], qh[mt], kb0[nt], kb1[nt]);
                mma16816(S[mt][nt], ql[mt], kb0[nt], kb1[nt]);
                mma16816(S[mt][nt], qh[mt], klb0[nt], klb1[nt]);
            }
        uint4 ph[2], pl[2];
        #pragma unroll
        for (int mt = 0; mt < 2; mt++) {
            float p[2][4];
            #pragma unroll
            for (int nt = 0; nt < 2; nt++)
                #pragma unroll
                for (int j = 0; j < 4; j++) p[nt][j] = ex2f(S[mt][nt][j]);
            lsum[2*mt]   += (p[0][0] + p[0][1]) + (p[1][0] + p[1][1]);
            lsum[2*mt+1] += (p[0][2] + p[0][3]) + (p[1][2] + p[1][3]);
            uint32_t hreg[4], lreg[4];
            #pragma unroll
            for (int q = 0; q < 4; q++) {
                int nt = q >> 1, jo = (q & 1) * 2;
                uint32_t h; PACKBF(h, p[nt][jo], p[nt][jo+1]);
                float r0 = __uint_as_float(h << 16);
                float r1 = __uint_as_float(h & 0xffff0000u);
                uint32_t l; PACKBF(l, p[nt][jo] - r0, p[nt][jo+1] - r1);
                hreg[q] = h; lreg[q] = l;
            }
            ph[mt] = make_uint4(hreg[0], hreg[1], hreg[2], hreg[3]);
            pl[mt] = make_uint4(lreg[0], lreg[1], lreg[2], lreg[3]);
        }
        uint32_t vb0[2], vb1[2], vlb0[2], vlb1[2];
        #pragma unroll
        for (int nt = 0; nt < 2; nt++) {
            int vc = nt * 8 + rlow;
            uint32_t off = (uint32_t)(vc * 512 + y0 * 2 + khb) ^ (uint32_t)((vc & 7) << 4);
            ldmx2(vb0[nt], vb1[nt], sb + FQ_VHI + off);
            ldmx2(vlb0[nt], vlb1[nt], sb + FQ_VLO + off);
        }
        #pragma unroll
        for (int mt = 0; mt < 2; mt++)
            #pragma unroll
            for (int nt = 0; nt < 2; nt++) {
                mma16816(O[mt][nt], ph[mt], vb0[nt], vb1[nt]);
                mma16816(O[mt][nt], pl[mt], vb0[nt], vb1[nt]);
                mma16816(O[mt][nt], ph[mt], vlb0[nt], vlb1[nt]);
            }
    }

    #pragma unroll
    for (int i = 0; i < 4; i++) {
        lsum[i] += __shfl_xor_sync(0xffffffffu, lsum[i], 1);
        lsum[i] += __shfl_xor_sync(0xffffffffu, lsum[i], 2);
    }

    __syncthreads();
    float* st = (float*)smf;   // stage [16c][256f]
    int r = lane >> 2, cq = (lane & 3) * 2;
    #pragma unroll
    for (int mt = 0; mt < 2; mt++) {
        float i0 = 1.f / lsum[2*mt], i1 = 1.f / lsum[2*mt+1];
        int f = fw + mt * 16 + r;
        #pragma unroll
        for (int nt = 0; nt < 2; nt++) {
            int c = nt * 8 + cq;
            st[c * 256 + f]           = O[mt][nt][0] * i0;
            st[(c + 1) * 256 + f]     = O[mt][nt][1] * i0;
            st[c * 256 + f + 8]       = O[mt][nt][2] * i1;
            st[(c + 1) * 256 + f + 8] = O[mt][nt][3] * i1;
        }
    }
    __syncthreads();
    float4* go = (float4*)(g_fout_t + (size_t)(b * TT + t) * DC * FF);
    const float4* s4 = (const float4*)smf;
    for (int i = tid; i < 1024; i += 256) go[i] = s4[i];
}

// ================= transpose 2 =================
__global__ __launch_bounds__(256)
void asa_transpose_fout_kernel()
{
    __shared__ float tile[32][33];
    int z = blockIdx.z;
    int f0 = blockIdx.x * 32, t0 = blockIdx.y * 32;
    int tx = threadIdx.x, ty = threadIdx.y;
    int b = z / 16, c = z % 16;
    #pragma unroll
    for (int k = 0; k < 32; k += 8) {
        int t = t0 + ty + k, f = f0 + tx;
        if (t < TT) tile[ty + k][tx] = g_fout_t[((size_t)(b * TT + t) * DC + c) * FF + f];
    }
    __syncthreads();
    #pragma unroll
    for (int k = 0; k < 32; k += 8) {
        int f = f0 + ty + k, t = t0 + tx;
        if (t < TT) g_fout_f[((size_t)(b * FF + f) * DC + c) * TT + t] = tile[tx][ty + k];
    }
}

// ======= kernel 3: causal time attention via mma.sync, 8 warps =======
#define TQ_QHI 0
#define TQ_QLO 12800
#define TQ_KHI 25600
#define TQ_KLO 38400
#define TQ_VHI 51200
#define TQ_VLO 64256
#define TQ_ST  77312
#define TQ_WP  109312
#define TQ_SC  113408
#define TQ_SH  113664
#define TQ_AL  113920
#define TQ_SMEM 114176

__global__ __launch_bounds__(256, 2)
void asa_time_attn_kernel(const float* __restrict__ inp, const float* __restrict__ w_proj,
    const float* __restrict__ g3, const float* __restrict__ b3, const float* __restrict__ m3,
    const float* __restrict__ v3, const float* __restrict__ a3, float* __restrict__ out)
{
    extern __shared__ char smt[];
    uint32_t sb = smem_u32(smt);
    int tid = threadIdx.x, wid = tid >> 5, lane = tid & 31;
    int f = blockIdx.x, b = blockIdx.y;
    size_t cbase = (size_t)b * 32 * SP + (size_t)f * TT;
    const float* vg = g_fout_f + (size_t)(b * FF + f) * DC * TT;

    #pragma unroll 1
    for (int idx = tid; idx < 3200; idx += 256) {
        int t = idx % 400;
        int cp = idx / 400;
        uint32_t qkoff = (uint32_t)(t * 32 + cp * 4) ^ (uint32_t)(((t >> 2) & 1) << 4);
        {
            float x0 = g_tqk2[cbase + (size_t)(2*cp) * SP + t] * QS;
            float x1 = g_tqk2[cbase + (size_t)(2*cp+1) * SP + t] * QS;
            uint32_t h; PACKBF(h, x0, x1);
            float r0 = __uint_as_float(h << 16);
            float r1 = __uint_as_float(h & 0xffff0000u);
            uint32_t l; PACKBF(l, x0 - r0, x1 - r1);
            *(uint32_t*)(smt + TQ_QHI + qkoff) = h;
            *(uint32_t*)(smt + TQ_QLO + qkoff) = l;
        }
        {
            float x0 = g_tqk2[cbase + (size_t)(16 + 2*cp) * SP + t];
            float x1 = g_tqk2[cbase + (size_t)(17 + 2*cp) * SP + t];
            uint32_t h; PACKBF(h, x0, x1);
            float r0 = __uint_as_float(h << 16);
            float r1 = __uint_as_float(h & 0xffff0000u);
            uint32_t l; PACKBF(l, x0 - r0, x1 - r1);
            *(uint32_t*)(smt + TQ_KHI + qkoff) = h;
            *(uint32_t*)(smt + TQ_KLO + qkoff) = l;
        }
        {
            float x0 = vg[(size_t)(2*cp) * TT + t];
            float x1 = vg[(size_t)(2*cp+1) * TT + t];
            uint32_t h; PACKBF(h, x0, x1);
            float r0 = __uint_as_float(h << 16);
            float r1 = __uint_as_float(h & 0xffff0000u);
            uint32_t l; PACKBF(l, x0 - r0, x1 - r1);
            uint32_t o0 = (uint32_t)((2*cp) * 816 + t * 2);
            uint32_t o1 = (uint32_t)((2*cp+1) * 816 + t * 2);
            *(uint16_t*)(smt + TQ_VHI + o0) = (uint16_t)(h & 0xffff);
            *(uint16_t*)(smt + TQ_VHI + o1) = (uint16_t)(h >> 16);
            *(uint16_t*)(smt + TQ_VLO + o0) = (uint16_t)(l & 0xffff);
            *(uint16_t*)(smt + TQ_VLO + o1) = (uint16_t)(l >> 16);
        }
    }
    for (int i = tid; i < 1024; i += 256) ((float*)(smt + TQ_WP))[i] = w_proj[i];
    if (tid < 64) {
        float s = g3[tid] * rsqrtf(v3[tid] + 1e-5f);
        ((float*)(smt + TQ_SC))[tid] = s;
        ((float*)(smt + TQ_SH))[tid] = b3[tid] - m3[tid] * s;
        ((float*)(smt + TQ_AL))[tid] = a3[tid];
    }
    __syncthreads();

    int l16 = lane & 15;
    int kh16 = ((lane >> 4) & 1) << 4;
    int rlow = l16 & 7;
    int khb = ((l16 >> 3) & 1) << 4;
    int rq = lane >> 2, cq = (lane & 3) * 2;
    float* st = (float*)(smt + TQ_ST);

    #pragma unroll 1
    for (int k8 = 0; k8 < 8; k8++) {
        int tile = TILE_LUT8[wid][k8];
        if (tile < 0) break;

        uint4 qh, ql;
        {
            int fr = tile * 16 + l16;
            uint32_t off = (uint32_t)(fr * 32 + kh16) ^ (uint32_t)(((fr >> 2) & 1) << 4);
            ldmx4(qh, sb + TQ_QHI + off);
            ldmx4(ql, sb + TQ_QLO + off);
        }
        float O[2][4];
        #pragma unroll
        for (int nt = 0; nt < 2; nt++)
            #pragma unroll
            for (int j = 0; j < 4; j++) O[nt][j] = 0.f;
        float ls0 = 0.f, ls1 = 0.f;

        #pragma unroll 1
        for (int ch = 0; ch <= tile; ch++) {
            int y0 = ch * 16;
            uint32_t kb0[2], kb1[2], klb0[2], klb1[2];
            #pragma unroll
            for (int nt = 0; nt < 2; nt++) {
                int kr = y0 + nt * 8 + rlow;
                uint32_t off = (uint32_t)(kr * 32 + khb) ^ (uint32_t)(((kr >> 2) & 1) << 4);
                ldmx2(kb0[nt], kb1[nt], sb + TQ_KHI + off);
                ldmx2(klb0[nt], klb1[nt], sb + TQ_KLO + off);
            }
            float S[2][4];
            #pragma unroll
            for (int nt = 0; nt < 2; nt++) {
                #pragma unroll
                for (int j = 0; j < 4; j++) S[nt][j] = 0.f;
                mma16816(S[nt], qh, kb0[nt], kb1[nt]);
                mma16816(S[nt], ql, kb0[nt], kb1[nt]);
                mma16816(S[nt], qh, klb0[nt], klb1[nt]);
            }
            if (ch == tile) {
                #pragma unroll
                for (int nt = 0; nt < 2; nt++) {
                    int c0 = nt * 8 + cq;
                    if (c0     > rq)     S[nt][0] = -3e38f;
                    if (c0 + 1 > rq)     S[nt][1] = -3e38f;
                    if (c0     > rq + 8) S[nt][2] = -3e38f;
                    if (c0 + 1 > rq + 8) S[nt][3] = -3e38f;
                }
            }
            float p[2][4];
            #pragma unroll
            for (int nt = 0; nt < 2; nt++)
                #pragma unroll
                for (int j = 0; j < 4; j++) p[nt][j] = ex2f(S[nt][j]);
            ls0 += (p[0][0] + p[0][1]) + (p[1][0] + p[1][1]);
            ls1 += (p[0][2] + p[0][3]) + (p[1][2] + p[1][3]);
            uint32_t hreg[4], lreg[4];
            #pragma unroll
            for (int q = 0; q < 4; q++) {
                int nt = q >> 1, jo = (q & 1) * 2;
                uint32_t h; PACKBF(h, p[nt][jo], p[nt][jo+1]);
                float r0 = __uint_as_float(h << 16);
                float r1 = __uint_as_float(h & 0xffff0000u);
                uint32_t l; PACKBF(l, p[nt][jo] - r0, p[nt][jo+1] - r1);
                hreg[q] = h; lreg[q] = l;
            }
            uint4 ph = make_uint4(hreg[0], hreg[1], hreg[2], hreg[3]);
            uint4 pl = make_uint4(lreg[0], lreg[1], lreg[2], lreg[3]);

            uint32_t vb0[2], vb1[2], vlb0[2], vlb1[2];
            #pragma unroll
            for (int nt = 0; nt < 2; nt++) {
                int vc = nt * 8 + rlow;
                uint32_t off = (uint32_t)(vc * 816 + y0 * 2 + khb);
                ldmx2(vb0[nt], vb1[nt], sb + TQ_VHI + off);
                ldmx2(vlb0[nt], vlb1[nt], sb + TQ_VLO + off);
            }
            #pragma unroll
            for (int nt = 0; nt < 2; nt++) {
                mma16816(O[nt], ph, vb0[nt], vb1[nt]);
                mma16816(O[nt], pl, vb0[nt], vb1[nt]);
                mma16816(O[nt], ph, vlb0[nt], vlb1[nt]);
            }
        }

        ls0 += __shfl_xor_sync(0xffffffffu, ls0, 1);
        ls0 += __shfl_xor_sync(0xffffffffu, ls0, 2);
        ls1 += __shfl_xor_sync(0xffffffffu, ls1, 1);
        ls1 += __shfl_xor_sync(0xffffffffu, ls1, 2);
        float i0 = 1.f / ls0, i1 = 1.f / ls1;

        int row0 = tile * 16 + rq, row1 = row0 + 8;
        #pragma unroll
        for (int nt = 0; nt < 2; nt++) {
            int c = nt * 8 + cq;
            st[row0 * 20 + c]     = O[nt][0] * i0;
            st[row0 * 20 + c + 1] = O[nt][1] * i0;
            st[row1 * 20 + c]     = O[nt][2] * i1;
            st[row1 * 20 + c + 1] = O[nt][3] * i1;
        }
    }
    __syncthreads();

    const float* wp  = (const float*)(smt + TQ_WP);
    const float* sc3 = (const float*)(smt + TQ_SC);
    const float* sh3 = (const float*)(smt + TQ_SH);
    const float* al3 = (const float*)(smt + TQ_AL);
    #pragma unroll 1
    for (int t = tid; t < 400; t += 256) {
        float a[16];
        const float* sr = st + t * 20;
        #pragma unroll
        for (int c = 0; c < 16; c++) a[c] = sr[c];
        size_t obase = (((size_t)b * CC) * FF + f) * TT + t;
        #pragma unroll 8
        for (int oc = 0; oc < CC; oc++) {
            const float4* wr = (const float4*)(wp + oc * 16);
            float4 w0 = wr[0], w1 = wr[1], w2 = wr[2], w3 = wr[3];
            float r = 0.f;
            r = fmaf(w0.x, a[0],  r); r = fmaf(w0.y, a[1],  r);
            r = fmaf(w0.z, a[2],  r); r = fmaf(w0.w, a[3],  r);
            r = fmaf(w1.x, a[4],  r); r = fmaf(w1.y, a[5],  r);
            r = fmaf(w1.z, a[6],  r); r = fmaf(w1.w, a[7],  r);
            r = fmaf(w2.x, a[8],  r); r = fmaf(w2.y, a[9],  r);
            r = fmaf(w2.z, a[10], r); r = fmaf(w2.w, a[11], r);
            r = fmaf(w3.x, a[12], r); r = fmaf(w3.y, a[13], r);
            r = fmaf(w3.z, a[14], r); r = fmaf(w3.w, a[15], r);
            r = fmaf(r, sc3[oc], sh3[oc]);
            r = r > 0.f ? r : al3[oc] * r;
            out[obase + (size_t)oc * SP] = r + inp[obase + (size_t)oc * SP];
        }
    }
}

// ================= launcher =================
extern "C" void kernel_launch(void* const* d_in, const int* in_sizes, int n_in,
                              void* d_out, int out_size)
{
    (void)in_sizes; (void)n_in; (void)out_size;
    const float* inp    = (const float*)d_in[0];
    const float* w_fqkv = (const float*)d_in[2];
    const float* g1 = (const float*)d_in[3];
    const float* b1 = (const float*)d_in[4];
    const float* m1 = (const float*)d_in[5];
    const float* v1 = (const float*)d_in[6];
    const float* a1 = (const float*)d_in[7];
    const float* w_tqk  = (const float*)d_in[8];
    const float* g2 = (const float*)d_in[9];
    const float* b2 = (const float*)d_in[10];
    const float* m2 = (const float*)d_in[11];
    const float* v2 = (const float*)d_in[12];
    const float* a2 = (const float*)d_in[13];
    const float* w_proj = (const float*)d_in[14];
    const float* g3 = (const float*)d_in[15];
    const float* b3 = (const float*)d_in[16];
    const float* m3 = (const float*)d_in[17];
    const float* v3 = (const float*)d_in[18];
    const float* a3 = (const float*)d_in[19];
    float* out = (float*)d_out;

    cudaFuncSetAttribute(asa_time_attn_kernel,
                         cudaFuncAttributeMaxDynamicSharedMemorySize, TQ_SMEM);

    asa_prep_kernel<<<3, 256>>>(w_fqkv, w_tqk, g1, b1, m1, v1, a1,
                                g2, b2, m2, v2, a2);
    asa_conv_mma_kernel<<<dim3(1600, BB), 320>>>(inp);
    asa_transpose_qkv_kernel<<<dim3(13, 8, BB * 48), dim3(32, 8)>>>();
    asa_freq_attn_kernel<<<dim3(TT, BB), 256>>>();
    asa_transpose_fout_kernel<<<dim3(8, 13, BB * 16), dim3(32, 8)>>>();
    asa_time_attn_kernel<<<dim3(FF, BB), 256, TQ_SMEM>>>(inp, w_proj,
        g3, b3, m3, v3, a3, out);
}

// round 13
// speedup vs baseline: 1.0780x; 1.0009x over previous
#include <cuda_runtime.h>
#include <cuda_bf16.h>
#include <cstdint>
#include <math.h>

#define BB 4
#define CC 64
#define FF 256
#define TT 400
#define DC 16
#define SP (FF*TT)

#define QS 0.36067376022224085f   /* 0.25 * log2(e) */

__device__ __forceinline__ float ex2f(float x) {
    float r; asm("ex2.approx.ftz.f32 %0, %1;" : "=f"(r) : "f"(x)); return r;
}
__device__ __forceinline__ uint32_t smem_u32(const void* p) {
    uint32_t a;
    asm("{ .reg .u64 t; cvta.to.shared.u64 t, %1; cvt.u32.u64 %0, t; }" : "=r"(a) : "l"(p));
    return a;
}
__device__ __forceinline__ void ldmx2(uint32_t& r0, uint32_t& r1, uint32_t a) {
    asm volatile("ldmatrix.sync.aligned.m8n8.x2.shared.b16 {%0,%1}, [%2];"
                 : "=r"(r0), "=r"(r1) : "r"(a));
}
__device__ __forceinline__ void ldmx4(uint4& r, uint32_t a) {
    asm volatile("ldmatrix.sync.aligned.m8n8.x4.shared.b16 {%0,%1,%2,%3}, [%4];"
                 : "=r"(r.x), "=r"(r.y), "=r"(r.z), "=r"(r.w) : "r"(a));
}
__device__ __forceinline__ void mma16816(float* d, uint4 a, uint32_t b0, uint32_t b1) {
    asm volatile("mma.sync.aligned.m16n8k16.row.col.f32.bf16.bf16.f32 "
        "{%0,%1,%2,%3}, {%4,%5,%6,%7}, {%8,%9}, {%0,%1,%2,%3};"
        : "+f"(d[0]), "+f"(d[1]), "+f"(d[2]), "+f"(d[3])
        : "r"(a.x), "r"(a.y), "r"(a.z), "r"(a.w), "r"(b0), "r"(b1));
}
#define PACKBF(r, a, b) asm("cvt.rn.bf16x2.f32 %0, %1, %2;" : "=r"(r) : "f"(b), "f"(a))

// ---------------- scratch ----------------
static __device__ float g_qkvf_t[(size_t)BB*48*FF*TT];
static __device__ float g_qkvf_f[(size_t)BB*TT*48*FF];
static __device__ float g_tqk2 [(size_t)BB*32*FF*TT];
static __device__ float g_fout_t[(size_t)BB*TT*DC*FF];
static __device__ float g_fout_f[(size_t)BB*FF*DC*TT];
static __device__ __align__(16) uint4 g_wafH[640];
static __device__ __align__(16) uint4 g_wafL[640];
static __device__ __align__(16) uint4 g_wpfH[128];   // proj W fragments [mtile4][lane32]
static __device__ __align__(16) uint4 g_wpfL[128];
static __device__ float g_shift[80];
static __device__ float g_alpha[80];

// greedy-balanced causal tile assignment over 8 warps (chunk loads 38-44)
static __device__ const int TILE_LUT8[8][8] = {
    {24, 14, 0, -1, -1, -1, -1, -1},
    {23, 15, -1, -1, -1, -1, -1, -1},
    {22, 16, -1, -1, -1, -1, -1, -1},
    {21, 17, -1, -1, -1, -1, -1, -1},
    {20, 18, -1, -1, -1, -1, -1, -1},
    {19, 13, 6, -1, -1, -1, -1, -1},
    {12, 11, 10, 4, -1, -1, -1, -1},
    {9, 8, 7, 5, 3, 2, 1, -1}
};

// ================= kernel 0: prep =================
__global__ __launch_bounds__(256)
void asa_prep_kernel(const float* __restrict__ w_fqkv, const float* __restrict__ w_tqk,
    const float* __restrict__ g1, const float* __restrict__ b1,
    const float* __restrict__ m1, const float* __restrict__ v1, const float* __restrict__ a1,
    const float* __restrict__ g2, const float* __restrict__ b2,
    const float* __restrict__ m2, const float* __restrict__ v2, const float* __restrict__ a2,
    const float* __restrict__ w_proj, const float* __restrict__ g3, const float* __restrict__ v3)
{
    int i = blockIdx.x * 256 + threadIdx.x;
    if (i < 640) {
        int lane = i & 31, ks = (i >> 5) & 3, o = i >> 7;
        int r = lane >> 2, cp = (lane & 3) * 2;
        int oc0 = o * 16 + r, k0 = ks * 16 + cp;
        uint32_t hiR[4], loR[4];
        #pragma unroll
        for (int aa = 0; aa < 4; aa++) {
            int oc = oc0 + ((aa & 1) << 3);
            int kk = k0 + ((aa >> 1) << 3);
            float s, w0, w1;
            if (oc < 48) {
                s = g1[oc] * rsqrtf(v1[oc] + 1e-5f);
                w0 = w_fqkv[oc * 64 + kk] * s; w1 = w_fqkv[oc * 64 + kk + 1] * s;
            } else {
                int j = oc - 48;
                s = g2[j] * rsqrtf(v2[j] + 1e-5f);
                w0 = w_tqk[j * 64 + kk] * s; w1 = w_tqk[j * 64 + kk + 1] * s;
            }
            uint32_t h; PACKBF(h, w0, w1);
            float r0 = __uint_as_float(h << 16);
            float r1 = __uint_as_float(h & 0xffff0000u);
            uint32_t l; PACKBF(l, w0 - r0, w1 - r1);
            hiR[aa] = h; loR[aa] = l;
        }
        g_wafH[i] = make_uint4(hiR[0], hiR[1], hiR[2], hiR[3]);
        g_wafL[i] = make_uint4(loR[0], loR[1], loR[2], loR[3]);
    } else if (i < 768) {
        // projection W fragments: D[64oc,.] = W[64,16] (BN3 scale folded)
        int idx = i - 640;
        int lane = idx & 31, o = idx >> 5;
        int r = lane >> 2, cp = (lane & 3) * 2;
        uint32_t hiR[4], loR[4];
        #pragma unroll
        for (int aa = 0; aa < 4; aa++) {
            int oc = o * 16 + r + ((aa & 1) << 3);
            int kk = cp + ((aa >> 1) << 3);
            float s = g3[oc] * rsqrtf(v3[oc] + 1e-5f);
            float w0 = w_proj[oc * 16 + kk] * s;
            float w1 = w_proj[oc * 16 + kk + 1] * s;
            uint32_t h; PACKBF(h, w0, w1);
            float r0 = __uint_as_float(h << 16);
            float r1 = __uint_as_float(h & 0xffff0000u);
            uint32_t l; PACKBF(l, w0 - r0, w1 - r1);
            hiR[aa] = h; loR[aa] = l;
        }
        g_wpfH[idx] = make_uint4(hiR[0], hiR[1], hiR[2], hiR[3]);
        g_wpfL[idx] = make_uint4(loR[0], loR[1], loR[2], loR[3]);
    }
    if (i < 80) {
        float ss, sh, al;
        if (i < 48) { ss = g1[i] * rsqrtf(v1[i] + 1e-5f); sh = b1[i] - m1[i] * ss; al = a1[i]; }
        else { int j = i - 48; ss = g2[j] * rsqrtf(v2[j] + 1e-5f); sh = b2[j] - m2[j] * ss; al = a2[j]; }
        g_shift[i] = sh; g_alpha[i] = al;
    }
}

// ====== kernel 1: conv1x1 via mma.sync bf16 — float4 loads + smem staging ======
__global__ __launch_bounds__(320)
void asa_conv_mma_kernel(const float* __restrict__ inp)
{
    __shared__ __align__(16) float xstage[64 * 68];
    __shared__ __align__(16) char xhi[8192];
    __shared__ __align__(16) char xlo[8192];
    int tid = threadIdx.x, wid = tid >> 5, lane = tid & 31;
    int b = blockIdx.y;
    int n0 = blockIdx.x * 64;
    const float* xb = inp + (size_t)b * CC * SP + n0;

    for (int i = tid; i < 1024; i += 320) {
        int k = i >> 4, s4 = (i & 15) * 4;
        float4 v = *(const float4*)(xb + (size_t)k * SP + s4);
        *(float4*)(xstage + k * 68 + s4) = v;
    }
    __syncthreads();

    for (int ch = tid; ch < 512; ch += 320) {
        int sp = ch & 63, kb = ch >> 6;
        float v[8];
        #pragma unroll
        for (int j = 0; j < 8; j++) v[j] = xstage[(kb * 8 + j) * 68 + sp];
        uint32_t hp[4], lp[4];
        #pragma unroll
        for (int j = 0; j < 4; j++) {
            uint32_t h; PACKBF(h, v[2*j], v[2*j+1]);
            float r0 = __uint_as_float(h << 16);
            float r1 = __uint_as_float(h & 0xffff0000u);
            uint32_t l; PACKBF(l, v[2*j] - r0, v[2*j+1] - r1);
            hp[j] = h; lp[j] = l;
        }
        uint32_t off = sp * 128 + ((kb * 16) ^ ((sp & 7) << 4));
        *(uint4*)(xhi + off) = make_uint4(hp[0], hp[1], hp[2], hp[3]);
        *(uint4*)(xlo + off) = make_uint4(lp[0], lp[1], lp[2], lp[3]);
    }
    __syncthreads();

    int octile = wid >> 1, sptile = wid & 1;
    uint32_t shi = smem_u32(xhi), slo = smem_u32(xlo);
    float d[4][4];
    #pragma unroll
    for (int nt = 0; nt < 4; nt++)
        #pragma unroll
        for (int j = 0; j < 4; j++) d[nt][j] = 0.f;

    int ln = lane & 15;
    int sprow_base = sptile * 32 + (ln & 7);
    int khalf = ((ln >> 3) & 1) << 3;

    #pragma unroll
    for (int ks = 0; ks < 4; ks++) {
        uint4 ah = g_wafH[(octile * 4 + ks) * 32 + lane];
        uint4 al = g_wafL[(octile * 4 + ks) * 32 + lane];
        #pragma unroll
        for (int nt = 0; nt < 4; nt++) {
            int spr = sprow_base + nt * 8;
            int ke = ks * 16 + khalf;
            uint32_t aoff = spr * 128 + ((ke * 2) ^ ((spr & 7) << 4));
            uint32_t bh0, bh1, bl0, bl1;
            ldmx2(bh0, bh1, shi + aoff);
            ldmx2(bl0, bl1, slo + aoff);
            mma16816(d[nt], ah, bh0, bh1);
            mma16816(d[nt], al, bh0, bh1);
            mma16816(d[nt], ah, bl0, bl1);
        }
    }

    int r = lane >> 2, cp = (lane & 3) * 2;
    #pragma unroll
    for (int half = 0; half < 2; half++) {
        int oc = octile * 16 + r + half * 8;
        float sh = g_shift[oc], al = g_alpha[oc];
        float* dst;
        if (oc < 48) dst = g_qkvf_t + ((size_t)b * 48 + oc) * SP + n0;
        else         dst = g_tqk2  + ((size_t)b * 32 + (oc - 48)) * SP + n0;
        #pragma unroll
        for (int nt = 0; nt < 4; nt++) {
            float v0 = d[nt][half * 2 + 0] + sh; v0 = v0 > 0.f ? v0 : al * v0;
            float v1 = d[nt][half * 2 + 1] + sh; v1 = v1 > 0.f ? v1 : al * v1;
            int sp = sptile * 32 + nt * 8 + cp;
            *(float2*)(dst + sp) = make_float2(v0, v1);
        }
    }
}

// ================= transpose 1 =================
__global__ __launch_bounds__(256)
void asa_transpose_qkv_kernel()
{
    __shared__ float tile[32][33];
    int z = blockIdx.z;
    int t0 = blockIdx.x * 32, f0 = blockIdx.y * 32;
    int tx = threadIdx.x, ty = threadIdx.y;
    size_t ibase = (size_t)z * FF * TT;
    #pragma unroll
    for (int k = 0; k < 32; k += 8) {
        int t = t0 + tx, f = f0 + ty + k;
        if (t < TT) tile[ty + k][tx] = g_qkvf_t[ibase + (size_t)f * TT + t];
    }
    __syncthreads();
    int b = z / 48, oc = z % 48;
    #pragma unroll
    for (int k = 0; k < 32; k += 8) {
        int t = t0 + ty + k, f = f0 + tx;
        if (t < TT) g_qkvf_f[((size_t)(b * TT + t) * 48 + oc) * FF + f] = tile[tx][ty + k];
    }
}

// ========== kernel 2: frequency attention via mma.sync, 8 warps, shared fill ==========
#define FQ_QHI 0
#define FQ_QLO 8192
#define FQ_KHI 16384
#define FQ_KLO 24576
#define FQ_VHI 32768
#define FQ_VLO 40960

__global__ __launch_bounds__(256)
void asa_freq_attn_kernel()
{
    __shared__ __align__(16) char smf[49152];
    int tid = threadIdx.x, wid = tid >> 5, lane = tid & 31;
    int t = blockIdx.x, b = blockIdx.y;
    const float* base = g_qkvf_f + (size_t)(b * TT + t) * 48 * FF;
    uint32_t sb = smem_u32(smf);

    for (int it = 0; it < 8; it++) {
        int idx = it * 256 + tid;
        int row = idx & 255;
        int cp = idx >> 8;
        uint32_t qkoff = (uint32_t)(row * 32 + cp * 4) ^ (uint32_t)(((row >> 2) & 1) << 4);
        {
            float x0 = base[(2*cp) * 256 + row] * QS;
            float x1 = base[(2*cp+1) * 256 + row] * QS;
            uint32_t h; PACKBF(h, x0, x1);
            float r0 = __uint_as_float(h << 16);
            float r1 = __uint_as_float(h & 0xffff0000u);
            uint32_t l; PACKBF(l, x0 - r0, x1 - r1);
            *(uint32_t*)(smf + FQ_QHI + qkoff) = h;
            *(uint32_t*)(smf + FQ_QLO + qkoff) = l;
        }
        {
            float x0 = base[4096 + (2*cp) * 256 + row];
            float x1 = base[4096 + (2*cp+1) * 256 + row];
            uint32_t h; PACKBF(h, x0, x1);
            float r0 = __uint_as_float(h << 16);
            float r1 = __uint_as_float(h & 0xffff0000u);
            uint32_t l; PACKBF(l, x0 - r0, x1 - r1);
            *(uint32_t*)(smf + FQ_KHI + qkoff) = h;
            *(uint32_t*)(smf + FQ_KLO + qkoff) = l;
        }
        {
            float x0 = base[8192 + (2*cp) * 256 + row];
            float x1 = base[8192 + (2*cp+1) * 256 + row];
            uint32_t h; PACKBF(h, x0, x1);
            float r0 = __uint_as_float(h << 16);
            float r1 = __uint_as_float(h & 0xffff0000u);
            uint32_t l; PACKBF(l, x0 - r0, x1 - r1);
            int c0 = 2*cp, c1 = 2*cp + 1, y = row;
            uint32_t o0 = (uint32_t)(c0 * 512 + y * 2) ^ (uint32_t)((c0 & 7) << 4);
            uint32_t o1 = (uint32_t)(c1 * 512 + y * 2) ^ (uint32_t)((c1 & 7) << 4);
            *(uint16_t*)(smf + FQ_VHI + o0) = (uint16_t)(h & 0xffff);
            *(uint16_t*)(smf + FQ_VHI + o1) = (uint16_t)(h >> 16);
            *(uint16_t*)(smf + FQ_VLO + o0) = (uint16_t)(l & 0xffff);
            *(uint16_t*)(smf + FQ_VLO + o1) = (uint16_t)(l >> 16);
        }
    }
    __syncthreads();

    int fw = wid * 32;
    int l16 = lane & 15;
    int kh16 = ((lane >> 4) & 1) << 4;
    uint4 qh[2], ql[2];
    #pragma unroll
    for (int mt = 0; mt < 2; mt++) {
        int fr = fw + mt * 16 + l16;
        uint32_t off = (uint32_t)(fr * 32 + kh16) ^ (uint32_t)(((fr >> 2) & 1) << 4);
        ldmx4(qh[mt], sb + FQ_QHI + off);
        ldmx4(ql[mt], sb + FQ_QLO + off);
    }

    float O[2][2][4];
    #pragma unroll
    for (int mt = 0; mt < 2; mt++)
        #pragma unroll
        for (int nt = 0; nt < 2; nt++)
            #pragma unroll
            for (int j = 0; j < 4; j++) O[mt][nt][j] = 0.f;
    float lsum[4];
    #pragma unroll
    for (int i = 0; i < 4; i++) lsum[i] = 0.f;

    int rlow = l16 & 7;
    int khb = ((l16 >> 3) & 1) << 4;

    for (int y0 = 0; y0 < 256; y0 += 16) {
        uint32_t kb0[2], kb1[2], klb0[2], klb1[2];
        #pragma unroll
        for (int nt = 0; nt < 2; nt++) {
            int kr = y0 + nt * 8 + rlow;
            uint32_t off = (uint32_t)(kr * 32 + khb) ^ (uint32_t)(((kr >> 2) & 1) << 4);
            ldmx2(kb0[nt], kb1[nt], sb + FQ_KHI + off);
            ldmx2(klb0[nt], klb1[nt], sb + FQ_KLO + off);
        }
        float S[2][2][4];
        #pragma unroll
        for (int mt = 0; mt < 2; mt++)
            #pragma unroll
            for (int nt = 0; nt < 2; nt++) {
                #pragma unroll
                for (int j = 0; j < 4; j++) S[mt][nt][j] = 0.f;
                mma16816(S[mt][nt], qh[mt], kb0[nt], kb1[nt]);
                mma16816(S[mt][nt], ql[mt], kb0[nt], kb1[nt]);
                mma16816(S[mt][nt], qh[mt], klb0[nt], klb1[nt]);
            }
        uint4 ph[2], pl[2];
        #pragma unroll
        for (int mt = 0; mt < 2; mt++) {
            float p[2][4];
            #pragma unroll
            for (int nt = 0; nt < 2; nt++)
                #pragma unroll
                for (int j = 0; j < 4; j++) p[nt][j] = ex2f(S[mt][nt][j]);
            lsum[2*mt]   += (p[0][0] + p[0][1]) + (p[1][0] + p[1][1]);
            lsum[2*mt+1] += (p[0][2] + p[0][3]) + (p[1][2] + p[1][3]);
            uint32_t hreg[4], lreg[4];
            #pragma unroll
            for (int q = 0; q < 4; q++) {
                int nt = q >> 1, jo = (q & 1) * 2;
                uint32_t h; PACKBF(h, p[nt][jo], p[nt][jo+1]);
                float r0 = __uint_as_float(h << 16);
                float r1 = __uint_as_float(h & 0xffff0000u);
                uint32_t l; PACKBF(l, p[nt][jo] - r0, p[nt][jo+1] - r1);
                hreg[q] = h; lreg[q] = l;
            }
            ph[mt] = make_uint4(hreg[0], hreg[1], hreg[2], hreg[3]);
            pl[mt] = make_uint4(lreg[0], lreg[1], lreg[2], lreg[3]);
        }
        uint32_t vb0[2], vb1[2], vlb0[2], vlb1[2];
        #pragma unroll
        for (int nt = 0; nt < 2; nt++) {
            int vc = nt * 8 + rlow;
            uint32_t off = (uint32_t)(vc * 512 + y0 * 2 + khb) ^ (uint32_t)((vc & 7) << 4);
            ldmx2(vb0[nt], vb1[nt], sb + FQ_VHI + off);
            ldmx2(vlb0[nt], vlb1[nt], sb + FQ_VLO + off);
        }
        #pragma unroll
        for (int mt = 0; mt < 2; mt++)
            #pragma unroll
            for (int nt = 0; nt < 2; nt++) {
                mma16816(O[mt][nt], ph[mt], vb0[nt], vb1[nt]);
                mma16816(O[mt][nt], pl[mt], vb0[nt], vb1[nt]);
                mma16816(O[mt][nt], ph[mt], vlb0[nt], vlb1[nt]);
            }
    }

    #pragma unroll
    for (int i = 0; i < 4; i++) {
        lsum[i] += __shfl_xor_sync(0xffffffffu, lsum[i], 1);
        lsum[i] += __shfl_xor_sync(0xffffffffu, lsum[i], 2);
    }

    __syncthreads();
    float* st = (float*)smf;
    int r = lane >> 2, cq = (lane & 3) * 2;
    #pragma unroll
    for (int mt = 0; mt < 2; mt++) {
        float i0 = 1.f / lsum[2*mt], i1 = 1.f / lsum[2*mt+1];
        int f = fw + mt * 16 + r;
        #pragma unroll
        for (int nt = 0; nt < 2; nt++) {
            int c = nt * 8 + cq;
            st[c * 256 + f]           = O[mt][nt][0] * i0;
            st[(c + 1) * 256 + f]     = O[mt][nt][1] * i0;
            st[c * 256 + f + 8]       = O[mt][nt][2] * i1;
            st[(c + 1) * 256 + f + 8] = O[mt][nt][3] * i1;
        }
    }
    __syncthreads();
    float4* go = (float4*)(g_fout_t + (size_t)(b * TT + t) * DC * FF);
    const float4* s4 = (const float4*)smf;
    for (int i = tid; i < 1024; i += 256) go[i] = s4[i];
}

// ================= transpose 2 =================
__global__ __launch_bounds__(256)
void asa_transpose_fout_kernel()
{
    __shared__ float tile[32][33];
    int z = blockIdx.z;
    int f0 = blockIdx.x * 32, t0 = blockIdx.y * 32;
    int tx = threadIdx.x, ty = threadIdx.y;
    int b = z / 16, c = z % 16;
    #pragma unroll
    for (int k = 0; k < 32; k += 8) {
        int t = t0 + ty + k, f = f0 + tx;
        if (t < TT) tile[ty + k][tx] = g_fout_t[((size_t)(b * TT + t) * DC + c) * FF + f];
    }
    __syncthreads();
    #pragma unroll
    for (int k = 0; k < 32; k += 8) {
        int f = f0 + ty + k, t = t0 + tx;
        if (t < TT) g_fout_f[((size_t)(b * FF + f) * DC + c) * TT + t] = tile[tx][ty + k];
    }
}

// ======= kernel 3: causal time attention via mma.sync + mma projection =======
#define TQ_QHI 0
#define TQ_QLO 12800
#define TQ_KHI 25600
#define TQ_KLO 38400
#define TQ_VHI 51200
#define TQ_VLO 64256
#define TQ_PHI 77312     /* P bf16 hi: 400 rows x 32B = 12800 */
#define TQ_PLO 90112     /* P bf16 lo */
#define TQ_SH  102912
#define TQ_AL  103168
#define TQ_SMEM 103424

__global__ __launch_bounds__(256, 2)
void asa_time_attn_kernel(const float* __restrict__ inp,
    const float* __restrict__ g3, const float* __restrict__ b3, const float* __restrict__ m3,
    const float* __restrict__ v3, const float* __restrict__ a3, float* __restrict__ out)
{
    extern __shared__ char smt[];
    uint32_t sb = smem_u32(smt);
    int tid = threadIdx.x, wid = tid >> 5, lane = tid & 31;
    int f = blockIdx.x, b = blockIdx.y;
    size_t cbase = (size_t)b * 32 * SP + (size_t)f * TT;
    const float* vg = g_fout_f + (size_t)(b * FF + f) * DC * TT;

    #pragma unroll 1
    for (int idx = tid; idx < 3200; idx += 256) {
        int t = idx % 400;
        int cp = idx / 400;
        uint32_t qkoff = (uint32_t)(t * 32 + cp * 4) ^ (uint32_t)(((t >> 2) & 1) << 4);
        {
            float x0 = g_tqk2[cbase + (size_t)(2*cp) * SP + t] * QS;
            float x1 = g_tqk2[cbase + (size_t)(2*cp+1) * SP + t] * QS;
            uint32_t h; PACKBF(h, x0, x1);
            float r0 = __uint_as_float(h << 16);
            float r1 = __uint_as_float(h & 0xffff0000u);
            uint32_t l; PACKBF(l, x0 - r0, x1 - r1);
            *(uint32_t*)(smt + TQ_QHI + qkoff) = h;
            *(uint32_t*)(smt + TQ_QLO + qkoff) = l;
        }
        {
            float x0 = g_tqk2[cbase + (size_t)(16 + 2*cp) * SP + t];
            float x1 = g_tqk2[cbase + (size_t)(17 + 2*cp) * SP + t];
            uint32_t h; PACKBF(h, x0, x1);
            float r0 = __uint_as_float(h << 16);
            float r1 = __uint_as_float(h & 0xffff0000u);
            uint32_t l; PACKBF(l, x0 - r0, x1 - r1);
            *(uint32_t*)(smt + TQ_KHI + qkoff) = h;
            *(uint32_t*)(smt + TQ_KLO + qkoff) = l;
        }
        {
            float x0 = vg[(size_t)(2*cp) * TT + t];
            float x1 = vg[(size_t)(2*cp+1) * TT + t];
            uint32_t h; PACKBF(h, x0, x1);
            float r0 = __uint_as_float(h << 16);
            float r1 = __uint_as_float(h & 0xffff0000u);
            uint32_t l; PACKBF(l, x0 - r0, x1 - r1);
            uint32_t o0 = (uint32_t)((2*cp) * 816 + t * 2);
            uint32_t o1 = (uint32_t)((2*cp+1) * 816 + t * 2);
            *(uint16_t*)(smt + TQ_VHI + o0) = (uint16_t)(h & 0xffff);
            *(uint16_t*)(smt + TQ_VHI + o1) = (uint16_t)(h >> 16);
            *(uint16_t*)(smt + TQ_VLO + o0) = (uint16_t)(l & 0xffff);
            *(uint16_t*)(smt + TQ_VLO + o1) = (uint16_t)(l >> 16);
        }
    }
    if (tid < 64) {
        float s = g3[tid] * rsqrtf(v3[tid] + 1e-5f);
        ((float*)(smt + TQ_SH))[tid] = b3[tid] - m3[tid] * s;
        ((float*)(smt + TQ_AL))[tid] = a3[tid];
    }
    __syncthreads();

    int l16 = lane & 15;
    int kh16 = ((lane >> 4) & 1) << 4;
    int rlow = l16 & 7;
    int khb = ((l16 >> 3) & 1) << 4;
    int rq = lane >> 2, cq = (lane & 3) * 2;

    #pragma unroll 1
    for (int k8 = 0; k8 < 8; k8++) {
        int tile = TILE_LUT8[wid][k8];
        if (tile < 0) break;

        uint4 qh, ql;
        {
            int fr = tile * 16 + l16;
            uint32_t off = (uint32_t)(fr * 32 + kh16) ^ (uint32_t)(((fr >> 2) & 1) << 4);
            ldmx4(qh, sb + TQ_QHI + off);
            ldmx4(ql, sb + TQ_QLO + off);
        }
        float O[2][4];
        #pragma unroll
        for (int nt = 0; nt < 2; nt++)
            #pragma unroll
            for (int j = 0; j < 4; j++) O[nt][j] = 0.f;
        float ls0 = 0.f, ls1 = 0.f;

        #pragma unroll 1
        for (int ch = 0; ch <= tile; ch++) {
            int y0 = ch * 16;
            uint32_t kb0[2], kb1[2], klb0[2], klb1[2];
            #pragma unroll
            for (int nt = 0; nt < 2; nt++) {
                int kr = y0 + nt * 8 + rlow;
                uint32_t off = (uint32_t)(kr * 32 + khb) ^ (uint32_t)(((kr >> 2) & 1) << 4);
                ldmx2(kb0[nt], kb1[nt], sb + TQ_KHI + off);
                ldmx2(klb0[nt], klb1[nt], sb + TQ_KLO + off);
            }
            float S[2][4];
            #pragma unroll
            for (int nt = 0; nt < 2; nt++) {
                #pragma unroll
                for (int j = 0; j < 4; j++) S[nt][j] = 0.f;
                mma16816(S[nt], qh, kb0[nt], kb1[nt]);
                mma16816(S[nt], ql, kb0[nt], kb1[nt]);
                mma16816(S[nt], qh, klb0[nt], klb1[nt]);
            }
            if (ch == tile) {
                #pragma unroll
                for (int nt = 0; nt < 2; nt++) {
                    int c0 = nt * 8 + cq;
                    if (c0     > rq)     S[nt][0] = -3e38f;
                    if (c0 + 1 > rq)     S[nt][1] = -3e38f;
                    if (c0     > rq + 8) S[nt][2] = -3e38f;
                    if (c0 + 1 > rq + 8) S[nt][3] = -3e38f;
                }
            }
            float p[2][4];
            #pragma unroll
            for (int nt = 0; nt < 2; nt++)
                #pragma unroll
                for (int j = 0; j < 4; j++) p[nt][j] = ex2f(S[nt][j]);
            ls0 += (p[0][0] + p[0][1]) + (p[1][0] + p[1][1]);
            ls1 += (p[0][2] + p[0][3]) + (p[1][2] + p[1][3]);
            uint32_t hreg[4], lreg[4];
            #pragma unroll
            for (int q = 0; q < 4; q++) {
                int nt = q >> 1, jo = (q & 1) * 2;
                uint32_t h; PACKBF(h, p[nt][jo], p[nt][jo+1]);
                float r0 = __uint_as_float(h << 16);
                float r1 = __uint_as_float(h & 0xffff0000u);
                uint32_t l; PACKBF(l, p[nt][jo] - r0, p[nt][jo+1] - r1);
                hreg[q] = h; lreg[q] = l;
            }
            uint4 ph = make_uint4(hreg[0], hreg[1], hreg[2], hreg[3]);
            uint4 pl = make_uint4(lreg[0], lreg[1], lreg[2], lreg[3]);

            uint32_t vb0[2], vb1[2], vlb0[2], vlb1[2];
            #pragma unroll
            for (int nt = 0; nt < 2; nt++) {
                int vc = nt * 8 + rlow;
                uint32_t off = (uint32_t)(vc * 816 + y0 * 2 + khb);
                ldmx2(vb0[nt], vb1[nt], sb + TQ_VHI + off);
                ldmx2(vlb0[nt], vlb1[nt], sb + TQ_VLO + off);
            }
            #pragma unroll
            for (int nt = 0; nt < 2; nt++) {
                mma16816(O[nt], ph, vb0[nt], vb1[nt]);
                mma16816(O[nt], pl, vb0[nt], vb1[nt]);
                mma16816(O[nt], ph, vlb0[nt], vlb1[nt]);
            }
        }

        ls0 += __shfl_xor_sync(0xffffffffu, ls0, 1);
        ls0 += __shfl_xor_sync(0xffffffffu, ls0, 2);
        ls1 += __shfl_xor_sync(0xffffffffu, ls1, 1);
        ls1 += __shfl_xor_sync(0xffffffffu, ls1, 2);
        float i0 = 1.f / ls0, i1 = 1.f / ls1;

        // write normalized P as bf16 hi/lo, K-style layout [t-row][16c]
        int row0 = tile * 16 + rq, row1 = row0 + 8;
        #pragma unroll
        for (int nt = 0; nt < 2; nt++) {
            int c = nt * 8 + cq;
            float p0 = O[nt][0] * i0, p1 = O[nt][1] * i0;
            float p2 = O[nt][2] * i1, p3 = O[nt][3] * i1;
            uint32_t h0; PACKBF(h0, p0, p1);
            uint32_t l0; PACKBF(l0, p0 - __uint_as_float(h0 << 16),
                                    p1 - __uint_as_float(h0 & 0xffff0000u));
            uint32_t h1; PACKBF(h1, p2, p3);
            uint32_t l1; PACKBF(l1, p2 - __uint_as_float(h1 << 16),
                                    p3 - __uint_as_float(h1 & 0xffff0000u));
            uint32_t a0 = (uint32_t)(row0 * 32 + c * 2) ^ (uint32_t)(((row0 >> 2) & 1) << 4);
            uint32_t a1 = (uint32_t)(row1 * 32 + c * 2) ^ (uint32_t)(((row1 >> 2) & 1) << 4);
            *(uint32_t*)(smt + TQ_PHI + a0) = h0;
            *(uint32_t*)(smt + TQ_PLO + a0) = l0;
            *(uint32_t*)(smt + TQ_PHI + a1) = h1;
            *(uint32_t*)(smt + TQ_PLO + a1) = l1;
        }
    }
    __syncthreads();

    // projection via mma: D[64oc, 400t] = Wproj(scaled) @ P
    const float* sh3 = (const float*)(smt + TQ_SH);
    const float* al3 = (const float*)(smt + TQ_AL);
    int m = wid & 3;
    int nt0 = (wid < 4) ? 0 : 25;
    uint4 wh = g_wpfH[m * 32 + lane];
    uint4 wl = g_wpfL[m * 32 + lane];
    int oc0 = m * 16 + rq, oc1 = oc0 + 8;
    float sh0 = sh3[oc0], al0 = al3[oc0];
    float sh1 = sh3[oc1], al1 = al3[oc1];
    size_t ob0 = (((size_t)b * CC + oc0) * FF + f) * TT;
    size_t ob1 = (((size_t)b * CC + oc1) * FF + f) * TT;

    #pragma unroll 1
    for (int ntile = nt0; ntile < nt0 + 25; ntile++) {
        int pr = ntile * 8 + rlow;
        uint32_t off = (uint32_t)(pr * 32 + khb) ^ (uint32_t)(((pr >> 2) & 1) << 4);
        uint32_t bh0, bh1, bl0, bl1;
        ldmx2(bh0, bh1, sb + TQ_PHI + off);
        ldmx2(bl0, bl1, sb + TQ_PLO + off);
        float D[4] = {0.f, 0.f, 0.f, 0.f};
        mma16816(D, wh, bh0, bh1);
        mma16816(D, wl, bh0, bh1);
        mma16816(D, wh, bl0, bl1);

        int tcol = ntile * 8 + cq;
        float2 r0 = *(const float2*)(inp + ob0 + tcol);
        float2 r1 = *(const float2*)(inp + ob1 + tcol);
        float v0 = D[0] + sh0; v0 = v0 > 0.f ? v0 : al0 * v0;
        float v1 = D[1] + sh0; v1 = v1 > 0.f ? v1 : al0 * v1;
        float v2 = D[2] + sh1; v2 = v2 > 0.f ? v2 : al1 * v2;
        float v3v = D[3] + sh1; v3v = v3v > 0.f ? v3v : al1 * v3v;
        *(float2*)(out + ob0 + tcol) = make_float2(v0 + r0.x, v1 + r0.y);
        *(float2*)(out + ob1 + tcol) = make_float2(v2 + r1.x, v3v + r1.y);
    }
}

// ================= launcher =================
extern "C" void kernel_launch(void* const* d_in, const int* in_sizes, int n_in,
                              void* d_out, int out_size)
{
    (void)in_sizes; (void)n_in; (void)out_size;
    const float* inp    = (const float*)d_in[0];
    const float* w_fqkv = (const float*)d_in[2];
    const float* g1 = (const float*)d_in[3];
    const float* b1 = (const float*)d_in[4];
    const float* m1 = (const float*)d_in[5];
    const float* v1 = (const float*)d_in[6];
    const float* a1 = (const float*)d_in[7];
    const float* w_tqk  = (const float*)d_in[8];
    const float* g2 = (const float*)d_in[9];
    const float* b2 = (const float*)d_in[10];
    const float* m2 = (const float*)d_in[11];
    const float* v2 = (const float*)d_in[12];
    const float* a2 = (const float*)d_in[13];
    const float* w_proj = (const float*)d_in[14];
    const float* g3 = (const float*)d_in[15];
    const float* b3 = (const float*)d_in[16];
    const float* m3 = (const float*)d_in[17];
    const float* v3 = (const float*)d_in[18];
    const float* a3 = (const float*)d_in[19];
    float* out = (float*)d_out;

    cudaFuncSetAttribute(asa_time_attn_kernel,
                         cudaFuncAttributeMaxDynamicSharedMemorySize, TQ_SMEM);

    asa_prep_kernel<<<3, 256>>>(w_fqkv, w_tqk, g1, b1, m1, v1, a1,
                                g2, b2, m2, v2, a2, w_proj, g3, v3);
    asa_conv_mma_kernel<<<dim3(1600, BB), 320>>>(inp);
    asa_transpose_qkv_kernel<<<dim3(13, 8, BB * 48), dim3(32, 8)>>>();
    asa_freq_attn_kernel<<<dim3(TT, BB), 256>>>();
    asa_transpose_fout_kernel<<<dim3(8, 13, BB * 16), dim3(32, 8)>>>();
    asa_time_attn_kernel<<<dim3(FF, BB), 256, TQ_SMEM>>>(inp,
        g3, b3, m3, v3, a3, out);
}

// round 14
// speedup vs baseline: 1.0855x; 1.0070x over previous
#include <cuda_runtime.h>
#include <cuda_bf16.h>
#include <cstdint>
#include <math.h>

#define BB 4
#define CC 64
#define FF 256
#define TT 400
#define DC 16
#define SP (FF*TT)

#define QS 0.36067376022224085f   /* 0.25 * log2(e) */

__device__ __forceinline__ float ex2f(float x) {
    float r; asm("ex2.approx.ftz.f32 %0, %1;" : "=f"(r) : "f"(x)); return r;
}
__device__ __forceinline__ uint32_t smem_u32(const void* p) {
    uint32_t a;
    asm("{ .reg .u64 t; cvta.to.shared.u64 t, %1; cvt.u32.u64 %0, t; }" : "=r"(a) : "l"(p));
    return a;
}
__device__ __forceinline__ void ldmx2(uint32_t& r0, uint32_t& r1, uint32_t a) {
    asm volatile("ldmatrix.sync.aligned.m8n8.x2.shared.b16 {%0,%1}, [%2];"
                 : "=r"(r0), "=r"(r1) : "r"(a));
}
__device__ __forceinline__ void ldmx4(uint4& r, uint32_t a) {
    asm volatile("ldmatrix.sync.aligned.m8n8.x4.shared.b16 {%0,%1,%2,%3}, [%4];"
                 : "=r"(r.x), "=r"(r.y), "=r"(r.z), "=r"(r.w) : "r"(a));
}
__device__ __forceinline__ void mma16816(float* d, uint4 a, uint32_t b0, uint32_t b1) {
    asm volatile("mma.sync.aligned.m16n8k16.row.col.f32.bf16.bf16.f32 "
        "{%0,%1,%2,%3}, {%4,%5,%6,%7}, {%8,%9}, {%0,%1,%2,%3};"
        : "+f"(d[0]), "+f"(d[1]), "+f"(d[2]), "+f"(d[3])
        : "r"(a.x), "r"(a.y), "r"(a.z), "r"(a.w), "r"(b0), "r"(b1));
}
#define PACKBF(r, a, b) asm("cvt.rn.bf16x2.f32 %0, %1, %2;" : "=r"(r) : "f"(b), "f"(a))

// ---------------- scratch ----------------
static __device__ float g_qkvf_t[(size_t)BB*48*FF*TT];
static __device__ float g_qkvf_f[(size_t)BB*TT*48*FF];
static __device__ float g_tqk2 [(size_t)BB*32*FF*TT];
static __device__ float g_fout_t[(size_t)BB*TT*DC*FF];
static __device__ float g_fout_f[(size_t)BB*FF*DC*TT];
static __device__ __align__(16) uint4 g_wafH[640];
static __device__ __align__(16) uint4 g_wafL[640];
static __device__ __align__(16) uint4 g_wpfH[128];
static __device__ __align__(16) uint4 g_wpfL[128];
static __device__ float g_shift[80];
static __device__ float g_alpha[80];

// causal 32-row band assignment over 8 warps (chunk-iters 25/24/22x6)
static __device__ const int BAND_LUT8[8][2] = {
    {12, -1}, {11, -1}, {10, -1}, {9, 0}, {8, 1}, {7, 2}, {6, 3}, {5, 4}
};

// ================= kernel 0: prep =================
__global__ __launch_bounds__(256)
void asa_prep_kernel(const float* __restrict__ w_fqkv, const float* __restrict__ w_tqk,
    const float* __restrict__ g1, const float* __restrict__ b1,
    const float* __restrict__ m1, const float* __restrict__ v1, const float* __restrict__ a1,
    const float* __restrict__ g2, const float* __restrict__ b2,
    const float* __restrict__ m2, const float* __restrict__ v2, const float* __restrict__ a2,
    const float* __restrict__ w_proj, const float* __restrict__ g3, const float* __restrict__ v3)
{
    int i = blockIdx.x * 256 + threadIdx.x;
    if (i < 640) {
        int lane = i & 31, ks = (i >> 5) & 3, o = i >> 7;
        int r = lane >> 2, cp = (lane & 3) * 2;
        int oc0 = o * 16 + r, k0 = ks * 16 + cp;
        uint32_t hiR[4], loR[4];
        #pragma unroll
        for (int aa = 0; aa < 4; aa++) {
            int oc = oc0 + ((aa & 1) << 3);
            int kk = k0 + ((aa >> 1) << 3);
            float s, w0, w1;
            if (oc < 48) {
                s = g1[oc] * rsqrtf(v1[oc] + 1e-5f);
                w0 = w_fqkv[oc * 64 + kk] * s; w1 = w_fqkv[oc * 64 + kk + 1] * s;
            } else {
                int j = oc - 48;
                s = g2[j] * rsqrtf(v2[j] + 1e-5f);
                w0 = w_tqk[j * 64 + kk] * s; w1 = w_tqk[j * 64 + kk + 1] * s;
            }
            uint32_t h; PACKBF(h, w0, w1);
            float r0 = __uint_as_float(h << 16);
            float r1 = __uint_as_float(h & 0xffff0000u);
            uint32_t l; PACKBF(l, w0 - r0, w1 - r1);
            hiR[aa] = h; loR[aa] = l;
        }
        g_wafH[i] = make_uint4(hiR[0], hiR[1], hiR[2], hiR[3]);
        g_wafL[i] = make_uint4(loR[0], loR[1], loR[2], loR[3]);
    } else if (i < 768) {
        int idx = i - 640;
        int lane = idx & 31, o = idx >> 5;
        int r = lane >> 2, cp = (lane & 3) * 2;
        uint32_t hiR[4], loR[4];
        #pragma unroll
        for (int aa = 0; aa < 4; aa++) {
            int oc = o * 16 + r + ((aa & 1) << 3);
            int kk = cp + ((aa >> 1) << 3);
            float s = g3[oc] * rsqrtf(v3[oc] + 1e-5f);
            float w0 = w_proj[oc * 16 + kk] * s;
            float w1 = w_proj[oc * 16 + kk + 1] * s;
            uint32_t h; PACKBF(h, w0, w1);
            float r0 = __uint_as_float(h << 16);
            float r1 = __uint_as_float(h & 0xffff0000u);
            uint32_t l; PACKBF(l, w0 - r0, w1 - r1);
            hiR[aa] = h; loR[aa] = l;
        }
        g_wpfH[idx] = make_uint4(hiR[0], hiR[1], hiR[2], hiR[3]);
        g_wpfL[idx] = make_uint4(loR[0], loR[1], loR[2], loR[3]);
    }
    if (i < 80) {
        float ss, sh, al;
        if (i < 48) { ss = g1[i] * rsqrtf(v1[i] + 1e-5f); sh = b1[i] - m1[i] * ss; al = a1[i]; }
        else { int j = i - 48; ss = g2[j] * rsqrtf(v2[j] + 1e-5f); sh = b2[j] - m2[j] * ss; al = a2[j]; }
        g_shift[i] = sh; g_alpha[i] = al;
    }
}

// ====== kernel 1: conv1x1 via mma.sync bf16 — 128-spatial tiles ======
#define CV_STAGE 0          /* 64 * 132 floats = 33792 B */
#define CV_HI 33792         /* 128 rows x 128 B */
#define CV_LO 50176
#define CV_SMEM 66560

__global__ __launch_bounds__(320)
void asa_conv_mma_kernel(const float* __restrict__ inp)
{
    extern __shared__ char smc[];
    float* xstage = (float*)(smc + CV_STAGE);
    uint32_t shi = smem_u32(smc + CV_HI), slo = smem_u32(smc + CV_LO);
    int tid = threadIdx.x, wid = tid >> 5, lane = tid & 31;
    int b = blockIdx.y;
    int n0 = blockIdx.x * 128;
    const float* xb = inp + (size_t)b * CC * SP + n0;

    for (int i = tid; i < 2048; i += 320) {
        int k = i >> 5, s4 = (i & 31) * 4;
        float4 v = *(const float4*)(xb + (size_t)k * SP + s4);
        *(float4*)(xstage + k * 132 + s4) = v;
    }
    __syncthreads();

    for (int ch = tid; ch < 1024; ch += 320) {
        int sp = ch & 127, kb = ch >> 7;
        float v[8];
        #pragma unroll
        for (int j = 0; j < 8; j++) v[j] = xstage[(kb * 8 + j) * 132 + sp];
        uint32_t hp[4], lp[4];
        #pragma unroll
        for (int j = 0; j < 4; j++) {
            uint32_t h; PACKBF(h, v[2*j], v[2*j+1]);
            float r0 = __uint_as_float(h << 16);
            float r1 = __uint_as_float(h & 0xffff0000u);
            uint32_t l; PACKBF(l, v[2*j] - r0, v[2*j+1] - r1);
            hp[j] = h; lp[j] = l;
        }
        uint32_t off = sp * 128 + ((kb * 16) ^ ((sp & 7) << 4));
        *(uint4*)(smc + CV_HI + off) = make_uint4(hp[0], hp[1], hp[2], hp[3]);
        *(uint4*)(smc + CV_LO + off) = make_uint4(lp[0], lp[1], lp[2], lp[3]);
    }
    __syncthreads();

    int octile = wid >> 1, sptile = wid & 1;
    float d[8][4];
    #pragma unroll
    for (int nt = 0; nt < 8; nt++)
        #pragma unroll
        for (int j = 0; j < 4; j++) d[nt][j] = 0.f;

    int ln = lane & 15;
    int sprow_base = sptile * 64 + (ln & 7);
    int khalf = ((ln >> 3) & 1) << 3;

    #pragma unroll
    for (int ks = 0; ks < 4; ks++) {
        uint4 ah = g_wafH[(octile * 4 + ks) * 32 + lane];
        uint4 al = g_wafL[(octile * 4 + ks) * 32 + lane];
        #pragma unroll
        for (int nt = 0; nt < 8; nt++) {
            int spr = sprow_base + nt * 8;
            int ke = ks * 16 + khalf;
            uint32_t aoff = spr * 128 + ((ke * 2) ^ ((spr & 7) << 4));
            uint32_t bh0, bh1, bl0, bl1;
            ldmx2(bh0, bh1, shi + aoff);
            ldmx2(bl0, bl1, slo + aoff);
            mma16816(d[nt], ah, bh0, bh1);
            mma16816(d[nt], al, bh0, bh1);
            mma16816(d[nt], ah, bl0, bl1);
        }
    }

    int r = lane >> 2, cp = (lane & 3) * 2;
    #pragma unroll
    for (int half = 0; half < 2; half++) {
        int oc = octile * 16 + r + half * 8;
        float sh = g_shift[oc], al = g_alpha[oc];
        float* dst;
        if (oc < 48) dst = g_qkvf_t + ((size_t)b * 48 + oc) * SP + n0;
        else         dst = g_tqk2  + ((size_t)b * 32 + (oc - 48)) * SP + n0;
        #pragma unroll
        for (int nt = 0; nt < 8; nt++) {
            float v0 = d[nt][half * 2 + 0] + sh; v0 = v0 > 0.f ? v0 : al * v0;
            float v1 = d[nt][half * 2 + 1] + sh; v1 = v1 > 0.f ? v1 : al * v1;
            int sp = sptile * 64 + nt * 8 + cp;
            *(float2*)(dst + sp) = make_float2(v0, v1);
        }
    }
}

// ================= transpose 1 =================
__global__ __launch_bounds__(256)
void asa_transpose_qkv_kernel()
{
    __shared__ float tile[32][33];
    int z = blockIdx.z;
    int t0 = blockIdx.x * 32, f0 = blockIdx.y * 32;
    int tx = threadIdx.x, ty = threadIdx.y;
    size_t ibase = (size_t)z * FF * TT;
    #pragma unroll
    for (int k = 0; k < 32; k += 8) {
        int t = t0 + tx, f = f0 + ty + k;
        if (t < TT) tile[ty + k][tx] = g_qkvf_t[ibase + (size_t)f * TT + t];
    }
    __syncthreads();
    int b = z / 48, oc = z % 48;
    #pragma unroll
    for (int k = 0; k < 32; k += 8) {
        int t = t0 + ty + k, f = f0 + tx;
        if (t < TT) g_qkvf_f[((size_t)(b * TT + t) * 48 + oc) * FF + f] = tile[tx][ty + k];
    }
}

// ========== kernel 2: frequency attention via mma.sync, 8 warps ==========
#define FQ_QHI 0
#define FQ_QLO 8192
#define FQ_KHI 16384
#define FQ_KLO 24576
#define FQ_VHI 32768
#define FQ_VLO 40960

__global__ __launch_bounds__(256)
void asa_freq_attn_kernel()
{
    __shared__ __align__(16) char smf[49152];
    int tid = threadIdx.x, wid = tid >> 5, lane = tid & 31;
    int t = blockIdx.x, b = blockIdx.y;
    const float* base = g_qkvf_f + (size_t)(b * TT + t) * 48 * FF;
    uint32_t sb = smem_u32(smf);

    for (int it = 0; it < 8; it++) {
        int idx = it * 256 + tid;
        int row = idx & 255;
        int cp = idx >> 8;
        uint32_t qkoff = (uint32_t)(row * 32 + cp * 4) ^ (uint32_t)(((row >> 2) & 1) << 4);
        {
            float x0 = base[(2*cp) * 256 + row] * QS;
            float x1 = base[(2*cp+1) * 256 + row] * QS;
            uint32_t h; PACKBF(h, x0, x1);
            float r0 = __uint_as_float(h << 16);
            float r1 = __uint_as_float(h & 0xffff0000u);
            uint32_t l; PACKBF(l, x0 - r0, x1 - r1);
            *(uint32_t*)(smf + FQ_QHI + qkoff) = h;
            *(uint32_t*)(smf + FQ_QLO + qkoff) = l;
        }
        {
            float x0 = base[4096 + (2*cp) * 256 + row];
            float x1 = base[4096 + (2*cp+1) * 256 + row];
            uint32_t h; PACKBF(h, x0, x1);
            float r0 = __uint_as_float(h << 16);
            float r1 = __uint_as_float(h & 0xffff0000u);
            uint32_t l; PACKBF(l, x0 - r0, x1 - r1);
            *(uint32_t*)(smf + FQ_KHI + qkoff) = h;
            *(uint32_t*)(smf + FQ_KLO + qkoff) = l;
        }
        {
            float x0 = base[8192 + (2*cp) * 256 + row];
            float x1 = base[8192 + (2*cp+1) * 256 + row];
            uint32_t h; PACKBF(h, x0, x1);
            float r0 = __uint_as_float(h << 16);
            float r1 = __uint_as_float(h & 0xffff0000u);
            uint32_t l; PACKBF(l, x0 - r0, x1 - r1);
            int c0 = 2*cp, c1 = 2*cp + 1, y = row;
            uint32_t o0 = (uint32_t)(c0 * 512 + y * 2) ^ (uint32_t)((c0 & 7) << 4);
            uint32_t o1 = (uint32_t)(c1 * 512 + y * 2) ^ (uint32_t)((c1 & 7) << 4);
            *(uint16_t*)(smf + FQ_VHI + o0) = (uint16_t)(h & 0xffff);
            *(uint16_t*)(smf + FQ_VHI + o1) = (uint16_t)(h >> 16);
            *(uint16_t*)(smf + FQ_VLO + o0) = (uint16_t)(l & 0xffff);
            *(uint16_t*)(smf + FQ_VLO + o1) = (uint16_t)(l >> 16);
        }
    }
    __syncthreads();

    int fw = wid * 32;
    int l16 = lane & 15;
    int kh16 = ((lane >> 4) & 1) << 4;
    uint4 qh[2], ql[2];
    #pragma unroll
    for (int mt = 0; mt < 2; mt++) {
        int fr = fw + mt * 16 + l16;
        uint32_t off = (uint32_t)(fr * 32 + kh16) ^ (uint32_t)(((fr >> 2) & 1) << 4);
        ldmx4(qh[mt], sb + FQ_QHI + off);
        ldmx4(ql[mt], sb + FQ_QLO + off);
    }

    float O[2][2][4];
    #pragma unroll
    for (int mt = 0; mt < 2; mt++)
        #pragma unroll
        for (int nt = 0; nt < 2; nt++)
            #pragma unroll
            for (int j = 0; j < 4; j++) O[mt][nt][j] = 0.f;
    float lsum[4];
    #pragma unroll
    for (int i = 0; i < 4; i++) lsum[i] = 0.f;

    int rlow = l16 & 7;
    int khb = ((l16 >> 3) & 1) << 4;

    for (int y0 = 0; y0 < 256; y0 += 16) {
        uint32_t kb0[2], kb1[2], klb0[2], klb1[2];
        #pragma unroll
        for (int nt = 0; nt < 2; nt++) {
            int kr = y0 + nt * 8 + rlow;
            uint32_t off = (uint32_t)(kr * 32 + khb) ^ (uint32_t)(((kr >> 2) & 1) << 4);
            ldmx2(kb0[nt], kb1[nt], sb + FQ_KHI + off);
            ldmx2(klb0[nt], klb1[nt], sb + FQ_KLO + off);
        }
        float S[2][2][4];
        #pragma unroll
        for (int mt = 0; mt < 2; mt++)
            #pragma unroll
            for (int nt = 0; nt < 2; nt++) {
                #pragma unroll
                for (int j = 0; j < 4; j++) S[mt][nt][j] = 0.f;
                mma16816(S[mt][nt], qh[mt], kb0[nt], kb1[nt]);
                mma16816(S[mt][nt], ql[mt], kb0[nt], kb1[nt]);
                mma16816(S[mt][nt], qh[mt], klb0[nt], klb1[nt]);
            }
        uint4 ph[2], pl[2];
        #pragma unroll
        for (int mt = 0; mt < 2; mt++) {
            float p[2][4];
            #pragma unroll
            for (int nt = 0; nt < 2; nt++)
                #pragma unroll
                for (int j = 0; j < 4; j++) p[nt][j] = ex2f(S[mt][nt][j]);
            lsum[2*mt]   += (p[0][0] + p[0][1]) + (p[1][0] + p[1][1]);
            lsum[2*mt+1] += (p[0][2] + p[0][3]) + (p[1][2] + p[1][3]);
            uint32_t hreg[4], lreg[4];
            #pragma unroll
            for (int q = 0; q < 4; q++) {
                int nt = q >> 1, jo = (q & 1) * 2;
                uint32_t h; PACKBF(h, p[nt][jo], p[nt][jo+1]);
                float r0 = __uint_as_float(h << 16);
                float r1 = __uint_as_float(h & 0xffff0000u);
                uint32_t l; PACKBF(l, p[nt][jo] - r0, p[nt][jo+1] - r1);
                hreg[q] = h; lreg[q] = l;
            }
            ph[mt] = make_uint4(hreg[0], hreg[1], hreg[2], hreg[3]);
            pl[mt] = make_uint4(lreg[0], lreg[1], lreg[2], lreg[3]);
        }
        uint32_t vb0[2], vb1[2], vlb0[2], vlb1[2];
        #pragma unroll
        for (int nt = 0; nt < 2; nt++) {
            int vc = nt * 8 + rlow;
            uint32_t off = (uint32_t)(vc * 512 + y0 * 2 + khb) ^ (uint32_t)((vc & 7) << 4);
            ldmx2(vb0[nt], vb1[nt], sb + FQ_VHI + off);
            ldmx2(vlb0[nt], vlb1[nt], sb + FQ_VLO + off);
        }
        #pragma unroll
        for (int mt = 0; mt < 2; mt++)
            #pragma unroll
            for (int nt = 0; nt < 2; nt++) {
                mma16816(O[mt][nt], ph[mt], vb0[nt], vb1[nt]);
                mma16816(O[mt][nt], pl[mt], vb0[nt], vb1[nt]);
                mma16816(O[mt][nt], ph[mt], vlb0[nt], vlb1[nt]);
            }
    }

    #pragma unroll
    for (int i = 0; i < 4; i++) {
        lsum[i] += __shfl_xor_sync(0xffffffffu, lsum[i], 1);
        lsum[i] += __shfl_xor_sync(0xffffffffu, lsum[i], 2);
    }

    __syncthreads();
    float* st = (float*)smf;
    int r = lane >> 2, cq = (lane & 3) * 2;
    #pragma unroll
    for (int mt = 0; mt < 2; mt++) {
        float i0 = 1.f / lsum[2*mt], i1 = 1.f / lsum[2*mt+1];
        int f = fw + mt * 16 + r;
        #pragma unroll
        for (int nt = 0; nt < 2; nt++) {
            int c = nt * 8 + cq;
            st[c * 256 + f]           = O[mt][nt][0] * i0;
            st[(c + 1) * 256 + f]     = O[mt][nt][1] * i0;
            st[c * 256 + f + 8]       = O[mt][nt][2] * i1;
            st[(c + 1) * 256 + f + 8] = O[mt][nt][3] * i1;
        }
    }
    __syncthreads();
    float4* go = (float4*)(g_fout_t + (size_t)(b * TT + t) * DC * FF);
    const float4* s4 = (const float4*)smf;
    for (int i = tid; i < 1024; i += 256) go[i] = s4[i];
}

// ================= transpose 2 =================
__global__ __launch_bounds__(256)
void asa_transpose_fout_kernel()
{
    __shared__ float tile[32][33];
    int z = blockIdx.z;
    int f0 = blockIdx.x * 32, t0 = blockIdx.y * 32;
    int tx = threadIdx.x, ty = threadIdx.y;
    int b = z / 16, c = z % 16;
    #pragma unroll
    for (int k = 0; k < 32; k += 8) {
        int t = t0 + ty + k, f = f0 + tx;
        if (t < TT) tile[ty + k][tx] = g_fout_t[((size_t)(b * TT + t) * DC + c) * FF + f];
    }
    __syncthreads();
    #pragma unroll
    for (int k = 0; k < 32; k += 8) {
        int f = f0 + ty + k, t = t0 + tx;
        if (t < TT) g_fout_f[((size_t)(b * FF + f) * DC + c) * TT + t] = tile[tx][ty + k];
    }
}

// ======= kernel 3: causal time attention via mma.sync, 32-row bands =======
#define TQ_QHI 0
#define TQ_QLO 12800
#define TQ_KHI 25600
#define TQ_KLO 38400
#define TQ_VHI 51200
#define TQ_VLO 64256
#define TQ_PHI 77312
#define TQ_PLO 90112
#define TQ_SH  102912
#define TQ_AL  103168
#define TQ_SMEM 103424

template<int NMT>
__device__ __forceinline__ void tq_band(char* smt, uint32_t sb, int band, int lane)
{
    int l16 = lane & 15;
    int kh16 = ((lane >> 4) & 1) << 4;
    int rlow = l16 & 7;
    int khb = ((l16 >> 3) & 1) << 4;
    int rq = lane >> 2, cq = (lane & 3) * 2;

    uint4 qh[NMT], ql[NMT];
    #pragma unroll
    for (int m = 0; m < NMT; m++) {
        int fr = band * 32 + m * 16 + l16;
        uint32_t off = (uint32_t)(fr * 32 + kh16) ^ (uint32_t)(((fr >> 2) & 1) << 4);
        ldmx4(qh[m], sb + TQ_QHI + off);
        ldmx4(ql[m], sb + TQ_QLO + off);
    }
    float O[NMT][2][4];
    #pragma unroll
    for (int m = 0; m < NMT; m++)
        #pragma unroll
        for (int nt = 0; nt < 2; nt++)
            #pragma unroll
            for (int j = 0; j < 4; j++) O[m][nt][j] = 0.f;
    float ls[2 * NMT];
    #pragma unroll
    for (int i = 0; i < 2 * NMT; i++) ls[i] = 0.f;

    int CL = (NMT == 1) ? 24 : 2 * band + 1;

    #pragma unroll 1
    for (int ch = 0; ch <= CL; ch++) {
        int y0 = ch * 16;
        uint32_t kb0[2], kb1[2], klb0[2], klb1[2];
        #pragma unroll
        for (int nt = 0; nt < 2; nt++) {
            int kr = y0 + nt * 8 + rlow;
            uint32_t off = (uint32_t)(kr * 32 + khb) ^ (uint32_t)(((kr >> 2) & 1) << 4);
            ldmx2(kb0[nt], kb1[nt], sb + TQ_KHI + off);
            ldmx2(klb0[nt], klb1[nt], sb + TQ_KLO + off);
        }
        float S[NMT][2][4];
        #pragma unroll
        for (int m = 0; m < NMT; m++)
            #pragma unroll
            for (int nt = 0; nt < 2; nt++) {
                #pragma unroll
                for (int j = 0; j < 4; j++) S[m][nt][j] = 0.f;
                mma16816(S[m][nt], qh[m], kb0[nt], kb1[nt]);
                mma16816(S[m][nt], ql[m], kb0[nt], kb1[nt]);
                mma16816(S[m][nt], qh[m], klb0[nt], klb1[nt]);
            }
        if (ch >= 2 * band) {
            #pragma unroll
            for (int m = 0; m < NMT; m++) {
                int rg0 = band * 32 + m * 16 + rq;
                int rg1 = rg0 + 8;
                #pragma unroll
                for (int nt = 0; nt < 2; nt++) {
                    int cg = y0 + nt * 8 + cq;
                    if (cg     > rg0) S[m][nt][0] = -3e38f;
                    if (cg + 1 > rg0) S[m][nt][1] = -3e38f;
                    if (cg     > rg1) S[m][nt][2] = -3e38f;
                    if (cg + 1 > rg1) S[m][nt][3] = -3e38f;
                }
            }
        }
        uint4 ph[NMT], pl[NMT];
        #pragma unroll
        for (int m = 0; m < NMT; m++) {
            float p[2][4];
            #pragma unroll
            for (int nt = 0; nt < 2; nt++)
                #pragma unroll
                for (int j = 0; j < 4; j++) p[nt][j] = ex2f(S[m][nt][j]);
            ls[2*m]   += (p[0][0] + p[0][1]) + (p[1][0] + p[1][1]);
            ls[2*m+1] += (p[0][2] + p[0][3]) + (p[1][2] + p[1][3]);
            uint32_t hreg[4], lreg[4];
            #pragma unroll
            for (int q = 0; q < 4; q++) {
                int nt = q >> 1, jo = (q & 1) * 2;
                uint32_t h; PACKBF(h, p[nt][jo], p[nt][jo+1]);
                float r0 = __uint_as_float(h << 16);
                float r1 = __uint_as_float(h & 0xffff0000u);
                uint32_t l; PACKBF(l, p[nt][jo] - r0, p[nt][jo+1] - r1);
                hreg[q] = h; lreg[q] = l;
            }
            ph[m] = make_uint4(hreg[0], hreg[1], hreg[2], hreg[3]);
            pl[m] = make_uint4(lreg[0], lreg[1], lreg[2], lreg[3]);
        }
        uint32_t vb0[2], vb1[2], vlb0[2], vlb1[2];
        #pragma unroll
        for (int nt = 0; nt < 2; nt++) {
            int vc = nt * 8 + rlow;
            uint32_t off = (uint32_t)(vc * 816 + y0 * 2 + khb);
            ldmx2(vb0[nt], vb1[nt], sb + TQ_VHI + off);
            ldmx2(vlb0[nt], vlb1[nt], sb + TQ_VLO + off);
        }
        #pragma unroll
        for (int m = 0; m < NMT; m++)
            #pragma unroll
            for (int nt = 0; nt < 2; nt++) {
                mma16816(O[m][nt], ph[m], vb0[nt], vb1[nt]);
                mma16816(O[m][nt], pl[m], vb0[nt], vb1[nt]);
                mma16816(O[m][nt], ph[m], vlb0[nt], vlb1[nt]);
            }
    }

    #pragma unroll
    for (int i = 0; i < 2 * NMT; i++) {
        ls[i] += __shfl_xor_sync(0xffffffffu, ls[i], 1);
        ls[i] += __shfl_xor_sync(0xffffffffu, ls[i], 2);
    }

    #pragma unroll
    for (int m = 0; m < NMT; m++) {
        float i0 = 1.f / ls[2*m], i1 = 1.f / ls[2*m+1];
        int row0 = band * 32 + m * 16 + rq, row1 = row0 + 8;
        #pragma unroll
        for (int nt = 0; nt < 2; nt++) {
            int c = nt * 8 + cq;
            float p0 = O[m][nt][0] * i0, p1 = O[m][nt][1] * i0;
            float p2 = O[m][nt][2] * i1, p3 = O[m][nt][3] * i1;
            uint32_t h0; PACKBF(h0, p0, p1);
            uint32_t l0; PACKBF(l0, p0 - __uint_as_float(h0 << 16),
                                    p1 - __uint_as_float(h0 & 0xffff0000u));
            uint32_t h1; PACKBF(h1, p2, p3);
            uint32_t l1; PACKBF(l1, p2 - __uint_as_float(h1 << 16),
                                    p3 - __uint_as_float(h1 & 0xffff0000u));
            uint32_t a0 = (uint32_t)(row0 * 32 + c * 2) ^ (uint32_t)(((row0 >> 2) & 1) << 4);
            uint32_t a1 = (uint32_t)(row1 * 32 + c * 2) ^ (uint32_t)(((row1 >> 2) & 1) << 4);
            *(uint32_t*)(smt + TQ_PHI + a0) = h0;
            *(uint32_t*)(smt + TQ_PLO + a0) = l0;
            *(uint32_t*)(smt + TQ_PHI + a1) = h1;
            *(uint32_t*)(smt + TQ_PLO + a1) = l1;
        }
    }
}

__global__ __launch_bounds__(256, 2)
void asa_time_attn_kernel(const float* __restrict__ inp,
    const float* __restrict__ g3, const float* __restrict__ b3, const float* __restrict__ m3,
    const float* __restrict__ v3, const float* __restrict__ a3, float* __restrict__ out)
{
    extern __shared__ char smt[];
    uint32_t sb = smem_u32(smt);
    int tid = threadIdx.x, wid = tid >> 5, lane = tid & 31;
    int f = blockIdx.x, b = blockIdx.y;
    size_t cbase = (size_t)b * 32 * SP + (size_t)f * TT;
    const float* vg = g_fout_f + (size_t)(b * FF + f) * DC * TT;

    #pragma unroll 1
    for (int idx = tid; idx < 3200; idx += 256) {
        int t = idx % 400;
        int cp = idx / 400;
        uint32_t qkoff = (uint32_t)(t * 32 + cp * 4) ^ (uint32_t)(((t >> 2) & 1) << 4);
        {
            float x0 = g_tqk2[cbase + (size_t)(2*cp) * SP + t] * QS;
            float x1 = g_tqk2[cbase + (size_t)(2*cp+1) * SP + t] * QS;
            uint32_t h; PACKBF(h, x0, x1);
            float r0 = __uint_as_float(h << 16);
            float r1 = __uint_as_float(h & 0xffff0000u);
            uint32_t l; PACKBF(l, x0 - r0, x1 - r1);
            *(uint32_t*)(smt + TQ_QHI + qkoff) = h;
            *(uint32_t*)(smt + TQ_QLO + qkoff) = l;
        }
        {
            float x0 = g_tqk2[cbase + (size_t)(16 + 2*cp) * SP + t];
            float x1 = g_tqk2[cbase + (size_t)(17 + 2*cp) * SP + t];
            uint32_t h; PACKBF(h, x0, x1);
            float r0 = __uint_as_float(h << 16);
            float r1 = __uint_as_float(h & 0xffff0000u);
            uint32_t l; PACKBF(l, x0 - r0, x1 - r1);
            *(uint32_t*)(smt + TQ_KHI + qkoff) = h;
            *(uint32_t*)(smt + TQ_KLO + qkoff) = l;
        }
        {
            float x0 = vg[(size_t)(2*cp) * TT + t];
            float x1 = vg[(size_t)(2*cp+1) * TT + t];
            uint32_t h; PACKBF(h, x0, x1);
            float r0 = __uint_as_float(h << 16);
            float r1 = __uint_as_float(h & 0xffff0000u);
            uint32_t l; PACKBF(l, x0 - r0, x1 - r1);
            uint32_t o0 = (uint32_t)((2*cp) * 816 + t * 2);
            uint32_t o1 = (uint32_t)((2*cp+1) * 816 + t * 2);
            *(uint16_t*)(smt + TQ_VHI + o0) = (uint16_t)(h & 0xffff);
            *(uint16_t*)(smt + TQ_VHI + o1) = (uint16_t)(h >> 16);
            *(uint16_t*)(smt + TQ_VLO + o0) = (uint16_t)(l & 0xffff);
            *(uint16_t*)(smt + TQ_VLO + o1) = (uint16_t)(l >> 16);
        }
    }
    if (tid < 64) {
        float s = g3[tid] * rsqrtf(v3[tid] + 1e-5f);
        ((float*)(smt + TQ_SH))[tid] = b3[tid] - m3[tid] * s;
        ((float*)(smt + TQ_AL))[tid] = a3[tid];
    }
    __syncthreads();

    #pragma unroll 1
    for (int bi = 0; bi < 2; bi++) {
        int band = BAND_LUT8[wid][bi];
        if (band < 0) break;
        if (band == 12) tq_band<1>(smt, sb, band, lane);
        else            tq_band<2>(smt, sb, band, lane);
    }
    __syncthreads();

    // projection via mma: D[64oc, 400t] = Wproj(scaled) @ P
    const float* sh3 = (const float*)(smt + TQ_SH);
    const float* al3 = (const float*)(smt + TQ_AL);
    int l16 = lane & 15;
    int rlow = l16 & 7;
    int khb = ((l16 >> 3) & 1) << 4;
    int rq = lane >> 2, cq = (lane & 3) * 2;
    int m = wid & 3;
    int nt0 = (wid < 4) ? 0 : 25;
    uint4 wh = g_wpfH[m * 32 + lane];
    uint4 wl = g_wpfL[m * 32 + lane];
    int oc0 = m * 16 + rq, oc1 = oc0 + 8;
    float sh0 = sh3[oc0], al0 = al3[oc0];
    float sh1 = sh3[oc1], al1 = al3[oc1];
    size_t ob0 = (((size_t)b * CC + oc0) * FF + f) * TT;
    size_t ob1 = (((size_t)b * CC + oc1) * FF + f) * TT;

    #pragma unroll 1
    for (int ntile = nt0; ntile < nt0 + 25; ntile++) {
        int pr = ntile * 8 + rlow;
        uint32_t off = (uint32_t)(pr * 32 + khb) ^ (uint32_t)(((pr >> 2) & 1) << 4);
        uint32_t bh0, bh1, bl0, bl1;
        ldmx2(bh0, bh1, sb + TQ_PHI + off);
        ldmx2(bl0, bl1, sb + TQ_PLO + off);
        float D[4] = {0.f, 0.f, 0.f, 0.f};
        mma16816(D, wh, bh0, bh1);
        mma16816(D, wl, bh0, bh1);
        mma16816(D, wh, bl0, bl1);

        int tcol = ntile * 8 + cq;
        float2 r0 = *(const float2*)(inp + ob0 + tcol);
        float2 r1 = *(const float2*)(inp + ob1 + tcol);
        float v0 = D[0] + sh0; v0 = v0 > 0.f ? v0 : al0 * v0;
        float v1 = D[1] + sh0; v1 = v1 > 0.f ? v1 : al0 * v1;
        float v2 = D[2] + sh1; v2 = v2 > 0.f ? v2 : al1 * v2;
        float v3v = D[3] + sh1; v3v = v3v > 0.f ? v3v : al1 * v3v;
        *(float2*)(out + ob0 + tcol) = make_float2(v0 + r0.x, v1 + r0.y);
        *(float2*)(out + ob1 + tcol) = make_float2(v2 + r1.x, v3v + r1.y);
    }
}

// ================= launcher =================
extern "C" void kernel_launch(void* const* d_in, const int* in_sizes, int n_in,
                              void* d_out, int out_size)
{
    (void)in_sizes; (void)n_in; (void)out_size;
    const float* inp    = (const float*)d_in[0];
    const float* w_fqkv = (const float*)d_in[2];
    const float* g1 = (const float*)d_in[3];
    const float* b1 = (const float*)d_in[4];
    const float* m1 = (const float*)d_in[5];
    const float* v1 = (const float*)d_in[6];
    const float* a1 = (const float*)d_in[7];
    const float* w_tqk  = (const float*)d_in[8];
    const float* g2 = (const float*)d_in[9];
    const float* b2 = (const float*)d_in[10];
    const float* m2 = (const float*)d_in[11];
    const float* v2 = (const float*)d_in[12];
    const float* a2 = (const float*)d_in[13];
    const float* w_proj = (const float*)d_in[14];
    const float* g3 = (const float*)d_in[15];
    const float* b3 = (const float*)d_in[16];
    const float* m3 = (const float*)d_in[17];
    const float* v3 = (const float*)d_in[18];
    const float* a3 = (const float*)d_in[19];
    float* out = (float*)d_out;

    cudaFuncSetAttribute(asa_conv_mma_kernel,
                         cudaFuncAttributeMaxDynamicSharedMemorySize, CV_SMEM);
    cudaFuncSetAttribute(asa_time_attn_kernel,
                         cudaFuncAttributeMaxDynamicSharedMemorySize, TQ_SMEM);

    asa_prep_kernel<<<3, 256>>>(w_fqkv, w_tqk, g1, b1, m1, v1, a1,
                                g2, b2, m2, v2, a2, w_proj, g3, v3);
    asa_conv_mma_kernel<<<dim3(800, BB), 320, CV_SMEM>>>(inp);
    asa_transpose_qkv_kernel<<<dim3(13, 8, BB * 48), dim3(32, 8)>>>();
    asa_freq_attn_kernel<<<dim3(TT, BB), 256>>>();
    asa_transpose_fout_kernel<<<dim3(8, 13, BB * 16), dim3(32, 8)>>>();
    asa_time_attn_kernel<<<dim3(FF, BB), 256, TQ_SMEM>>>(inp,
        g3, b3, m3, v3, a3, out);
}

// round 15
// speedup vs baseline: 1.1391x; 1.0494x over previous
#include <cuda_runtime.h>
#include <cuda_bf16.h>
#include <cstdint>
#include <math.h>

#define BB 4
#define CC 64
#define FF 256
#define TT 400
#define DC 16
#define SP (FF*TT)

#define QS 0.36067376022224085f   /* 0.25 * log2(e) */

__device__ __forceinline__ float ex2f(float x) {
    float r; asm("ex2.approx.ftz.f32 %0, %1;" : "=f"(r) : "f"(x)); return r;
}
__device__ __forceinline__ uint32_t smem_u32(const void* p) {
    uint32_t a;
    asm("{ .reg .u64 t; cvta.to.shared.u64 t, %1; cvt.u32.u64 %0, t; }" : "=r"(a) : "l"(p));
    return a;
}
__device__ __forceinline__ void ldmx2(uint32_t& r0, uint32_t& r1, uint32_t a) {
    asm volatile("ldmatrix.sync.aligned.m8n8.x2.shared.b16 {%0,%1}, [%2];"
                 : "=r"(r0), "=r"(r1) : "r"(a));
}
__device__ __forceinline__ void ldmx4(uint4& r, uint32_t a) {
    asm volatile("ldmatrix.sync.aligned.m8n8.x4.shared.b16 {%0,%1,%2,%3}, [%4];"
                 : "=r"(r.x), "=r"(r.y), "=r"(r.z), "=r"(r.w) : "r"(a));
}
__device__ __forceinline__ void mma16816(float* d, uint4 a, uint32_t b0, uint32_t b1) {
    asm volatile("mma.sync.aligned.m16n8k16.row.col.f32.bf16.bf16.f32 "
        "{%0,%1,%2,%3}, {%4,%5,%6,%7}, {%8,%9}, {%0,%1,%2,%3};"
        : "+f"(d[0]), "+f"(d[1]), "+f"(d[2]), "+f"(d[3])
        : "r"(a.x), "r"(a.y), "r"(a.z), "r"(a.w), "r"(b0), "r"(b1));
}
#define PACKBF(r, a, b) asm("cvt.rn.bf16x2.f32 %0, %1, %2;" : "=r"(r) : "f"(b), "f"(a))

// ---------------- scratch ----------------
static __device__ float g_qkvf_t[(size_t)BB*48*FF*TT];
static __device__ float g_qkvf_f[(size_t)BB*TT*48*FF];
static __device__ float g_tqk2 [(size_t)BB*32*FF*TT];
static __device__ float g_fout_t[(size_t)BB*TT*DC*FF];
static __device__ float g_fout_f[(size_t)BB*FF*DC*TT];
static __device__ __align__(16) uint4 g_wafH[640];
static __device__ __align__(16) uint4 g_wafL[640];
static __device__ __align__(16) uint4 g_wpfH[128];
static __device__ __align__(16) uint4 g_wpfL[128];
static __device__ float g_shift[80];
static __device__ float g_alpha[80];

static __device__ const int BAND_LUT8[8][2] = {
    {12, -1}, {11, -1}, {10, -1}, {9, 0}, {8, 1}, {7, 2}, {6, 3}, {5, 4}
};

// ================= kernel 0: prep =================
__global__ __launch_bounds__(256)
void asa_prep_kernel(const float* __restrict__ w_fqkv, const float* __restrict__ w_tqk,
    const float* __restrict__ g1, const float* __restrict__ b1,
    const float* __restrict__ m1, const float* __restrict__ v1, const float* __restrict__ a1,
    const float* __restrict__ g2, const float* __restrict__ b2,
    const float* __restrict__ m2, const float* __restrict__ v2, const float* __restrict__ a2,
    const float* __restrict__ w_proj, const float* __restrict__ g3, const float* __restrict__ v3)
{
    int i = blockIdx.x * 256 + threadIdx.x;
    if (i < 640) {
        int lane = i & 31, ks = (i >> 5) & 3, o = i >> 7;
        int r = lane >> 2, cp = (lane & 3) * 2;
        int oc0 = o * 16 + r, k0 = ks * 16 + cp;
        uint32_t hiR[4], loR[4];
        #pragma unroll
        for (int aa = 0; aa < 4; aa++) {
            int oc = oc0 + ((aa & 1) << 3);
            int kk = k0 + ((aa >> 1) << 3);
            float s, w0, w1;
            if (oc < 48) {
                s = g1[oc] * rsqrtf(v1[oc] + 1e-5f);
                w0 = w_fqkv[oc * 64 + kk] * s; w1 = w_fqkv[oc * 64 + kk + 1] * s;
            } else {
                int j = oc - 48;
                s = g2[j] * rsqrtf(v2[j] + 1e-5f);
                w0 = w_tqk[j * 64 + kk] * s; w1 = w_tqk[j * 64 + kk + 1] * s;
            }
            uint32_t h; PACKBF(h, w0, w1);
            float r0 = __uint_as_float(h << 16);
            float r1 = __uint_as_float(h & 0xffff0000u);
            uint32_t l; PACKBF(l, w0 - r0, w1 - r1);
            hiR[aa] = h; loR[aa] = l;
        }
        g_wafH[i] = make_uint4(hiR[0], hiR[1], hiR[2], hiR[3]);
        g_wafL[i] = make_uint4(loR[0], loR[1], loR[2], loR[3]);
    } else if (i < 768) {
        int idx = i - 640;
        int lane = idx & 31, o = idx >> 5;
        int r = lane >> 2, cp = (lane & 3) * 2;
        uint32_t hiR[4], loR[4];
        #pragma unroll
        for (int aa = 0; aa < 4; aa++) {
            int oc = o * 16 + r + ((aa & 1) << 3);
            int kk = cp + ((aa >> 1) << 3);
            float s = g3[oc] * rsqrtf(v3[oc] + 1e-5f);
            float w0 = w_proj[oc * 16 + kk] * s;
            float w1 = w_proj[oc * 16 + kk + 1] * s;
            uint32_t h; PACKBF(h, w0, w1);
            float r0 = __uint_as_float(h << 16);
            float r1 = __uint_as_float(h & 0xffff0000u);
            uint32_t l; PACKBF(l, w0 - r0, w1 - r1);
            hiR[aa] = h; loR[aa] = l;
        }
        g_wpfH[idx] = make_uint4(hiR[0], hiR[1], hiR[2], hiR[3]);
        g_wpfL[idx] = make_uint4(loR[0], loR[1], loR[2], loR[3]);
    }
    if (i < 80) {
        float ss, sh, al;
        if (i < 48) { ss = g1[i] * rsqrtf(v1[i] + 1e-5f); sh = b1[i] - m1[i] * ss; al = a1[i]; }
        else { int j = i - 48; ss = g2[j] * rsqrtf(v2[j] + 1e-5f); sh = b2[j] - m2[j] * ss; al = a2[j]; }
        g_shift[i] = sh; g_alpha[i] = al;
    }
}

// ====== kernel 1: conv1x1 via mma.sync bf16 — X in plain bf16, W split ======
#define CV_STAGE 0          /* 64 * 132 floats = 33792 B */
#define CV_HI 33792         /* 128 rows x 128 B */
#define CV_SMEM 50176

__global__ __launch_bounds__(320)
void asa_conv_mma_kernel(const float* __restrict__ inp)
{
    extern __shared__ char smc[];
    float* xstage = (float*)(smc + CV_STAGE);
    uint32_t shi = smem_u32(smc + CV_HI);
    int tid = threadIdx.x, wid = tid >> 5, lane = tid & 31;
    int b = blockIdx.y;
    int n0 = blockIdx.x * 128;
    const float* xb = inp + (size_t)b * CC * SP + n0;

    for (int i = tid; i < 2048; i += 320) {
        int k = i >> 5, s4 = (i & 31) * 4;
        float4 v = *(const float4*)(xb + (size_t)k * SP + s4);
        *(float4*)(xstage + k * 132 + s4) = v;
    }
    __syncthreads();

    for (int ch = tid; ch < 1024; ch += 320) {
        int sp = ch & 127, kb = ch >> 7;
        float v[8];
        #pragma unroll
        for (int j = 0; j < 8; j++) v[j] = xstage[(kb * 8 + j) * 132 + sp];
        uint32_t hp[4];
        #pragma unroll
        for (int j = 0; j < 4; j++) { PACKBF(hp[j], v[2*j], v[2*j+1]); }
        uint32_t off = sp * 128 + ((kb * 16) ^ ((sp & 7) << 4));
        *(uint4*)(smc + CV_HI + off) = make_uint4(hp[0], hp[1], hp[2], hp[3]);
    }
    __syncthreads();

    int octile = wid >> 1, sptile = wid & 1;
    float d[8][4];
    #pragma unroll
    for (int nt = 0; nt < 8; nt++)
        #pragma unroll
        for (int j = 0; j < 4; j++) d[nt][j] = 0.f;

    int ln = lane & 15;
    int sprow_base = sptile * 64 + (ln & 7);
    int khalf = ((ln >> 3) & 1) << 3;

    #pragma unroll
    for (int ks = 0; ks < 4; ks++) {
        uint4 ah = g_wafH[(octile * 4 + ks) * 32 + lane];
        uint4 al = g_wafL[(octile * 4 + ks) * 32 + lane];
        #pragma unroll
        for (int nt = 0; nt < 8; nt++) {
            int spr = sprow_base + nt * 8;
            int ke = ks * 16 + khalf;
            uint32_t aoff = spr * 128 + ((ke * 2) ^ ((spr & 7) << 4));
            uint32_t bh0, bh1;
            ldmx2(bh0, bh1, shi + aoff);
            mma16816(d[nt], ah, bh0, bh1);
            mma16816(d[nt], al, bh0, bh1);
        }
    }

    int r = lane >> 2, cp = (lane & 3) * 2;
    #pragma unroll
    for (int half = 0; half < 2; half++) {
        int oc = octile * 16 + r + half * 8;
        float sh = g_shift[oc], al = g_alpha[oc];
        float* dst;
        if (oc < 48) dst = g_qkvf_t + ((size_t)b * 48 + oc) * SP + n0;
        else         dst = g_tqk2  + ((size_t)b * 32 + (oc - 48)) * SP + n0;
        #pragma unroll
        for (int nt = 0; nt < 8; nt++) {
            float v0 = d[nt][half * 2 + 0] + sh; v0 = v0 > 0.f ? v0 : al * v0;
            float v1 = d[nt][half * 2 + 1] + sh; v1 = v1 > 0.f ? v1 : al * v1;
            int sp = sptile * 64 + nt * 8 + cp;
            *(float2*)(dst + sp) = make_float2(v0, v1);
        }
    }
}

// ================= transpose 1 =================
__global__ __launch_bounds__(256)
void asa_transpose_qkv_kernel()
{
    __shared__ float tile[32][33];
    int z = blockIdx.z;
    int t0 = blockIdx.x * 32, f0 = blockIdx.y * 32;
    int tx = threadIdx.x, ty = threadIdx.y;
    size_t ibase = (size_t)z * FF * TT;
    #pragma unroll
    for (int k = 0; k < 32; k += 8) {
        int t = t0 + tx, f = f0 + ty + k;
        if (t < TT) tile[ty + k][tx] = g_qkvf_t[ibase + (size_t)f * TT + t];
    }
    __syncthreads();
    int b = z / 48, oc = z % 48;
    #pragma unroll
    for (int k = 0; k < 32; k += 8) {
        int t = t0 + ty + k, f = f0 + tx;
        if (t < TT) g_qkvf_f[((size_t)(b * TT + t) * 48 + oc) * FF + f] = tile[tx][ty + k];
    }
}

// ========== kernel 2: frequency attention — K,V plain bf16, Q split ==========
#define FQ_QHI 0
#define FQ_QLO 8192
#define FQ_KHI 16384
#define FQ_VHI 24576
#define FQ_SMEM 32768

__global__ __launch_bounds__(256)
void asa_freq_attn_kernel()
{
    __shared__ __align__(16) char smf[FQ_SMEM];
    int tid = threadIdx.x, wid = tid >> 5, lane = tid & 31;
    int t = blockIdx.x, b = blockIdx.y;
    const float* base = g_qkvf_f + (size_t)(b * TT + t) * 48 * FF;
    uint32_t sb = smem_u32(smf);

    for (int it = 0; it < 8; it++) {
        int idx = it * 256 + tid;
        int row = idx & 255;
        int cp = idx >> 8;
        uint32_t qkoff = (uint32_t)(row * 32 + cp * 4) ^ (uint32_t)(((row >> 2) & 1) << 4);
        {
            float x0 = base[(2*cp) * 256 + row] * QS;
            float x1 = base[(2*cp+1) * 256 + row] * QS;
            uint32_t h; PACKBF(h, x0, x1);
            float r0 = __uint_as_float(h << 16);
            float r1 = __uint_as_float(h & 0xffff0000u);
            uint32_t l; PACKBF(l, x0 - r0, x1 - r1);
            *(uint32_t*)(smf + FQ_QHI + qkoff) = h;
            *(uint32_t*)(smf + FQ_QLO + qkoff) = l;
        }
        {
            float x0 = base[4096 + (2*cp) * 256 + row];
            float x1 = base[4096 + (2*cp+1) * 256 + row];
            uint32_t h; PACKBF(h, x0, x1);
            *(uint32_t*)(smf + FQ_KHI + qkoff) = h;
        }
        {
            float x0 = base[8192 + (2*cp) * 256 + row];
            float x1 = base[8192 + (2*cp+1) * 256 + row];
            uint32_t h; PACKBF(h, x0, x1);
            int c0 = 2*cp, c1 = 2*cp + 1, y = row;
            uint32_t o0 = (uint32_t)(c0 * 512 + y * 2) ^ (uint32_t)((c0 & 7) << 4);
            uint32_t o1 = (uint32_t)(c1 * 512 + y * 2) ^ (uint32_t)((c1 & 7) << 4);
            *(uint16_t*)(smf + FQ_VHI + o0) = (uint16_t)(h & 0xffff);
            *(uint16_t*)(smf + FQ_VHI + o1) = (uint16_t)(h >> 16);
        }
    }
    __syncthreads();

    int fw = wid * 32;
    int l16 = lane & 15;
    int kh16 = ((lane >> 4) & 1) << 4;
    uint4 qh[2], ql[2];
    #pragma unroll
    for (int mt = 0; mt < 2; mt++) {
        int fr = fw + mt * 16 + l16;
        uint32_t off = (uint32_t)(fr * 32 + kh16) ^ (uint32_t)(((fr >> 2) & 1) << 4);
        ldmx4(qh[mt], sb + FQ_QHI + off);
        ldmx4(ql[mt], sb + FQ_QLO + off);
    }

    float O[2][2][4];
    #pragma unroll
    for (int mt = 0; mt < 2; mt++)
        #pragma unroll
        for (int nt = 0; nt < 2; nt++)
            #pragma unroll
            for (int j = 0; j < 4; j++) O[mt][nt][j] = 0.f;
    float lsum[4];
    #pragma unroll
    for (int i = 0; i < 4; i++) lsum[i] = 0.f;

    int rlow = l16 & 7;
    int khb = ((l16 >> 3) & 1) << 4;

    for (int y0 = 0; y0 < 256; y0 += 16) {
        uint32_t kb0[2], kb1[2];
        #pragma unroll
        for (int nt = 0; nt < 2; nt++) {
            int kr = y0 + nt * 8 + rlow;
            uint32_t off = (uint32_t)(kr * 32 + khb) ^ (uint32_t)(((kr >> 2) & 1) << 4);
            ldmx2(kb0[nt], kb1[nt], sb + FQ_KHI + off);
        }
        float S[2][2][4];
        #pragma unroll
        for (int mt = 0; mt < 2; mt++)
            #pragma unroll
            for (int nt = 0; nt < 2; nt++) {
                #pragma unroll
                for (int j = 0; j < 4; j++) S[mt][nt][j] = 0.f;
                mma16816(S[mt][nt], qh[mt], kb0[nt], kb1[nt]);
                mma16816(S[mt][nt], ql[mt], kb0[nt], kb1[nt]);
            }
        uint4 ph[2], pl[2];
        #pragma unroll
        for (int mt = 0; mt < 2; mt++) {
            float p[2][4];
            #pragma unroll
            for (int nt = 0; nt < 2; nt++)
                #pragma unroll
                for (int j = 0; j < 4; j++) p[nt][j] = ex2f(S[mt][nt][j]);
            lsum[2*mt]   += (p[0][0] + p[0][1]) + (p[1][0] + p[1][1]);
            lsum[2*mt+1] += (p[0][2] + p[0][3]) + (p[1][2] + p[1][3]);
            uint32_t hreg[4], lreg[4];
            #pragma unroll
            for (int q = 0; q < 4; q++) {
                int nt = q >> 1, jo = (q & 1) * 2;
                uint32_t h; PACKBF(h, p[nt][jo], p[nt][jo+1]);
                float r0 = __uint_as_float(h << 16);
                float r1 = __uint_as_float(h & 0xffff0000u);
                uint32_t l; PACKBF(l, p[nt][jo] - r0, p[nt][jo+1] - r1);
                hreg[q] = h; lreg[q] = l;
            }
            ph[mt] = make_uint4(hreg[0], hreg[1], hreg[2], hreg[3]);
            pl[mt] = make_uint4(lreg[0], lreg[1], lreg[2], lreg[3]);
        }
        uint32_t vb0[2], vb1[2];
        #pragma unroll
        for (int nt = 0; nt < 2; nt++) {
            int vc = nt * 8 + rlow;
            uint32_t off = (uint32_t)(vc * 512 + y0 * 2 + khb) ^ (uint32_t)((vc & 7) << 4);
            ldmx2(vb0[nt], vb1[nt], sb + FQ_VHI + off);
        }
        #pragma unroll
        for (int mt = 0; mt < 2; mt++)
            #pragma unroll
            for (int nt = 0; nt < 2; nt++) {
                mma16816(O[mt][nt], ph[mt], vb0[nt], vb1[nt]);
                mma16816(O[mt][nt], pl[mt], vb0[nt], vb1[nt]);
            }
    }

    #pragma unroll
    for (int i = 0; i < 4; i++) {
        lsum[i] += __shfl_xor_sync(0xffffffffu, lsum[i], 1);
        lsum[i] += __shfl_xor_sync(0xffffffffu, lsum[i], 2);
    }

    __syncthreads();
    float* st = (float*)smf;
    int r = lane >> 2, cq = (lane & 3) * 2;
    #pragma unroll
    for (int mt = 0; mt < 2; mt++) {
        float i0 = 1.f / lsum[2*mt], i1 = 1.f / lsum[2*mt+1];
        int f = fw + mt * 16 + r;
        #pragma unroll
        for (int nt = 0; nt < 2; nt++) {
            int c = nt * 8 + cq;
            st[c * 256 + f]           = O[mt][nt][0] * i0;
            st[(c + 1) * 256 + f]     = O[mt][nt][1] * i0;
            st[c * 256 + f + 8]       = O[mt][nt][2] * i1;
            st[(c + 1) * 256 + f + 8] = O[mt][nt][3] * i1;
        }
    }
    __syncthreads();
    float4* go = (float4*)(g_fout_t + (size_t)(b * TT + t) * DC * FF);
    const float4* s4 = (const float4*)smf;
    for (int i = tid; i < 1024; i += 256) go[i] = s4[i];
}

// ================= transpose 2 =================
__global__ __launch_bounds__(256)
void asa_transpose_fout_kernel()
{
    __shared__ float tile[32][33];
    int z = blockIdx.z;
    int f0 = blockIdx.x * 32, t0 = blockIdx.y * 32;
    int tx = threadIdx.x, ty = threadIdx.y;
    int b = z / 16, c = z % 16;
    #pragma unroll
    for (int k = 0; k < 32; k += 8) {
        int t = t0 + ty + k, f = f0 + tx;
        if (t < TT) tile[ty + k][tx] = g_fout_t[((size_t)(b * TT + t) * DC + c) * FF + f];
    }
    __syncthreads();
    #pragma unroll
    for (int k = 0; k < 32; k += 8) {
        int f = f0 + ty + k, t = t0 + tx;
        if (t < TT) g_fout_f[((size_t)(b * FF + f) * DC + c) * TT + t] = tile[tx][ty + k];
    }
}

// ======= kernel 3: causal time attention — K,V plain bf16, Q/P split =======
#define TQ_QHI 0
#define TQ_QLO 12800
#define TQ_KHI 25600
#define TQ_VHI 38400     /* 16 rows x 816 = 13056 */
#define TQ_PHI 51456
#define TQ_PLO 64256
#define TQ_SH  77056
#define TQ_AL  77312
#define TQ_SMEM 77568

template<int NMT>
__device__ __forceinline__ void tq_band(char* smt, uint32_t sb, int band, int lane)
{
    int l16 = lane & 15;
    int kh16 = ((lane >> 4) & 1) << 4;
    int rlow = l16 & 7;
    int khb = ((l16 >> 3) & 1) << 4;
    int rq = lane >> 2, cq = (lane & 3) * 2;

    uint4 qh[NMT], ql[NMT];
    #pragma unroll
    for (int m = 0; m < NMT; m++) {
        int fr = band * 32 + m * 16 + l16;
        uint32_t off = (uint32_t)(fr * 32 + kh16) ^ (uint32_t)(((fr >> 2) & 1) << 4);
        ldmx4(qh[m], sb + TQ_QHI + off);
        ldmx4(ql[m], sb + TQ_QLO + off);
    }
    float O[NMT][2][4];
    #pragma unroll
    for (int m = 0; m < NMT; m++)
        #pragma unroll
        for (int nt = 0; nt < 2; nt++)
            #pragma unroll
            for (int j = 0; j < 4; j++) O[m][nt][j] = 0.f;
    float ls[2 * NMT];
    #pragma unroll
    for (int i = 0; i < 2 * NMT; i++) ls[i] = 0.f;

    int CL = (NMT == 1) ? 24 : 2 * band + 1;

    #pragma unroll 1
    for (int ch = 0; ch <= CL; ch++) {
        int y0 = ch * 16;
        uint32_t kb0[2], kb1[2];
        #pragma unroll
        for (int nt = 0; nt < 2; nt++) {
            int kr = y0 + nt * 8 + rlow;
            uint32_t off = (uint32_t)(kr * 32 + khb) ^ (uint32_t)(((kr >> 2) & 1) << 4);
            ldmx2(kb0[nt], kb1[nt], sb + TQ_KHI + off);
        }
        float S[NMT][2][4];
        #pragma unroll
        for (int m = 0; m < NMT; m++)
            #pragma unroll
            for (int nt = 0; nt < 2; nt++) {
                #pragma unroll
                for (int j = 0; j < 4; j++) S[m][nt][j] = 0.f;
                mma16816(S[m][nt], qh[m], kb0[nt], kb1[nt]);
                mma16816(S[m][nt], ql[m], kb0[nt], kb1[nt]);
            }
        if (ch >= 2 * band) {
            #pragma unroll
            for (int m = 0; m < NMT; m++) {
                int rg0 = band * 32 + m * 16 + rq;
                int rg1 = rg0 + 8;
                #pragma unroll
                for (int nt = 0; nt < 2; nt++) {
                    int cg = y0 + nt * 8 + cq;
                    if (cg     > rg0) S[m][nt][0] = -3e38f;
                    if (cg + 1 > rg0) S[m][nt][1] = -3e38f;
                    if (cg     > rg1) S[m][nt][2] = -3e38f;
                    if (cg + 1 > rg1) S[m][nt][3] = -3e38f;
                }
            }
        }
        uint4 ph[NMT], pl[NMT];
        #pragma unroll
        for (int m = 0; m < NMT; m++) {
            float p[2][4];
            #pragma unroll
            for (int nt = 0; nt < 2; nt++)
                #pragma unroll
                for (int j = 0; j < 4; j++) p[nt][j] = ex2f(S[m][nt][j]);
            ls[2*m]   += (p[0][0] + p[0][1]) + (p[1][0] + p[1][1]);
            ls[2*m+1] += (p[0][2] + p[0][3]) + (p[1][2] + p[1][3]);
            uint32_t hreg[4], lreg[4];
            #pragma unroll
            for (int q = 0; q < 4; q++) {
                int nt = q >> 1, jo = (q & 1) * 2;
                uint32_t h; PACKBF(h, p[nt][jo], p[nt][jo+1]);
                float r0 = __uint_as_float(h << 16);
                float r1 = __uint_as_float(h & 0xffff0000u);
                uint32_t l; PACKBF(l, p[nt][jo] - r0, p[nt][jo+1] - r1);
                hreg[q] = h; lreg[q] = l;
            }
            ph[m] = make_uint4(hreg[0], hreg[1], hreg[2], hreg[3]);
            pl[m] = make_uint4(lreg[0], lreg[1], lreg[2], lreg[3]);
        }
        uint32_t vb0[2], vb1[2];
        #pragma unroll
        for (int nt = 0; nt < 2; nt++) {
            int vc = nt * 8 + rlow;
            uint32_t off = (uint32_t)(vc * 816 + y0 * 2 + khb);
            ldmx2(vb0[nt], vb1[nt], sb + TQ_VHI + off);
        }
        #pragma unroll
        for (int m = 0; m < NMT; m++)
            #pragma unroll
            for (int nt = 0; nt < 2; nt++) {
                mma16816(O[m][nt], ph[m], vb0[nt], vb1[nt]);
                mma16816(O[m][nt], pl[m], vb0[nt], vb1[nt]);
            }
    }

    #pragma unroll
    for (int i = 0; i < 2 * NMT; i++) {
        ls[i] += __shfl_xor_sync(0xffffffffu, ls[i], 1);
        ls[i] += __shfl_xor_sync(0xffffffffu, ls[i], 2);
    }

    #pragma unroll
    for (int m = 0; m < NMT; m++) {
        float i0 = 1.f / ls[2*m], i1 = 1.f / ls[2*m+1];
        int row0 = band * 32 + m * 16 + rq, row1 = row0 + 8;
        #pragma unroll
        for (int nt = 0; nt < 2; nt++) {
            int c = nt * 8 + cq;
            float p0 = O[m][nt][0] * i0, p1 = O[m][nt][1] * i0;
            float p2 = O[m][nt][2] * i1, p3 = O[m][nt][3] * i1;
            uint32_t h0; PACKBF(h0, p0, p1);
            uint32_t l0; PACKBF(l0, p0 - __uint_as_float(h0 << 16),
                                    p1 - __uint_as_float(h0 & 0xffff0000u));
            uint32_t h1; PACKBF(h1, p2, p3);
            uint32_t l1; PACKBF(l1, p2 - __uint_as_float(h1 << 16),
                                    p3 - __uint_as_float(h1 & 0xffff0000u));
            uint32_t a0 = (uint32_t)(row0 * 32 + c * 2) ^ (uint32_t)(((row0 >> 2) & 1) << 4);
            uint32_t a1 = (uint32_t)(row1 * 32 + c * 2) ^ (uint32_t)(((row1 >> 2) & 1) << 4);
            *(uint32_t*)(smt + TQ_PHI + a0) = h0;
            *(uint32_t*)(smt + TQ_PLO + a0) = l0;
            *(uint32_t*)(smt + TQ_PHI + a1) = h1;
            *(uint32_t*)(smt + TQ_PLO + a1) = l1;
        }
    }
}

__global__ __launch_bounds__(256, 2)
void asa_time_attn_kernel(const float* __restrict__ inp,
    const float* __restrict__ g3, const float* __restrict__ b3, const float* __restrict__ m3,
    const float* __restrict__ v3, const float* __restrict__ a3, float* __restrict__ out)
{
    extern __shared__ char smt[];
    uint32_t sb = smem_u32(smt);
    int tid = threadIdx.x, wid = tid >> 5, lane = tid & 31;
    int f = blockIdx.x, b = blockIdx.y;
    size_t cbase = (size_t)b * 32 * SP + (size_t)f * TT;
    const float* vg = g_fout_f + (size_t)(b * FF + f) * DC * TT;

    #pragma unroll 1
    for (int idx = tid; idx < 3200; idx += 256) {
        int t = idx % 400;
        int cp = idx / 400;
        uint32_t qkoff = (uint32_t)(t * 32 + cp * 4) ^ (uint32_t)(((t >> 2) & 1) << 4);
        {
            float x0 = g_tqk2[cbase + (size_t)(2*cp) * SP + t] * QS;
            float x1 = g_tqk2[cbase + (size_t)(2*cp+1) * SP + t] * QS;
            uint32_t h; PACKBF(h, x0, x1);
            float r0 = __uint_as_float(h << 16);
            float r1 = __uint_as_float(h & 0xffff0000u);
            uint32_t l; PACKBF(l, x0 - r0, x1 - r1);
            *(uint32_t*)(smt + TQ_QHI + qkoff) = h;
            *(uint32_t*)(smt + TQ_QLO + qkoff) = l;
        }
        {
            float x0 = g_tqk2[cbase + (size_t)(16 + 2*cp) * SP + t];
            float x1 = g_tqk2[cbase + (size_t)(17 + 2*cp) * SP + t];
            uint32_t h; PACKBF(h, x0, x1);
            *(uint32_t*)(smt + TQ_KHI + qkoff) = h;
        }
        {
            float x0 = vg[(size_t)(2*cp) * TT + t];
            float x1 = vg[(size_t)(2*cp+1) * TT + t];
            uint32_t h; PACKBF(h, x0, x1);
            uint32_t o0 = (uint32_t)((2*cp) * 816 + t * 2);
            uint32_t o1 = (uint32_t)((2*cp+1) * 816 + t * 2);
            *(uint16_t*)(smt + TQ_VHI + o0) = (uint16_t)(h & 0xffff);
            *(uint16_t*)(smt + TQ_VHI + o1) = (uint16_t)(h >> 16);
        }
    }
    if (tid < 64) {
        float s = g3[tid] * rsqrtf(v3[tid] + 1e-5f);
        ((float*)(smt + TQ_SH))[tid] = b3[tid] - m3[tid] * s;
        ((float*)(smt + TQ_AL))[tid] = a3[tid];
    }
    __syncthreads();

    #pragma unroll 1
    for (int bi = 0; bi < 2; bi++) {
        int band = BAND_LUT8[wid][bi];
        if (band < 0) break;
        if (band == 12) tq_band<1>(smt, sb, band, lane);
        else            tq_band<2>(smt, sb, band, lane);
    }
    __syncthreads();

    // projection via mma: D[64oc, 400t] = Wproj(scaled) @ P  (3-term, keeps P precision)
    const float* sh3 = (const float*)(smt + TQ_SH);
    const float* al3 = (const float*)(smt + TQ_AL);
    int l16 = lane & 15;
    int rlow = l16 & 7;
    int khb = ((l16 >> 3) & 1) << 4;
    int rq = lane >> 2, cq = (lane & 3) * 2;
    int m = wid & 3;
    int nt0 = (wid < 4) ? 0 : 25;
    uint4 wh = g_wpfH[m * 32 + lane];
    uint4 wl = g_wpfL[m * 32 + lane];
    int oc0 = m * 16 + rq, oc1 = oc0 + 8;
    float sh0 = sh3[oc0], al0 = al3[oc0];
    float sh1 = sh3[oc1], al1 = al3[oc1];
    size_t ob0 = (((size_t)b * CC + oc0) * FF + f) * TT;
    size_t ob1 = (((size_t)b * CC + oc1) * FF + f) * TT;

    #pragma unroll 1
    for (int ntile = nt0; ntile < nt0 + 25; ntile++) {
        int pr = ntile * 8 + rlow;
        uint32_t off = (uint32_t)(pr * 32 + khb) ^ (uint32_t)(((pr >> 2) & 1) << 4);
        uint32_t bh0, bh1, bl0, bl1;
        ldmx2(bh0, bh1, sb + TQ_PHI + off);
        ldmx2(bl0, bl1, sb + TQ_PLO + off);
        float D[4] = {0.f, 0.f, 0.f, 0.f};
        mma16816(D, wh, bh0, bh1);
        mma16816(D, wl, bh0, bh1);
        mma16816(D, wh, bl0, bl1);

        int tcol = ntile * 8 + cq;
        float2 r0 = *(const float2*)(inp + ob0 + tcol);
        float2 r1 = *(const float2*)(inp + ob1 + tcol);
        float v0 = D[0] + sh0; v0 = v0 > 0.f ? v0 : al0 * v0;
        float v1 = D[1] + sh0; v1 = v1 > 0.f ? v1 : al0 * v1;
        float v2 = D[2] + sh1; v2 = v2 > 0.f ? v2 : al1 * v2;
        float v3v = D[3] + sh1; v3v = v3v > 0.f ? v3v : al1 * v3v;
        *(float2*)(out + ob0 + tcol) = make_float2(v0 + r0.x, v1 + r0.y);
        *(float2*)(out + ob1 + tcol) = make_float2(v2 + r1.x, v3v + r1.y);
    }
}

// ================= launcher =================
extern "C" void kernel_launch(void* const* d_in, const int* in_sizes, int n_in,
                              void* d_out, int out_size)
{
    (void)in_sizes; (void)n_in; (void)out_size;
    const float* inp    = (const float*)d_in[0];
    const float* w_fqkv = (const float*)d_in[2];
    const float* g1 = (const float*)d_in[3];
    const float* b1 = (const float*)d_in[4];
    const float* m1 = (const float*)d_in[5];
    const float* v1 = (const float*)d_in[6];
    const float* a1 = (const float*)d_in[7];
    const float* w_tqk  = (const float*)d_in[8];
    const float* g2 = (const float*)d_in[9];
    const float* b2 = (const float*)d_in[10];
    const float* m2 = (const float*)d_in[11];
    const float* v2 = (const float*)d_in[12];
    const float* a2 = (const float*)d_in[13];
    const float* w_proj = (const float*)d_in[14];
    const float* g3 = (const float*)d_in[15];
    const float* b3 = (const float*)d_in[16];
    const float* m3 = (const float*)d_in[17];
    const float* v3 = (const float*)d_in[18];
    const float* a3 = (const float*)d_in[19];
    float* out = (float*)d_out;

    cudaFuncSetAttribute(asa_conv_mma_kernel,
                         cudaFuncAttributeMaxDynamicSharedMemorySize, CV_SMEM);
    cudaFuncSetAttribute(asa_time_attn_kernel,
                         cudaFuncAttributeMaxDynamicSharedMemorySize, TQ_SMEM);

    asa_prep_kernel<<<3, 256>>>(w_fqkv, w_tqk, g1, b1, m1, v1, a1,
                                g2, b2, m2, v2, a2, w_proj, g3, v3);
    asa_conv_mma_kernel<<<dim3(800, BB), 320, CV_SMEM>>>(inp);
    asa_transpose_qkv_kernel<<<dim3(13, 8, BB * 48), dim3(32, 8)>>>();
    asa_freq_attn_kernel<<<dim3(TT, BB), 256>>>();
    asa_transpose_fout_kernel<<<dim3(8, 13, BB * 16), dim3(32, 8)>>>();
    asa_time_attn_kernel<<<dim3(FF, BB), 256, TQ_SMEM>>>(inp,
        g3, b3, m3, v3, a3, out);
}

// round 16
// speedup vs baseline: 1.3393x; 1.1757x over previous
#include <cuda_runtime.h>
#include <cuda_bf16.h>
#include <cstdint>
#include <math.h>

#define BB 4
#define CC 64
#define FF 256
#define TT 400
#define DC 16
#define SP (FF*TT)

#define QS 0.36067376022224085f   /* 0.25 * log2(e) */

__device__ __forceinline__ float ex2f(float x) {
    float r; asm("ex2.approx.ftz.f32 %0, %1;" : "=f"(r) : "f"(x)); return r;
}
__device__ __forceinline__ uint32_t smem_u32(const void* p) {
    uint32_t a;
    asm("{ .reg .u64 t; cvta.to.shared.u64 t, %1; cvt.u32.u64 %0, t; }" : "=r"(a) : "l"(p));
    return a;
}
__device__ __forceinline__ void ldmx2(uint32_t& r0, uint32_t& r1, uint32_t a) {
    asm volatile("ldmatrix.sync.aligned.m8n8.x2.shared.b16 {%0,%1}, [%2];"
                 : "=r"(r0), "=r"(r1) : "r"(a));
}
__device__ __forceinline__ void ldmx4(uint4& r, uint32_t a) {
    asm volatile("ldmatrix.sync.aligned.m8n8.x4.shared.b16 {%0,%1,%2,%3}, [%4];"
                 : "=r"(r.x), "=r"(r.y), "=r"(r.z), "=r"(r.w) : "r"(a));
}
__device__ __forceinline__ void mma16816(float* d, uint4 a, uint32_t b0, uint32_t b1) {
    asm volatile("mma.sync.aligned.m16n8k16.row.col.f32.bf16.bf16.f32 "
        "{%0,%1,%2,%3}, {%4,%5,%6,%7}, {%8,%9}, {%0,%1,%2,%3};"
        : "+f"(d[0]), "+f"(d[1]), "+f"(d[2]), "+f"(d[3])
        : "r"(a.x), "r"(a.y), "r"(a.z), "r"(a.w), "r"(b0), "r"(b1));
}
#define PACKBF(r, a, b) asm("cvt.rn.bf16x2.f32 %0, %1, %2;" : "=r"(r) : "f"(b), "f"(a))

// ---------------- scratch ----------------
static __device__ float g_qkvf_t[(size_t)BB*48*FF*TT];
static __device__ float g_qkvf_f[(size_t)BB*TT*48*FF];
static __device__ float g_tqk2 [(size_t)BB*32*FF*TT];
static __device__ float g_fout_t[(size_t)BB*TT*DC*FF];
static __device__ float g_fout_f[(size_t)BB*FF*DC*TT];
static __device__ __align__(16) uint4 g_wafH[640];
static __device__ __align__(16) uint4 g_wpfH[128];
static __device__ __align__(16) uint4 g_wpfL[128];
static __device__ float g_shift[80];
static __device__ float g_alpha[80];

static __device__ const int BAND_LUT8[8][2] = {
    {12, -1}, {11, -1}, {10, -1}, {9, 0}, {8, 1}, {7, 2}, {6, 3}, {5, 4}
};

// ================= kernel 0: prep =================
__global__ __launch_bounds__(256)
void asa_prep_kernel(const float* __restrict__ w_fqkv, const float* __restrict__ w_tqk,
    const float* __restrict__ g1, const float* __restrict__ b1,
    const float* __restrict__ m1, const float* __restrict__ v1, const float* __restrict__ a1,
    const float* __restrict__ g2, const float* __restrict__ b2,
    const float* __restrict__ m2, const float* __restrict__ v2, const float* __restrict__ a2,
    const float* __restrict__ w_proj, const float* __restrict__ g3, const float* __restrict__ v3)
{
    int i = blockIdx.x * 256 + threadIdx.x;
    if (i < 640) {
        int lane = i & 31, ks = (i >> 5) & 3, o = i >> 7;
        int r = lane >> 2, cp = (lane & 3) * 2;
        int oc0 = o * 16 + r, k0 = ks * 16 + cp;
        uint32_t hiR[4];
        #pragma unroll
        for (int aa = 0; aa < 4; aa++) {
            int oc = oc0 + ((aa & 1) << 3);
            int kk = k0 + ((aa >> 1) << 3);
            float s, w0, w1;
            if (oc < 48) {
                s = g1[oc] * rsqrtf(v1[oc] + 1e-5f);
                w0 = w_fqkv[oc * 64 + kk] * s; w1 = w_fqkv[oc * 64 + kk + 1] * s;
            } else {
                int j = oc - 48;
                s = g2[j] * rsqrtf(v2[j] + 1e-5f);
                w0 = w_tqk[j * 64 + kk] * s; w1 = w_tqk[j * 64 + kk + 1] * s;
            }
            PACKBF(hiR[aa], w0, w1);
        }
        g_wafH[i] = make_uint4(hiR[0], hiR[1], hiR[2], hiR[3]);
    } else if (i < 768) {
        int idx = i - 640;
        int lane = idx & 31, o = idx >> 5;
        int r = lane >> 2, cp = (lane & 3) * 2;
        uint32_t hiR[4], loR[4];
        #pragma unroll
        for (int aa = 0; aa < 4; aa++) {
            int oc = o * 16 + r + ((aa & 1) << 3);
            int kk = cp + ((aa >> 1) << 3);
            float s = g3[oc] * rsqrtf(v3[oc] + 1e-5f);
            float w0 = w_proj[oc * 16 + kk] * s;
            float w1 = w_proj[oc * 16 + kk + 1] * s;
            uint32_t h; PACKBF(h, w0, w1);
            float r0 = __uint_as_float(h << 16);
            float r1 = __uint_as_float(h & 0xffff0000u);
            uint32_t l; PACKBF(l, w0 - r0, w1 - r1);
            hiR[aa] = h; loR[aa] = l;
        }
        g_wpfH[idx] = make_uint4(hiR[0], hiR[1], hiR[2], hiR[3]);
        g_wpfL[idx] = make_uint4(loR[0], loR[1], loR[2], loR[3]);
    }
    if (i < 80) {
        float ss, sh, al;
        if (i < 48) { ss = g1[i] * rsqrtf(v1[i] + 1e-5f); sh = b1[i] - m1[i] * ss; al = a1[i]; }
        else { int j = i - 48; ss = g2[j] * rsqrtf(v2[j] + 1e-5f); sh = b2[j] - m2[j] * ss; al = a2[j]; }
        g_shift[i] = sh; g_alpha[i] = al;
    }
}

// ====== kernel 1: conv1x1 via mma.sync — pure bf16 ======
#define CV_STAGE 0          /* 64 * 132 floats = 33792 B */
#define CV_HI 33792         /* 128 rows x 128 B */
#define CV_SMEM 50176

__global__ __launch_bounds__(320)
void asa_conv_mma_kernel(const float* __restrict__ inp)
{
    extern __shared__ char smc[];
    float* xstage = (float*)(smc + CV_STAGE);
    uint32_t shi = smem_u32(smc + CV_HI);
    int tid = threadIdx.x, wid = tid >> 5, lane = tid & 31;
    int b = blockIdx.y;
    int n0 = blockIdx.x * 128;
    const float* xb = inp + (size_t)b * CC * SP + n0;

    for (int i = tid; i < 2048; i += 320) {
        int k = i >> 5, s4 = (i & 31) * 4;
        float4 v = *(const float4*)(xb + (size_t)k * SP + s4);
        *(float4*)(xstage + k * 132 + s4) = v;
    }
    __syncthreads();

    for (int ch = tid; ch < 1024; ch += 320) {
        int sp = ch & 127, kb = ch >> 7;
        float v[8];
        #pragma unroll
        for (int j = 0; j < 8; j++) v[j] = xstage[(kb * 8 + j) * 132 + sp];
        uint32_t hp[4];
        #pragma unroll
        for (int j = 0; j < 4; j++) { PACKBF(hp[j], v[2*j], v[2*j+1]); }
        uint32_t off = sp * 128 + ((kb * 16) ^ ((sp & 7) << 4));
        *(uint4*)(smc + CV_HI + off) = make_uint4(hp[0], hp[1], hp[2], hp[3]);
    }
    __syncthreads();

    int octile = wid >> 1, sptile = wid & 1;
    float d[8][4];
    #pragma unroll
    for (int nt = 0; nt < 8; nt++)
        #pragma unroll
        for (int j = 0; j < 4; j++) d[nt][j] = 0.f;

    int ln = lane & 15;
    int sprow_base = sptile * 64 + (ln & 7);
    int khalf = ((ln >> 3) & 1) << 3;

    #pragma unroll
    for (int ks = 0; ks < 4; ks++) {
        uint4 ah = g_wafH[(octile * 4 + ks) * 32 + lane];
        #pragma unroll
        for (int nt = 0; nt < 8; nt++) {
            int spr = sprow_base + nt * 8;
            int ke = ks * 16 + khalf;
            uint32_t aoff = spr * 128 + ((ke * 2) ^ ((spr & 7) << 4));
            uint32_t bh0, bh1;
            ldmx2(bh0, bh1, shi + aoff);
            mma16816(d[nt], ah, bh0, bh1);
        }
    }

    int r = lane >> 2, cp = (lane & 3) * 2;
    #pragma unroll
    for (int half = 0; half < 2; half++) {
        int oc = octile * 16 + r + half * 8;
        float sh = g_shift[oc], al = g_alpha[oc];
        float* dst;
        if (oc < 48) dst = g_qkvf_t + ((size_t)b * 48 + oc) * SP + n0;
        else         dst = g_tqk2  + ((size_t)b * 32 + (oc - 48)) * SP + n0;
        #pragma unroll
        for (int nt = 0; nt < 8; nt++) {
            float v0 = d[nt][half * 2 + 0] + sh; v0 = v0 > 0.f ? v0 : al * v0;
            float v1 = d[nt][half * 2 + 1] + sh; v1 = v1 > 0.f ? v1 : al * v1;
            int sp = sptile * 64 + nt * 8 + cp;
            *(float2*)(dst + sp) = make_float2(v0, v1);
        }
    }
}

// ================= transpose 1 =================
__global__ __launch_bounds__(256)
void asa_transpose_qkv_kernel()
{
    __shared__ float tile[32][33];
    int z = blockIdx.z;
    int t0 = blockIdx.x * 32, f0 = blockIdx.y * 32;
    int tx = threadIdx.x, ty = threadIdx.y;
    size_t ibase = (size_t)z * FF * TT;
    #pragma unroll
    for (int k = 0; k < 32; k += 8) {
        int t = t0 + tx, f = f0 + ty + k;
        if (t < TT) tile[ty + k][tx] = g_qkvf_t[ibase + (size_t)f * TT + t];
    }
    __syncthreads();
    int b = z / 48, oc = z % 48;
    #pragma unroll
    for (int k = 0; k < 32; k += 8) {
        int t = t0 + ty + k, f = f0 + tx;
        if (t < TT) g_qkvf_f[((size_t)(b * TT + t) * 48 + oc) * FF + f] = tile[tx][ty + k];
    }
}

// ========== kernel 2: frequency attention — pure bf16 ==========
#define FQ_QHI 0
#define FQ_KHI 8192
#define FQ_VHI 16384
#define FQ_SMEM 24576

__global__ __launch_bounds__(256)
void asa_freq_attn_kernel()
{
    __shared__ __align__(16) char smf[FQ_SMEM];
    int tid = threadIdx.x, wid = tid >> 5, lane = tid & 31;
    int t = blockIdx.x, b = blockIdx.y;
    const float* base = g_qkvf_f + (size_t)(b * TT + t) * 48 * FF;
    uint32_t sb = smem_u32(smf);

    for (int it = 0; it < 8; it++) {
        int idx = it * 256 + tid;
        int row = idx & 255;
        int cp = idx >> 8;
        uint32_t qkoff = (uint32_t)(row * 32 + cp * 4) ^ (uint32_t)(((row >> 2) & 1) << 4);
        {
            float x0 = base[(2*cp) * 256 + row] * QS;
            float x1 = base[(2*cp+1) * 256 + row] * QS;
            uint32_t h; PACKBF(h, x0, x1);
            *(uint32_t*)(smf + FQ_QHI + qkoff) = h;
        }
        {
            float x0 = base[4096 + (2*cp) * 256 + row];
            float x1 = base[4096 + (2*cp+1) * 256 + row];
            uint32_t h; PACKBF(h, x0, x1);
            *(uint32_t*)(smf + FQ_KHI + qkoff) = h;
        }
        {
            float x0 = base[8192 + (2*cp) * 256 + row];
            float x1 = base[8192 + (2*cp+1) * 256 + row];
            uint32_t h; PACKBF(h, x0, x1);
            int c0 = 2*cp, c1 = 2*cp + 1, y = row;
            uint32_t o0 = (uint32_t)(c0 * 512 + y * 2) ^ (uint32_t)((c0 & 7) << 4);
            uint32_t o1 = (uint32_t)(c1 * 512 + y * 2) ^ (uint32_t)((c1 & 7) << 4);
            *(uint16_t*)(smf + FQ_VHI + o0) = (uint16_t)(h & 0xffff);
            *(uint16_t*)(smf + FQ_VHI + o1) = (uint16_t)(h >> 16);
        }
    }
    __syncthreads();

    int fw = wid * 32;
    int l16 = lane & 15;
    int kh16 = ((lane >> 4) & 1) << 4;
    uint4 qh[2];
    #pragma unroll
    for (int mt = 0; mt < 2; mt++) {
        int fr = fw + mt * 16 + l16;
        uint32_t off = (uint32_t)(fr * 32 + kh16) ^ (uint32_t)(((fr >> 2) & 1) << 4);
        ldmx4(qh[mt], sb + FQ_QHI + off);
    }

    float O[2][2][4];
    #pragma unroll
    for (int mt = 0; mt < 2; mt++)
        #pragma unroll
        for (int nt = 0; nt < 2; nt++)
            #pragma unroll
            for (int j = 0; j < 4; j++) O[mt][nt][j] = 0.f;
    float lsum[4];
    #pragma unroll
    for (int i = 0; i < 4; i++) lsum[i] = 0.f;

    int rlow = l16 & 7;
    int khb = ((l16 >> 3) & 1) << 4;

    for (int y0 = 0; y0 < 256; y0 += 16) {
        uint32_t kb0[2], kb1[2];
        #pragma unroll
        for (int nt = 0; nt < 2; nt++) {
            int kr = y0 + nt * 8 + rlow;
            uint32_t off = (uint32_t)(kr * 32 + khb) ^ (uint32_t)(((kr >> 2) & 1) << 4);
            ldmx2(kb0[nt], kb1[nt], sb + FQ_KHI + off);
        }
        float S[2][2][4];
        #pragma unroll
        for (int mt = 0; mt < 2; mt++)
            #pragma unroll
            for (int nt = 0; nt < 2; nt++) {
                #pragma unroll
                for (int j = 0; j < 4; j++) S[mt][nt][j] = 0.f;
                mma16816(S[mt][nt], qh[mt], kb0[nt], kb1[nt]);
            }
        uint4 ph[2];
        #pragma unroll
        for (int mt = 0; mt < 2; mt++) {
            float p[2][4];
            #pragma unroll
            for (int nt = 0; nt < 2; nt++)
                #pragma unroll
                for (int j = 0; j < 4; j++) p[nt][j] = ex2f(S[mt][nt][j]);
            lsum[2*mt]   += (p[0][0] + p[0][1]) + (p[1][0] + p[1][1]);
            lsum[2*mt+1] += (p[0][2] + p[0][3]) + (p[1][2] + p[1][3]);
            uint32_t hreg[4];
            #pragma unroll
            for (int q = 0; q < 4; q++) {
                int nt = q >> 1, jo = (q & 1) * 2;
                PACKBF(hreg[q], p[nt][jo], p[nt][jo+1]);
            }
            ph[mt] = make_uint4(hreg[0], hreg[1], hreg[2], hreg[3]);
        }
        uint32_t vb0[2], vb1[2];
        #pragma unroll
        for (int nt = 0; nt < 2; nt++) {
            int vc = nt * 8 + rlow;
            uint32_t off = (uint32_t)(vc * 512 + y0 * 2 + khb) ^ (uint32_t)((vc & 7) << 4);
            ldmx2(vb0[nt], vb1[nt], sb + FQ_VHI + off);
        }
        #pragma unroll
        for (int mt = 0; mt < 2; mt++)
            #pragma unroll
            for (int nt = 0; nt < 2; nt++)
                mma16816(O[mt][nt], ph[mt], vb0[nt], vb1[nt]);
    }

    #pragma unroll
    for (int i = 0; i < 4; i++) {
        lsum[i] += __shfl_xor_sync(0xffffffffu, lsum[i], 1);
        lsum[i] += __shfl_xor_sync(0xffffffffu, lsum[i], 2);
    }

    __syncthreads();
    float* st = (float*)smf;
    int r = lane >> 2, cq = (lane & 3) * 2;
    #pragma unroll
    for (int mt = 0; mt < 2; mt++) {
        float i0 = 1.f / lsum[2*mt], i1 = 1.f / lsum[2*mt+1];
        int f = fw + mt * 16 + r;
        #pragma unroll
        for (int nt = 0; nt < 2; nt++) {
            int c = nt * 8 + cq;
            st[c * 256 + f]           = O[mt][nt][0] * i0;
            st[(c + 1) * 256 + f]     = O[mt][nt][1] * i0;
            st[c * 256 + f + 8]       = O[mt][nt][2] * i1;
            st[(c + 1) * 256 + f + 8] = O[mt][nt][3] * i1;
        }
    }
    __syncthreads();
    float4* go = (float4*)(g_fout_t + (size_t)(b * TT + t) * DC * FF);
    const float4* s4 = (const float4*)smf;
    for (int i = tid; i < 1024; i += 256) go[i] = s4[i];
}

// ================= transpose 2 =================
__global__ __launch_bounds__(256)
void asa_transpose_fout_kernel()
{
    __shared__ float tile[32][33];
    int z = blockIdx.z;
    int f0 = blockIdx.x * 32, t0 = blockIdx.y * 32;
    int tx = threadIdx.x, ty = threadIdx.y;
    int b = z / 16, c = z % 16;
    #pragma unroll
    for (int k = 0; k < 32; k += 8) {
        int t = t0 + ty + k, f = f0 + tx;
        if (t < TT) tile[ty + k][tx] = g_fout_t[((size_t)(b * TT + t) * DC + c) * FF + f];
    }
    __syncthreads();
    #pragma unroll
    for (int k = 0; k < 32; k += 8) {
        int f = f0 + ty + k, t = t0 + tx;
        if (t < TT) g_fout_f[((size_t)(b * FF + f) * DC + c) * TT + t] = tile[tx][ty + k];
    }
}

// ======= kernel 3: causal time attention — pure bf16 mainloop, split proj =======
#define TQ_QHI 0
#define TQ_KHI 12800
#define TQ_VHI 25600     /* 16 rows x 816 = 13056 */
#define TQ_PHI 38656
#define TQ_PLO 51456
#define TQ_SH  64256
#define TQ_AL  64512
#define TQ_SMEM 64768

template<int NMT>
__device__ __forceinline__ void tq_band(char* smt, uint32_t sb, int band, int lane)
{
    int l16 = lane & 15;
    int kh16 = ((lane >> 4) & 1) << 4;
    int rlow = l16 & 7;
    int khb = ((l16 >> 3) & 1) << 4;
    int rq = lane >> 2, cq = (lane & 3) * 2;

    uint4 qh[NMT];
    #pragma unroll
    for (int m = 0; m < NMT; m++) {
        int fr = band * 32 + m * 16 + l16;
        uint32_t off = (uint32_t)(fr * 32 + kh16) ^ (uint32_t)(((fr >> 2) & 1) << 4);
        ldmx4(qh[m], sb + TQ_QHI + off);
    }
    float O[NMT][2][4];
    #pragma unroll
    for (int m = 0; m < NMT; m++)
        #pragma unroll
        for (int nt = 0; nt < 2; nt++)
            #pragma unroll
            for (int j = 0; j < 4; j++) O[m][nt][j] = 0.f;
    float ls[2 * NMT];
    #pragma unroll
    for (int i = 0; i < 2 * NMT; i++) ls[i] = 0.f;

    int CL = (NMT == 1) ? 24 : 2 * band + 1;

    #pragma unroll 1
    for (int ch = 0; ch <= CL; ch++) {
        int y0 = ch * 16;
        uint32_t kb0[2], kb1[2];
        #pragma unroll
        for (int nt = 0; nt < 2; nt++) {
            int kr = y0 + nt * 8 + rlow;
            uint32_t off = (uint32_t)(kr * 32 + khb) ^ (uint32_t)(((kr >> 2) & 1) << 4);
            ldmx2(kb0[nt], kb1[nt], sb + TQ_KHI + off);
        }
        float S[NMT][2][4];
        #pragma unroll
        for (int m = 0; m < NMT; m++)
            #pragma unroll
            for (int nt = 0; nt < 2; nt++) {
                #pragma unroll
                for (int j = 0; j < 4; j++) S[m][nt][j] = 0.f;
                mma16816(S[m][nt], qh[m], kb0[nt], kb1[nt]);
            }
        if (ch >= 2 * band) {
            #pragma unroll
            for (int m = 0; m < NMT; m++) {
                int rg0 = band * 32 + m * 16 + rq;
                int rg1 = rg0 + 8;
                #pragma unroll
                for (int nt = 0; nt < 2; nt++) {
                    int cg = y0 + nt * 8 + cq;
                    if (cg     > rg0) S[m][nt][0] = -3e38f;
                    if (cg + 1 > rg0) S[m][nt][1] = -3e38f;
                    if (cg     > rg1) S[m][nt][2] = -3e38f;
                    if (cg + 1 > rg1) S[m][nt][3] = -3e38f;
                }
            }
        }
        uint4 ph[NMT];
        #pragma unroll
        for (int m = 0; m < NMT; m++) {
            float p[2][4];
            #pragma unroll
            for (int nt = 0; nt < 2; nt++)
                #pragma unroll
                for (int j = 0; j < 4; j++) p[nt][j] = ex2f(S[m][nt][j]);
            ls[2*m]   += (p[0][0] + p[0][1]) + (p[1][0] + p[1][1]);
            ls[2*m+1] += (p[0][2] + p[0][3]) + (p[1][2] + p[1][3]);
            uint32_t hreg[4];
            #pragma unroll
            for (int q = 0; q < 4; q++) {
                int nt = q >> 1, jo = (q & 1) * 2;
                PACKBF(hreg[q], p[nt][jo], p[nt][jo+1]);
            }
            ph[m] = make_uint4(hreg[0], hreg[1], hreg[2], hreg[3]);
        }
        uint32_t vb0[2], vb1[2];
        #pragma unroll
        for (int nt = 0; nt < 2; nt++) {
            int vc = nt * 8 + rlow;
            uint32_t off = (uint32_t)(vc * 816 + y0 * 2 + khb);
            ldmx2(vb0[nt], vb1[nt], sb + TQ_VHI + off);
        }
        #pragma unroll
        for (int m = 0; m < NMT; m++)
            #pragma unroll
            for (int nt = 0; nt < 2; nt++)
                mma16816(O[m][nt], ph[m], vb0[nt], vb1[nt]);
    }

    #pragma unroll
    for (int i = 0; i < 2 * NMT; i++) {
        ls[i] += __shfl_xor_sync(0xffffffffu, ls[i], 1);
        ls[i] += __shfl_xor_sync(0xffffffffu, ls[i], 2);
    }

    #pragma unroll
    for (int m = 0; m < NMT; m++) {
        float i0 = 1.f / ls[2*m], i1 = 1.f / ls[2*m+1];
        int row0 = band * 32 + m * 16 + rq, row1 = row0 + 8;
        #pragma unroll
        for (int nt = 0; nt < 2; nt++) {
            int c = nt * 8 + cq;
            float p0 = O[m][nt][0] * i0, p1 = O[m][nt][1] * i0;
            float p2 = O[m][nt][2] * i1, p3 = O[m][nt][3] * i1;
            uint32_t h0; PACKBF(h0, p0, p1);
            uint32_t l0; PACKBF(l0, p0 - __uint_as_float(h0 << 16),
                                    p1 - __uint_as_float(h0 & 0xffff0000u));
            uint32_t h1; PACKBF(h1, p2, p3);
            uint32_t l1; PACKBF(l1, p2 - __uint_as_float(h1 << 16),
                                    p3 - __uint_as_float(h1 & 0xffff0000u));
            uint32_t a0 = (uint32_t)(row0 * 32 + c * 2) ^ (uint32_t)(((row0 >> 2) & 1) << 4);
            uint32_t a1 = (uint32_t)(row1 * 32 + c * 2) ^ (uint32_t)(((row1 >> 2) & 1) << 4);
            *(uint32_t*)(smt + TQ_PHI + a0) = h0;
            *(uint32_t*)(smt + TQ_PLO + a0) = l0;
            *(uint32_t*)(smt + TQ_PHI + a1) = h1;
            *(uint32_t*)(smt + TQ_PLO + a1) = l1;
        }
    }
}

__global__ __launch_bounds__(256, 2)
void asa_time_attn_kernel(const float* __restrict__ inp,
    const float* __restrict__ g3, const float* __restrict__ b3, const float* __restrict__ m3,
    const float* __restrict__ v3, const float* __restrict__ a3, float* __restrict__ out)
{
    extern __shared__ char smt[];
    uint32_t sb = smem_u32(smt);
    int tid = threadIdx.x, wid = tid >> 5, lane = tid & 31;
    int f = blockIdx.x, b = blockIdx.y;
    size_t cbase = (size_t)b * 32 * SP + (size_t)f * TT;
    const float* vg = g_fout_f + (size_t)(b * FF + f) * DC * TT;

    #pragma unroll 1
    for (int idx = tid; idx < 3200; idx += 256) {
        int t = idx % 400;
        int cp = idx / 400;
        uint32_t qkoff = (uint32_t)(t * 32 + cp * 4) ^ (uint32_t)(((t >> 2) & 1) << 4);
        {
            float x0 = g_tqk2[cbase + (size_t)(2*cp) * SP + t] * QS;
            float x1 = g_tqk2[cbase + (size_t)(2*cp+1) * SP + t] * QS;
            uint32_t h; PACKBF(h, x0, x1);
            *(uint32_t*)(smt + TQ_QHI + qkoff) = h;
        }
        {
            float x0 = g_tqk2[cbase + (size_t)(16 + 2*cp) * SP + t];
            float x1 = g_tqk2[cbase + (size_t)(17 + 2*cp) * SP + t];
            uint32_t h; PACKBF(h, x0, x1);
            *(uint32_t*)(smt + TQ_KHI + qkoff) = h;
        }
        {
            float x0 = vg[(size_t)(2*cp) * TT + t];
            float x1 = vg[(size_t)(2*cp+1) * TT + t];
            uint32_t h; PACKBF(h, x0, x1);
            uint32_t o0 = (uint32_t)((2*cp) * 816 + t * 2);
            uint32_t o1 = (uint32_t)((2*cp+1) * 816 + t * 2);
            *(uint16_t*)(smt + TQ_VHI + o0) = (uint16_t)(h & 0xffff);
            *(uint16_t*)(smt + TQ_VHI + o1) = (uint16_t)(h >> 16);
        }
    }
    if (tid < 64) {
        float s = g3[tid] * rsqrtf(v3[tid] + 1e-5f);
        ((float*)(smt + TQ_SH))[tid] = b3[tid] - m3[tid] * s;
        ((float*)(smt + TQ_AL))[tid] = a3[tid];
    }
    __syncthreads();

    #pragma unroll 1
    for (int bi = 0; bi < 2; bi++) {
        int band = BAND_LUT8[wid][bi];
        if (band < 0) break;
        if (band == 12) tq_band<1>(smt, sb, band, lane);
        else            tq_band<2>(smt, sb, band, lane);
    }
    __syncthreads();

    // projection via mma (3-term split, cheap insurance)
    const float* sh3 = (const float*)(smt + TQ_SH);
    const float* al3 = (const float*)(smt + TQ_AL);
    int l16 = lane & 15;
    int rlow = l16 & 7;
    int khb = ((l16 >> 3) & 1) << 4;
    int rq = lane >> 2, cq = (lane & 3) * 2;
    int m = wid & 3;
    int nt0 = (wid < 4) ? 0 : 25;
    uint4 wh = g_wpfH[m * 32 + lane];
    uint4 wl = g_wpfL[m * 32 + lane];
    int oc0 = m * 16 + rq, oc1 = oc0 + 8;
    float sh0 = sh3[oc0], al0 = al3[oc0];
    float sh1 = sh3[oc1], al1 = al3[oc1];
    size_t ob0 = (((size_t)b * CC + oc0) * FF + f) * TT;
    size_t ob1 = (((size_t)b * CC + oc1) * FF + f) * TT;

    #pragma unroll 1
    for (int ntile = nt0; ntile < nt0 + 25; ntile++) {
        int pr = ntile * 8 + rlow;
        uint32_t off = (uint32_t)(pr * 32 + khb) ^ (uint32_t)(((pr >> 2) & 1) << 4);
        uint32_t bh0, bh1, bl0, bl1;
        ldmx2(bh0, bh1, sb + TQ_PHI + off);
        ldmx2(bl0, bl1, sb + TQ_PLO + off);
        float D[4] = {0.f, 0.f, 0.f, 0.f};
        mma16816(D, wh, bh0, bh1);
        mma16816(D, wl, bh0, bh1);
        mma16816(D, wh, bl0, bl1);

        int tcol = ntile * 8 + cq;
        float2 r0 = *(const float2*)(inp + ob0 + tcol);
        float2 r1 = *(const float2*)(inp + ob1 + tcol);
        float v0 = D[0] + sh0; v0 = v0 > 0.f ? v0 : al0 * v0;
        float v1 = D[1] + sh0; v1 = v1 > 0.f ? v1 : al0 * v1;
        float v2 = D[2] + sh1; v2 = v2 > 0.f ? v2 : al1 * v2;
        float v3v = D[3] + sh1; v3v = v3v > 0.f ? v3v : al1 * v3v;
        *(float2*)(out + ob0 + tcol) = make_float2(v0 + r0.x, v1 + r0.y);
        *(float2*)(out + ob1 + tcol) = make_float2(v2 + r1.x, v3v + r1.y);
    }
}

// ================= launcher =================
extern "C" void kernel_launch(void* const* d_in, const int* in_sizes, int n_in,
                              void* d_out, int out_size)
{
    (void)in_sizes; (void)n_in; (void)out_size;
    const float* inp    = (const float*)d_in[0];
    const float* w_fqkv = (const float*)d_in[2];
    const float* g1 = (const float*)d_in[3];
    const float* b1 = (const float*)d_in[4];
    const float* m1 = (const float*)d_in[5];
    const float* v1 = (const float*)d_in[6];
    const float* a1 = (const float*)d_in[7];
    const float* w_tqk  = (const float*)d_in[8];
    const float* g2 = (const float*)d_in[9];
    const float* b2 = (const float*)d_in[10];
    const float* m2 = (const float*)d_in[11];
    const float* v2 = (const float*)d_in[12];
    const float* a2 = (const float*)d_in[13];
    const float* w_proj = (const float*)d_in[14];
    const float* g3 = (const float*)d_in[15];
    const float* b3 = (const float*)d_in[16];
    const float* m3 = (const float*)d_in[17];
    const float* v3 = (const float*)d_in[18];
    const float* a3 = (const float*)d_in[19];
    float* out = (float*)d_out;

    cudaFuncSetAttribute(asa_conv_mma_kernel,
                         cudaFuncAttributeMaxDynamicSharedMemorySize, CV_SMEM);
    cudaFuncSetAttribute(asa_time_attn_kernel,
                         cudaFuncAttributeMaxDynamicSharedMemorySize, TQ_SMEM);

    asa_prep_kernel<<<3, 256>>>(w_fqkv, w_tqk, g1, b1, m1, v1, a1,
                                g2, b2, m2, v2, a2, w_proj, g3, v3);
    asa_conv_mma_kernel<<<dim3(800, BB), 320, CV_SMEM>>>(inp);
    asa_transpose_qkv_kernel<<<dim3(13, 8, BB * 48), dim3(32, 8)>>>();
    asa_freq_attn_kernel<<<dim3(TT, BB), 256>>>();
    asa_transpose_fout_kernel<<<dim3(8, 13, BB * 16), dim3(32, 8)>>>();
    asa_time_attn_kernel<<<dim3(FF, BB), 256, TQ_SMEM>>>(inp,
        g3, b3, m3, v3, a3, out);
}